// round 1
// baseline (speedup 1.0000x reference)
#include <cuda_runtime.h>
#include <math.h>

#define NN   20000
#define EE   400000
#define ET   (EE + NN)
#define HH   10
#define FF   78
#define HID  780
#define BB   200
#define SEQ  1000
#define VOC  26
#define EMB  128
#define NF   32
#define KS   8
#define COUT 993

// ---------------- scratch (device globals; no allocs allowed) ----------------
__device__ float g_h  [NN * HID];   // x @ gat_W
__device__ float g_agg[NN * HID];   // GAT aggregate -> x1
__device__ float g_h2 [NN * HID];   // x1 @ gcn_W
__device__ float g_x2 [NN * HID];   // GCN aggregate (pre-bias/relu)
__device__ float g_as [NN * HH];
__device__ float g_ad [NN * HH];
__device__ float g_e  [ET * HH];    // e -> ex (in place)
__device__ float g_m  [NN * HH];
__device__ float g_den[NN * HH];
__device__ float g_deg [NN];
__device__ float g_dinv[NN];
__device__ float g_xg [BB * HID];
__device__ float g_t1 [BB * 1500];
__device__ float g_xc [BB * 256];
__device__ float g_t2 [BB * 1024];
__device__ float g_t3 [BB * 512];
__device__ float g_t4 [BB * 256];
__device__ float g_t5 [BB * 128];
__device__ float g_P  [VOC * NF * KS];
__device__ float g_R  [VOC * SEQ * 128];
__device__ float g_biasY[128];

// ---------------- utility ----------------
__global__ void kfill(float* p, float v, int n) {
    int i = blockIdx.x * blockDim.x + threadIdx.x;
    if (i < n) p[i] = v;
}

__device__ __forceinline__ void atomicMaxF(float* addr, float v) {
    if (v >= 0.f) atomicMax((int*)addr, __float_as_int(v));
    else          atomicMin((unsigned int*)addr, __float_as_uint(v));
}

// ---------------- generic SGEMM: C = A[MxK] * B[KxN] (+bias)(+relu) ----------------
// row-major, lda=K, ldb=N; C written at C[row*ldc + coff + col]
__global__ void sgemm128(const float* __restrict__ A, const float* __restrict__ B,
                         float* __restrict__ C, const float* __restrict__ bias,
                         int M, int N, int K, int ldc, int coff, int relu) {
    __shared__ float As[8][128];
    __shared__ float Bs[8][128];
    int tid = threadIdx.x;
    int m0 = blockIdx.y * 128, n0 = blockIdx.x * 128;
    int ar = tid >> 1, ac = (tid & 1) * 4;
    int br = tid >> 5, bc = (tid & 31) * 4;
    int ty = tid >> 4, tx = tid & 15;

    float acc[8][8];
#pragma unroll
    for (int i = 0; i < 8; i++)
#pragma unroll
        for (int j = 0; j < 8; j++) acc[i][j] = 0.f;

    for (int k0 = 0; k0 < K; k0 += 8) {
#pragma unroll
        for (int i = 0; i < 4; i++) {
            int m = m0 + ar, k = k0 + ac + i;
            As[ac + i][ar] = (m < M && k < K) ? A[(long)m * K + k] : 0.f;
        }
#pragma unroll
        for (int i = 0; i < 4; i++) {
            int k = k0 + br, n = n0 + bc + i;
            Bs[br][bc + i] = (k < K && n < N) ? B[(long)k * N + n] : 0.f;
        }
        __syncthreads();
#pragma unroll
        for (int kk = 0; kk < 8; kk++) {
            float a[8], b[8];
#pragma unroll
            for (int i = 0; i < 8; i++) a[i] = As[kk][ty * 8 + i];
#pragma unroll
            for (int j = 0; j < 8; j++) b[j] = Bs[kk][tx * 8 + j];
#pragma unroll
            for (int i = 0; i < 8; i++)
#pragma unroll
                for (int j = 0; j < 8; j++) acc[i][j] += a[i] * b[j];
        }
        __syncthreads();
    }

#pragma unroll
    for (int i = 0; i < 8; i++) {
        int row = m0 + ty * 8 + i;
        if (row >= M) continue;
#pragma unroll
        for (int j = 0; j < 8; j++) {
            int col = n0 + tx * 8 + j;
            if (col >= N) continue;
            float v = acc[i][j] + (bias ? bias[col] : 0.f);
            if (relu) v = fmaxf(v, 0.f);
            C[(long)row * ldc + coff + col] = v;
        }
    }
}

// ---------------- GAT ----------------
__global__ void k_attn_coef(const float* __restrict__ aS, const float* __restrict__ aD) {
    int g = blockIdx.x * blockDim.x + threadIdx.x;
    if (g >= NN * HH) return;
    int n = g / HH, h = g % HH;
    const float* hp = g_h + (long)n * HID + h * FF;
    float s = 0.f, d = 0.f;
#pragma unroll 13
    for (int f = 0; f < FF; f++) {
        float hv = hp[f];
        s += hv * aS[h * FF + f];
        d += hv * aD[h * FF + f];
    }
    g_as[g] = s;
    g_ad[g] = d;
}

__global__ void k_edgeA(const int* __restrict__ edge) {
    int i = blockIdx.x * blockDim.x + threadIdx.x;
    if (i >= ET) return;
    int src = (i < EE) ? edge[i]      : i - EE;
    int dst = (i < EE) ? edge[EE + i] : i - EE;
    atomicAdd(&g_deg[dst], 1.f);
#pragma unroll
    for (int h = 0; h < HH; h++) {
        float e = g_as[src * HH + h] + g_ad[dst * HH + h];
        e = (e > 0.f) ? e : 0.2f * e;
        g_e[(long)i * HH + h] = e;
        atomicMaxF(&g_m[dst * HH + h], e);
    }
}

__global__ void k_edgeB(const int* __restrict__ edge) {
    long g = (long)blockIdx.x * blockDim.x + threadIdx.x;
    if (g >= (long)ET * HH) return;
    int i = (int)(g / HH), h = (int)(g % HH);
    int dst = (i < EE) ? edge[EE + i] : i - EE;
    float ex = expf(g_e[g] - g_m[dst * HH + h]);
    g_e[g] = ex;
    atomicAdd(&g_den[dst * HH + h], ex);
}

__global__ void k_edgeC(const int* __restrict__ edge) {
    __shared__ float sal[HH];
    __shared__ int ss, sd;
    int i = blockIdx.x;
    int tid = threadIdx.x;
    if (tid == 0) {
        ss = (i < EE) ? edge[i]      : i - EE;
        sd = (i < EE) ? edge[EE + i] : i - EE;
    }
    if (tid < HH) {
        int dst = (i < EE) ? edge[EE + i] : i - EE;
        sal[tid] = g_e[(long)i * HH + tid] / g_den[dst * HH + tid];
    }
    __syncthreads();
    if (tid < HID)
        atomicAdd(&g_agg[(long)sd * HID + tid], g_h[(long)ss * HID + tid] * sal[tid / FF]);
}

__global__ void k_x1(const float* __restrict__ gat_b) {
    long g = (long)blockIdx.x * blockDim.x + threadIdx.x;
    if (g >= (long)NN * HID) return;
    int j = (int)(g % HID);
    g_agg[g] = fmaxf(g_agg[g] + gat_b[j], 0.f);
}

__global__ void k_dinv() {
    int n = blockIdx.x * blockDim.x + threadIdx.x;
    if (n < NN) g_dinv[n] = rsqrtf(fmaxf(g_deg[n], 1.f));
}

// ---------------- GCN ----------------
__global__ void k_edgeD(const int* __restrict__ edge) {
    __shared__ float sn;
    __shared__ int ss, sd;
    int i = blockIdx.x;
    int tid = threadIdx.x;
    if (tid == 0) {
        ss = (i < EE) ? edge[i]      : i - EE;
        sd = (i < EE) ? edge[EE + i] : i - EE;
        sn = g_dinv[ss] * g_dinv[sd];
    }
    __syncthreads();
    if (tid < HID)
        atomicAdd(&g_x2[(long)sd * HID + tid], g_h2[(long)ss * HID + tid] * sn);
}

__global__ void k_pool(const float* __restrict__ gcn_b, const int* __restrict__ batch) {
    long g = (long)blockIdx.x * blockDim.x + threadIdx.x;
    if (g >= (long)NN * HID) return;
    int n = (int)(g / HID), j = (int)(g % HID);
    float v = fmaxf(g_x2[g] + gcn_b[j], 0.f);
    atomicAdd(&g_xg[(long)batch[n] * HID + j], v);
}

// ---------------- protein branch (factorized) ----------------
// P[v,o,k] = sum_e emb[v,e] * cW[o,e,k]
__global__ void k_P(const float* __restrict__ emb, const float* __restrict__ cW) {
    int g = blockIdx.x * blockDim.x + threadIdx.x;
    if (g >= VOC * NF * KS) return;
    int v = g / (NF * KS), r = g % (NF * KS);
    int o = r / KS, k = r % KS;
    float s = 0.f;
#pragma unroll 16
    for (int e = 0; e < EMB; e++)
        s += emb[v * EMB + e] * cW[o * EMB * KS + e * KS + k];
    g_P[g] = s;
}

__global__ void k_biasY_init(const float* __restrict__ fxt_b) {
    int j = threadIdx.x;
    g_biasY[j] = fxt_b[j];
}

// biasY[j] += sum_{o,t} cb[o] * fxt_W[(o*993+t)*128 + j]
__global__ void k_biasY_acc(const float* __restrict__ fxtW, const float* __restrict__ cb) {
    int o = blockIdx.x;
    int j = threadIdx.x;
    float p = 0.f;
    for (int t = 0; t < COUT; t++)
        p += fxtW[((long)(o * COUT + t)) * 128 + j];
    atomicAdd(&g_biasY[j], cb[o] * p);
}

// R[v,s,j] = sum_{o,k valid} P[v,o,k] * fxt_W[(o*993 + s - k)*128 + j]
__global__ void k_R(const float* __restrict__ fxtW) {
    __shared__ float Ps[VOC * NF * KS];
    int s = blockIdx.x;
    int j = threadIdx.x;
    for (int idx = j; idx < VOC * NF * KS; idx += 128) Ps[idx] = g_P[idx];
    __syncthreads();
    float acc[VOC];
#pragma unroll
    for (int v = 0; v < VOC; v++) acc[v] = 0.f;
    int kmin = (s > COUT - 1) ? (s - (COUT - 1)) : 0;
    int kmax = (s < KS - 1) ? s : (KS - 1);
    for (int o = 0; o < NF; o++) {
        for (int k = kmin; k <= kmax; k++) {
            float w = fxtW[((long)(o * COUT + s - k)) * 128 + j];
#pragma unroll
            for (int v = 0; v < VOC; v++)
                acc[v] += Ps[v * (NF * KS) + o * KS + k] * w;
        }
    }
#pragma unroll
    for (int v = 0; v < VOC; v++)
        g_R[((long)v * SEQ + s) * 128 + j] = acc[v];
}

// xt[b,j] = biasY[j] + sum_s R[tg[b,s], s, j]   -> xc[b, 128+j]
__global__ void k_Y(const int* __restrict__ target) {
    int b = blockIdx.x;
    int j = threadIdx.x;
    float acc = g_biasY[j];
    for (int s = 0; s < SEQ; s++) {
        int v = target[b * SEQ + s];
        acc += g_R[((long)v * SEQ + s) * 128 + j];
    }
    g_xc[b * 256 + 128 + j] = acc;
}

// ---------------- output ----------------
__global__ void k_out(const float* __restrict__ oW, const float* __restrict__ ob,
                      float* __restrict__ out) {
    __shared__ float red[4];
    int b = blockIdx.x;
    int j = threadIdx.x;
    float v = g_t5[b * 128 + j] * oW[j];
#pragma unroll
    for (int off = 16; off; off >>= 1) v += __shfl_down_sync(0xffffffffu, v, off);
    if ((j & 31) == 0) red[j >> 5] = v;
    __syncthreads();
    if (j == 0) out[b] = red[0] + red[1] + red[2] + red[3] + ob[0];
}

// ---------------- host ----------------
static inline dim3 ggrid(long n, int t) { return dim3((unsigned)((n + t - 1) / t)); }

extern "C" void kernel_launch(void* const* d_in, const int* in_sizes, int n_in,
                              void* d_out, int out_size) {
    const float* x      = (const float*)d_in[0];
    const int*   edge   = (const int*)  d_in[1];
    const int*   batch  = (const int*)  d_in[2];
    const int*   target = (const int*)  d_in[3];
    const float* gat_W  = (const float*)d_in[4];
    const float* a_src  = (const float*)d_in[5];
    const float* a_dst  = (const float*)d_in[6];
    const float* gat_b  = (const float*)d_in[7];
    const float* gcn_W  = (const float*)d_in[8];
    const float* gcn_b  = (const float*)d_in[9];
    const float* fcg1_W = (const float*)d_in[10];
    const float* fcg1_b = (const float*)d_in[11];
    const float* fcg2_W = (const float*)d_in[12];
    const float* fcg2_b = (const float*)d_in[13];
    const float* emb    = (const float*)d_in[14];
    const float* cW     = (const float*)d_in[15];
    const float* cb     = (const float*)d_in[16];
    const float* fxt_W  = (const float*)d_in[17];
    const float* fxt_b  = (const float*)d_in[18];
    const float* f1_W   = (const float*)d_in[19];
    const float* f1_b   = (const float*)d_in[20];
    const float* f2_W   = (const float*)d_in[21];
    const float* f2_b   = (const float*)d_in[22];
    const float* f3_W   = (const float*)d_in[23];
    const float* f3_b   = (const float*)d_in[24];
    const float* f4_W   = (const float*)d_in[25];
    const float* f4_b   = (const float*)d_in[26];
    const float* o_W    = (const float*)d_in[27];
    const float* o_b    = (const float*)d_in[28];
    float* out = (float*)d_out;

    float *p_h, *p_agg, *p_h2, *p_x2, *p_m, *p_den, *p_deg, *p_xg;
    float *p_t1, *p_xc, *p_t2, *p_t3, *p_t4, *p_t5;
    cudaGetSymbolAddress((void**)&p_h,   g_h);
    cudaGetSymbolAddress((void**)&p_agg, g_agg);
    cudaGetSymbolAddress((void**)&p_h2,  g_h2);
    cudaGetSymbolAddress((void**)&p_x2,  g_x2);
    cudaGetSymbolAddress((void**)&p_m,   g_m);
    cudaGetSymbolAddress((void**)&p_den, g_den);
    cudaGetSymbolAddress((void**)&p_deg, g_deg);
    cudaGetSymbolAddress((void**)&p_xg,  g_xg);
    cudaGetSymbolAddress((void**)&p_t1,  g_t1);
    cudaGetSymbolAddress((void**)&p_xc,  g_xc);
    cudaGetSymbolAddress((void**)&p_t2,  g_t2);
    cudaGetSymbolAddress((void**)&p_t3,  g_t3);
    cudaGetSymbolAddress((void**)&p_t4,  g_t4);
    cudaGetSymbolAddress((void**)&p_t5,  g_t5);

    // ---- init scratch ----
    kfill<<<ggrid((long)NN * HID, 256), 256>>>(p_agg, 0.f, NN * HID);
    kfill<<<ggrid((long)NN * HID, 256), 256>>>(p_x2,  0.f, NN * HID);
    kfill<<<ggrid(NN * HH, 256), 256>>>(p_m,   -INFINITY, NN * HH);
    kfill<<<ggrid(NN * HH, 256), 256>>>(p_den, 0.f, NN * HH);
    kfill<<<ggrid(NN, 256), 256>>>(p_deg, 0.f, NN);
    kfill<<<ggrid(BB * HID, 256), 256>>>(p_xg, 0.f, BB * HID);

    // ---- GAT ----
    {   // h = x @ gat_W
        dim3 grid((HID + 127) / 128, (NN + 127) / 128);
        sgemm128<<<grid, 256>>>(x, gat_W, p_h, nullptr, NN, HID, FF, HID, 0, 0);
    }
    k_attn_coef<<<ggrid(NN * HH, 256), 256>>>(a_src, a_dst);
    k_edgeA<<<ggrid(ET, 256), 256>>>(edge);
    k_edgeB<<<ggrid((long)ET * HH, 256), 256>>>(edge);
    k_edgeC<<<ET, 800>>>(edge);
    k_x1<<<ggrid((long)NN * HID, 256), 256>>>(gat_b);
    k_dinv<<<ggrid(NN, 256), 256>>>();

    // ---- GCN ----
    {   // h2 = x1 @ gcn_W
        dim3 grid((HID + 127) / 128, (NN + 127) / 128);
        sgemm128<<<grid, 256>>>(p_agg, gcn_W, p_h2, nullptr, NN, HID, HID, HID, 0, 0);
    }
    k_edgeD<<<ET, 800>>>(edge);
    k_pool<<<ggrid((long)NN * HID, 256), 256>>>(gcn_b, batch);

    // ---- graph MLP head ----
    {
        dim3 grid((1500 + 127) / 128, (BB + 127) / 128);
        sgemm128<<<grid, 256>>>(p_xg, fcg1_W, p_t1, fcg1_b, BB, 1500, HID, 1500, 0, 1);
    }
    {
        dim3 grid(1, (BB + 127) / 128);
        sgemm128<<<grid, 256>>>(p_t1, fcg2_W, p_xc, fcg2_b, BB, 128, 1500, 256, 0, 0);
    }

    // ---- protein branch ----
    k_P<<<ggrid(VOC * NF * KS, 256), 256>>>(emb, cW);
    k_biasY_init<<<1, 128>>>(fxt_b);
    k_biasY_acc<<<NF, 128>>>(fxt_W, cb);
    k_R<<<SEQ, 128>>>(fxt_W);
    k_Y<<<BB, 128>>>(target);

    // ---- fusion MLP ----
    {
        dim3 grid((1024 + 127) / 128, (BB + 127) / 128);
        sgemm128<<<grid, 256>>>(p_xc, f1_W, p_t2, f1_b, BB, 1024, 256, 1024, 0, 1);
    }
    {
        dim3 grid((512 + 127) / 128, (BB + 127) / 128);
        sgemm128<<<grid, 256>>>(p_t2, f2_W, p_t3, f2_b, BB, 512, 1024, 512, 0, 1);
    }
    {
        dim3 grid((256 + 127) / 128, (BB + 127) / 128);
        sgemm128<<<grid, 256>>>(p_t3, f3_W, p_t4, f3_b, BB, 256, 512, 256, 0, 1);
    }
    {
        dim3 grid((128 + 127) / 128, (BB + 127) / 128);
        sgemm128<<<grid, 256>>>(p_t4, f4_W, p_t5, f4_b, BB, 128, 256, 128, 0, 1);
    }
    k_out<<<BB, 128>>>(o_W, o_b, out);
}

// round 2
// speedup vs baseline: 2.9938x; 2.9938x over previous
#include <cuda_runtime.h>
#include <math.h>

#define NN   20000
#define EE   400000
#define ET   (EE + NN)
#define HH   10
#define FF   78
#define FFP  80
#define HID  780
#define BB   200
#define SEQ  1000
#define VOC  26
#define EMB  128
#define NF   32
#define KS   8
#define COUT 993

// ---------------- scratch ----------------
__device__ float g_h  [NN * HID];
__device__ float g_agg[NN * HID];
__device__ float g_h2 [NN * HID];
__device__ float g_x2 [NN * HID];
__device__ float g_as [NN * HH];
__device__ float g_ad [NN * HH];
__device__ float g_e  [(long)ET * HH];
__device__ float g_m  [NN * HH];
__device__ float g_den[NN * HH];
__device__ float g_dinv[NN];
__device__ float g_xp [NN * FFP];
__device__ float g_Wp [FFP * HID];
__device__ float g_xg [BB * HID];
__device__ float g_t1 [BB * 1500];
__device__ float g_xc [BB * 256];
__device__ float g_t2 [BB * 1024];
__device__ float g_t3 [BB * 512];
__device__ float g_t4 [BB * 256];
__device__ float g_t5 [BB * 128];
__device__ float g_P  [VOC * NF * KS];
__device__ float g_R  [(long)VOC * SEQ * 128];
__device__ float g_biasY[128];
__device__ int   g_cnt[NN];
__device__ int   g_off[NN + 1];
__device__ int   g_srcA[ET];
__device__ int   g_eid[ET];
__device__ int   g_start[BB + 1];

// ---------------- f32x2 packed FMA ----------------
#define PK2(d, lo, hi) asm("mov.b64 %0, {%1,%2};" : "=l"(d) : "r"(__float_as_uint(lo)), "r"(__float_as_uint(hi)))
#define FMA2(d, a, b)  asm("fma.rn.f32x2 %0, %1, %2, %3;" : "=l"(d) : "l"(a), "l"(b), "l"(d))
#define UPK2(lo, hi, s) { unsigned int u0_, u1_; asm("mov.b64 {%0,%1}, %2;" : "=r"(u0_), "=r"(u1_) : "l"(s)); lo = __uint_as_float(u0_); hi = __uint_as_float(u1_); }

// ---------------- utility ----------------
__global__ void kfill(float* p, float v, int n) {
    int i = blockIdx.x * blockDim.x + threadIdx.x;
    if (i < n) p[i] = v;
}
__global__ void kfillI(int* p, int v, int n) {
    int i = blockIdx.x * blockDim.x + threadIdx.x;
    if (i < n) p[i] = v;
}
__device__ __forceinline__ void atomicMaxF(float* addr, float v) {
    if (v >= 0.f) atomicMax((int*)addr, __float_as_int(v));
    else          atomicMin((unsigned int*)addr, __float_as_uint(v));
}

// ---------------- SGEMM v2: 128x128x16 tiles, f32x2, double buffered ----------------
#define BMg 128
#define BNg 128
#define BKg 16
__global__ void __launch_bounds__(256)
sgemm2(const float* __restrict__ A, const float* __restrict__ B,
       float* __restrict__ C, const float* __restrict__ bias,
       int M, int N, int K, int lda, int ldb, int ldc, int coff, int relu) {
    __shared__ float As[2][BKg][BMg + 4];
    __shared__ float Bs[2][BKg][BNg];
    int tid = threadIdx.x;
    int m0 = blockIdx.y * BMg, n0 = blockIdx.x * BNg;
    int ty = tid >> 4, tx = tid & 15;

    unsigned long long acc2[8][4];
#pragma unroll
    for (int i = 0; i < 8; i++)
#pragma unroll
        for (int j = 0; j < 4; j++) acc2[i][j] = 0ull;

    float4 ra[2], rb[2];

    auto loadStage = [&](int kT) {
#pragma unroll
        for (int p = 0; p < 2; p++) {
            int f = tid + p * 256;
            int m = f >> 2, kq = f & 3;
            int gm = m0 + m, gk = kT + kq * 4;
            const float* ap = A + (long)gm * lda + gk;
            if (gm < M && gk + 3 < K) ra[p] = *(const float4*)ap;
            else {
                ra[p].x = (gm < M && gk     < K) ? ap[0] : 0.f;
                ra[p].y = (gm < M && gk + 1 < K) ? ap[1] : 0.f;
                ra[p].z = (gm < M && gk + 2 < K) ? ap[2] : 0.f;
                ra[p].w = (gm < M && gk + 3 < K) ? ap[3] : 0.f;
            }
        }
#pragma unroll
        for (int p = 0; p < 2; p++) {
            int f = tid + p * 256;
            int kr = f >> 5, nq = f & 31;
            int gk = kT + kr, gn = n0 + nq * 4;
            const float* bp = B + (long)gk * ldb + gn;
            if (gk < K && gn + 3 < N) rb[p] = *(const float4*)bp;
            else {
                rb[p].x = (gk < K && gn     < N) ? bp[0] : 0.f;
                rb[p].y = (gk < K && gn + 1 < N) ? bp[1] : 0.f;
                rb[p].z = (gk < K && gn + 2 < N) ? bp[2] : 0.f;
                rb[p].w = (gk < K && gn + 3 < N) ? bp[3] : 0.f;
            }
        }
    };
    auto storeStage = [&](int buf) {
#pragma unroll
        for (int p = 0; p < 2; p++) {
            int f = tid + p * 256;
            int m = f >> 2, kq = f & 3;
            As[buf][kq * 4 + 0][m] = ra[p].x;
            As[buf][kq * 4 + 1][m] = ra[p].y;
            As[buf][kq * 4 + 2][m] = ra[p].z;
            As[buf][kq * 4 + 3][m] = ra[p].w;
        }
#pragma unroll
        for (int p = 0; p < 2; p++) {
            int f = tid + p * 256;
            int kr = f >> 5, nq = f & 31;
            *(float4*)&Bs[buf][kr][nq * 4] = rb[p];
        }
    };

    int buf = 0;
    loadStage(0);
    storeStage(0);
    __syncthreads();

    for (int kT = 0;;) {
        int kN = kT + BKg;
        bool more = kN < K;
        if (more) loadStage(kN);
#pragma unroll
        for (int kk = 0; kk < BKg; kk++) {
            float4 a0 = *(const float4*)&As[buf][kk][ty * 8];
            float4 a1 = *(const float4*)&As[buf][kk][ty * 8 + 4];
            float4 b0 = *(const float4*)&Bs[buf][kk][tx * 8];
            float4 b1 = *(const float4*)&Bs[buf][kk][tx * 8 + 4];
            unsigned long long bp0, bp1, bp2, bp3;
            PK2(bp0, b0.x, b0.y); PK2(bp1, b0.z, b0.w);
            PK2(bp2, b1.x, b1.y); PK2(bp3, b1.z, b1.w);
            float av[8] = {a0.x, a0.y, a0.z, a0.w, a1.x, a1.y, a1.z, a1.w};
#pragma unroll
            for (int i = 0; i < 8; i++) {
                unsigned long long aa;
                PK2(aa, av[i], av[i]);
                FMA2(acc2[i][0], aa, bp0);
                FMA2(acc2[i][1], aa, bp1);
                FMA2(acc2[i][2], aa, bp2);
                FMA2(acc2[i][3], aa, bp3);
            }
        }
        if (!more) break;
        storeStage(buf ^ 1);
        buf ^= 1; kT = kN;
        __syncthreads();
    }

#pragma unroll
    for (int i = 0; i < 8; i++) {
        int row = m0 + ty * 8 + i;
        if (row >= M) continue;
        float cv[8];
        UPK2(cv[0], cv[1], acc2[i][0]);
        UPK2(cv[2], cv[3], acc2[i][1]);
        UPK2(cv[4], cv[5], acc2[i][2]);
        UPK2(cv[6], cv[7], acc2[i][3]);
#pragma unroll
        for (int j = 0; j < 8; j++) {
            int col = n0 + tx * 8 + j;
            if (col >= N) continue;
            float v = cv[j] + (bias ? bias[col] : 0.f);
            if (relu) v = fmaxf(v, 0.f);
            C[(long)row * ldc + coff + col] = v;
        }
    }
}

// ---------------- padding for GAT GEMM ----------------
__global__ void k_padx(const float* __restrict__ x) {
    int i = blockIdx.x * blockDim.x + threadIdx.x;
    if (i >= NN * FFP) return;
    int m = i / FFP, k = i % FFP;
    g_xp[i] = (k < FF) ? x[m * FF + k] : 0.f;
}
__global__ void k_padW(const float* __restrict__ W) {
    int i = blockIdx.x * blockDim.x + threadIdx.x;
    if (i >= FFP * HID) return;
    int k = i / HID, n = i % HID;
    g_Wp[i] = (k < FF) ? W[k * HID + n] : 0.f;
}

// ---------------- GAT attention ----------------
__global__ void k_attn_coef(const float* __restrict__ aS, const float* __restrict__ aD) {
    int g = blockIdx.x * blockDim.x + threadIdx.x;
    if (g >= NN * HH) return;
    int n = g / HH, h = g % HH;
    const float* hp = g_h + (long)n * HID + h * FF;
    float s = 0.f, d = 0.f;
#pragma unroll 13
    for (int f = 0; f < FF; f++) {
        float hv = hp[f];
        s += hv * aS[h * FF + f];
        d += hv * aD[h * FF + f];
    }
    g_as[g] = s;
    g_ad[g] = d;
}

__global__ void k_edgeA(const int* __restrict__ edge) {
    int i = blockIdx.x * blockDim.x + threadIdx.x;
    if (i >= ET) return;
    int src = (i < EE) ? edge[i]      : i - EE;
    int dst = (i < EE) ? edge[EE + i] : i - EE;
#pragma unroll
    for (int h = 0; h < HH; h++) {
        float e = g_as[src * HH + h] + g_ad[dst * HH + h];
        e = (e > 0.f) ? e : 0.2f * e;
        g_e[(long)i * HH + h] = e;
        atomicMaxF(&g_m[dst * HH + h], e);
    }
}

__global__ void k_edgeB(const int* __restrict__ edge) {
    long g = (long)blockIdx.x * blockDim.x + threadIdx.x;
    if (g >= (long)ET * HH) return;
    int i = (int)(g / HH), h = (int)(g % HH);
    int dst = (i < EE) ? edge[EE + i] : i - EE;
    float ex = expf(g_e[g] - g_m[dst * HH + h]);
    g_e[g] = ex;
    atomicAdd(&g_den[dst * HH + h], ex);
}

__global__ void k_alpha(const int* __restrict__ edge) {
    long g = (long)blockIdx.x * blockDim.x + threadIdx.x;
    if (g >= (long)ET * HH) return;
    int i = (int)(g / HH), h = (int)(g % HH);
    int dst = (i < EE) ? edge[EE + i] : i - EE;
    g_e[g] = g_e[g] / g_den[dst * HH + h];
}

// ---------------- CSR build ----------------
__global__ void k_count(const int* __restrict__ edge) {
    int i = blockIdx.x * blockDim.x + threadIdx.x;
    if (i >= ET) return;
    int dst = (i < EE) ? edge[EE + i] : i - EE;
    atomicAdd(&g_cnt[dst], 1);
}

__global__ void k_scan() {
    __shared__ int part[256];
    int tid = threadIdx.x;
    const int chunk = (NN + 255) / 256;
    int lo = tid * chunk, hi = min(lo + chunk, NN);
    int s = 0;
    for (int n = lo; n < hi; n++) s += g_cnt[n];
    part[tid] = s;
    __syncthreads();
    if (tid == 0) {
        int r = 0;
        for (int i = 0; i < 256; i++) { int t = part[i]; part[i] = r; r += t; }
        g_off[NN] = r;
    }
    __syncthreads();
    int r = part[tid];
    for (int n = lo; n < hi; n++) {
        g_off[n] = r;
        int c = g_cnt[n];
        r += c;
        g_dinv[n] = rsqrtf((float)(c > 0 ? c : 1));
    }
}

__global__ void k_scatter(const int* __restrict__ edge) {
    int i = blockIdx.x * blockDim.x + threadIdx.x;
    if (i >= ET) return;
    int src = (i < EE) ? edge[i]      : i - EE;
    int dst = (i < EE) ? edge[EE + i] : i - EE;
    int pos = g_off[dst] + atomicAdd(&g_cnt[dst], 1);
    g_srcA[pos] = src;
    g_eid[pos] = i;
}

// ---------------- CSR aggregations ----------------
__global__ void __launch_bounds__(256) k_gat_agg(const float* __restrict__ gat_b) {
    int n = blockIdx.x, t = threadIdx.x;
    int c0 = t, c1 = t + 256, c2 = t + 512, c3 = t + 768;
    int h0 = c0 / FF, h1 = c1 / FF, h2 = c2 / FF;
    bool has3 = (c3 < HID);
    float a0s = 0.f, a1s = 0.f, a2s = 0.f, a3s = 0.f;
    int lo = g_off[n], hi = g_off[n + 1];
    for (int idx = lo; idx < hi; idx++) {
        int s = g_srcA[idx];
        int e = g_eid[idx];
        const float* __restrict__ hr = g_h + (long)s * HID;
        const float* __restrict__ al = g_e + (long)e * HH;
        float w0 = al[h0], w1 = al[h1], w2 = al[h2];
        a0s += hr[c0] * w0;
        a1s += hr[c1] * w1;
        a2s += hr[c2] * w2;
        if (has3) a3s += hr[c3] * al[9];
    }
    float* o = g_agg + (long)n * HID;
    o[c0] = fmaxf(a0s + gat_b[c0], 0.f);
    o[c1] = fmaxf(a1s + gat_b[c1], 0.f);
    o[c2] = fmaxf(a2s + gat_b[c2], 0.f);
    if (has3) o[c3] = fmaxf(a3s + gat_b[c3], 0.f);
}

__global__ void __launch_bounds__(256) k_gcn_agg(const float* __restrict__ gcn_b) {
    int n = blockIdx.x, t = threadIdx.x;
    int c0 = t, c1 = t + 256, c2 = t + 512, c3 = t + 768;
    bool has3 = (c3 < HID);
    float dn = g_dinv[n];
    float a0s = 0.f, a1s = 0.f, a2s = 0.f, a3s = 0.f;
    int lo = g_off[n], hi = g_off[n + 1];
    for (int idx = lo; idx < hi; idx++) {
        int s = g_srcA[idx];
        float norm = dn * g_dinv[s];
        const float* __restrict__ hr = g_h2 + (long)s * HID;
        a0s += hr[c0] * norm;
        a1s += hr[c1] * norm;
        a2s += hr[c2] * norm;
        if (has3) a3s += hr[c3] * norm;
    }
    float* o = g_x2 + (long)n * HID;
    o[c0] = fmaxf(a0s + gcn_b[c0], 0.f);
    o[c1] = fmaxf(a1s + gcn_b[c1], 0.f);
    o[c2] = fmaxf(a2s + gcn_b[c2], 0.f);
    if (has3) o[c3] = fmaxf(a3s + gcn_b[c3], 0.f);
}

// ---------------- pool (batch sorted -> segments) ----------------
__global__ void k_startK(const int* __restrict__ batch) {
    int n = blockIdx.x * blockDim.x + threadIdx.x;
    if (n >= NN) return;
    int b = batch[n];
    if (n == 0) {
        for (int bb = 0; bb <= b; bb++) g_start[bb] = 0;
    } else {
        int pb = batch[n - 1];
        if (pb != b) for (int bb = pb + 1; bb <= b; bb++) g_start[bb] = n;
    }
    if (n == NN - 1) {
        for (int bb = b + 1; bb <= BB; bb++) g_start[bb] = NN;
    }
}

__global__ void k_pool2() {
    int b = blockIdx.x, j = threadIdx.x;
    if (j >= HID) return;
    int lo = g_start[b], hi = g_start[b + 1];
    float s = 0.f;
    for (int n = lo; n < hi; n++) s += g_x2[(long)n * HID + j];
    g_xg[(long)b * HID + j] = s;
}

// ---------------- protein branch (factorized) ----------------
__global__ void k_P(const float* __restrict__ emb, const float* __restrict__ cW) {
    int g = blockIdx.x * blockDim.x + threadIdx.x;
    if (g >= VOC * NF * KS) return;
    int v = g / (NF * KS), r = g % (NF * KS);
    int o = r / KS, k = r % KS;
    float s = 0.f;
#pragma unroll 16
    for (int e = 0; e < EMB; e++)
        s += emb[v * EMB + e] * cW[o * EMB * KS + e * KS + k];
    g_P[g] = s;
}

__global__ void k_biasY_init(const float* __restrict__ fxt_b) {
    g_biasY[threadIdx.x] = fxt_b[threadIdx.x];
}

__global__ void k_biasY_acc(const float* __restrict__ fxtW, const float* __restrict__ cb) {
    int o = blockIdx.x, c = blockIdx.y, j = threadIdx.x;
    int t0 = c * 125, t1 = min(t0 + 125, COUT);
    float p = 0.f;
    for (int t = t0; t < t1; t++)
        p += fxtW[((long)(o * COUT + t)) * 128 + j];
    atomicAdd(&g_biasY[j], cb[o] * p);
}

__global__ void k_R(const float* __restrict__ fxtW) {
    __shared__ float Ps[VOC * NF * KS];
    int s = blockIdx.x, j = threadIdx.x;
    for (int idx = j; idx < VOC * NF * KS; idx += 128) Ps[idx] = g_P[idx];
    __syncthreads();
    float acc[VOC];
#pragma unroll
    for (int v = 0; v < VOC; v++) acc[v] = 0.f;
    int kmin = (s > COUT - 1) ? (s - (COUT - 1)) : 0;
    int kmax = (s < KS - 1) ? s : (KS - 1);
    for (int o = 0; o < NF; o++) {
        for (int k = kmin; k <= kmax; k++) {
            float w = fxtW[((long)(o * COUT + s - k)) * 128 + j];
#pragma unroll
            for (int v = 0; v < VOC; v++)
                acc[v] += Ps[v * (NF * KS) + o * KS + k] * w;
        }
    }
#pragma unroll
    for (int v = 0; v < VOC; v++)
        g_R[((long)v * SEQ + s) * 128 + j] = acc[v];
}

__global__ void k_Y(const int* __restrict__ target) {
    int b = blockIdx.x, ch = blockIdx.y, j = threadIdx.x;
    int s0 = ch * 250, s1 = s0 + 250;
    float acc = (ch == 0) ? g_biasY[j] : 0.f;
#pragma unroll 4
    for (int s = s0; s < s1; s++) {
        int v = target[b * SEQ + s];
        acc += g_R[((long)v * SEQ + s) * 128 + j];
    }
    atomicAdd(&g_xc[b * 256 + 128 + j], acc);
}

// ---------------- output ----------------
__global__ void k_out(const float* __restrict__ oW, const float* __restrict__ ob,
                      float* __restrict__ out) {
    __shared__ float red[4];
    int b = blockIdx.x, j = threadIdx.x;
    float v = g_t5[b * 128 + j] * oW[j];
#pragma unroll
    for (int off = 16; off; off >>= 1) v += __shfl_down_sync(0xffffffffu, v, off);
    if ((j & 31) == 0) red[j >> 5] = v;
    __syncthreads();
    if (j == 0) out[b] = red[0] + red[1] + red[2] + red[3] + ob[0];
}

// ---------------- host ----------------
static inline dim3 ggrid(long n, int t) { return dim3((unsigned)((n + t - 1) / t)); }

extern "C" void kernel_launch(void* const* d_in, const int* in_sizes, int n_in,
                              void* d_out, int out_size) {
    const float* x      = (const float*)d_in[0];
    const int*   edge   = (const int*)  d_in[1];
    const int*   batch  = (const int*)  d_in[2];
    const int*   target = (const int*)  d_in[3];
    const float* gat_W  = (const float*)d_in[4];
    const float* a_src  = (const float*)d_in[5];
    const float* a_dst  = (const float*)d_in[6];
    const float* gat_b  = (const float*)d_in[7];
    const float* gcn_W  = (const float*)d_in[8];
    const float* gcn_b  = (const float*)d_in[9];
    const float* fcg1_W = (const float*)d_in[10];
    const float* fcg1_b = (const float*)d_in[11];
    const float* fcg2_W = (const float*)d_in[12];
    const float* fcg2_b = (const float*)d_in[13];
    const float* emb    = (const float*)d_in[14];
    const float* cW     = (const float*)d_in[15];
    const float* cb     = (const float*)d_in[16];
    const float* fxt_W  = (const float*)d_in[17];
    const float* fxt_b  = (const float*)d_in[18];
    const float* f1_W   = (const float*)d_in[19];
    const float* f1_b   = (const float*)d_in[20];
    const float* f2_W   = (const float*)d_in[21];
    const float* f2_b   = (const float*)d_in[22];
    const float* f3_W   = (const float*)d_in[23];
    const float* f3_b   = (const float*)d_in[24];
    const float* f4_W   = (const float*)d_in[25];
    const float* f4_b   = (const float*)d_in[26];
    const float* o_W    = (const float*)d_in[27];
    const float* o_b    = (const float*)d_in[28];
    float* out = (float*)d_out;

    float *p_h, *p_agg, *p_h2, *p_m, *p_den, *p_xg, *p_xp, *p_Wp;
    float *p_t1, *p_xc, *p_t2, *p_t3, *p_t4, *p_t5;
    int *p_cnt;
    cudaGetSymbolAddress((void**)&p_h,   g_h);
    cudaGetSymbolAddress((void**)&p_agg, g_agg);
    cudaGetSymbolAddress((void**)&p_h2,  g_h2);
    cudaGetSymbolAddress((void**)&p_m,   g_m);
    cudaGetSymbolAddress((void**)&p_den, g_den);
    cudaGetSymbolAddress((void**)&p_xg,  g_xg);
    cudaGetSymbolAddress((void**)&p_xp,  g_xp);
    cudaGetSymbolAddress((void**)&p_Wp,  g_Wp);
    cudaGetSymbolAddress((void**)&p_t1,  g_t1);
    cudaGetSymbolAddress((void**)&p_xc,  g_xc);
    cudaGetSymbolAddress((void**)&p_t2,  g_t2);
    cudaGetSymbolAddress((void**)&p_t3,  g_t3);
    cudaGetSymbolAddress((void**)&p_t4,  g_t4);
    cudaGetSymbolAddress((void**)&p_t5,  g_t5);
    cudaGetSymbolAddress((void**)&p_cnt, g_cnt);

    // ---- init ----
    kfill<<<ggrid(NN * HH, 256), 256>>>(p_m,   -INFINITY, NN * HH);
    kfill<<<ggrid(NN * HH, 256), 256>>>(p_den, 0.f, NN * HH);
    kfillI<<<ggrid(NN, 256), 256>>>(p_cnt, 0, NN);
    kfill<<<ggrid(BB * 256, 256), 256>>>(p_xc, 0.f, BB * 256);

    // ---- protein branch precompute (independent) ----
    k_P<<<ggrid(VOC * NF * KS, 256), 256>>>(emb, cW);
    k_biasY_init<<<1, 128>>>(fxt_b);
    k_biasY_acc<<<dim3(NF, 8), 128>>>(fxt_W, cb);
    k_R<<<SEQ, 128>>>(fxt_W);

    // ---- GAT GEMM (padded K for float4 alignment) ----
    k_padx<<<ggrid((long)NN * FFP, 256), 256>>>(x);
    k_padW<<<ggrid(FFP * HID, 256), 256>>>(gat_W);
    sgemm2<<<dim3((HID + 127) / 128, (NN + 127) / 128), 256>>>(
        p_xp, p_Wp, p_h, nullptr, NN, HID, FFP, FFP, HID, HID, 0, 0);

    // ---- attention ----
    k_attn_coef<<<ggrid(NN * HH, 256), 256>>>(a_src, a_dst);

    // ---- CSR build ----
    k_count<<<ggrid(ET, 256), 256>>>(edge);
    k_scan<<<1, 256>>>();
    kfillI<<<ggrid(NN, 256), 256>>>(p_cnt, 0, NN);
    k_scatter<<<ggrid(ET, 256), 256>>>(edge);

    // ---- softmax over edges ----
    k_edgeA<<<ggrid(ET, 256), 256>>>(edge);
    k_edgeB<<<ggrid((long)ET * HH, 256), 256>>>(edge);
    k_alpha<<<ggrid((long)ET * HH, 256), 256>>>(edge);

    // ---- GAT aggregation (CSR, fused bias+relu) ----
    k_gat_agg<<<NN, 256>>>(gat_b);

    // ---- GCN ----
    sgemm2<<<dim3((HID + 127) / 128, (NN + 127) / 128), 256>>>(
        p_agg, gcn_W, p_h2, nullptr, NN, HID, HID, HID, HID, HID, 0, 0);
    k_gcn_agg<<<NN, 256>>>(gcn_b);

    // ---- pool ----
    k_startK<<<ggrid(NN, 256), 256>>>(batch);
    k_pool2<<<BB, HID>>>();

    // ---- graph MLP head ----
    sgemm2<<<dim3(12, 2), 256>>>(p_xg, fcg1_W, p_t1, fcg1_b, BB, 1500, HID, HID, 1500, 1500, 0, 1);
    sgemm2<<<dim3(1, 2), 256>>>(p_t1, fcg2_W, p_xc, fcg2_b, BB, 128, 1500, 1500, 128, 256, 0, 0);

    // ---- protein gather ----
    k_Y<<<dim3(BB, 4), 128>>>(target);

    // ---- fusion MLP ----
    sgemm2<<<dim3(8, 2), 256>>>(p_xc, f1_W, p_t2, f1_b, BB, 1024, 256, 256, 1024, 1024, 0, 1);
    sgemm2<<<dim3(4, 2), 256>>>(p_t2, f2_W, p_t3, f2_b, BB, 512, 1024, 1024, 512, 512, 0, 1);
    sgemm2<<<dim3(2, 2), 256>>>(p_t3, f3_W, p_t4, f3_b, BB, 256, 512, 512, 256, 256, 0, 1);
    sgemm2<<<dim3(1, 2), 256>>>(p_t4, f4_W, p_t5, f4_b, BB, 128, 256, 256, 128, 128, 0, 1);
    k_out<<<BB, 128>>>(o_W, o_b, out);
}

// round 4
// speedup vs baseline: 4.1636x; 1.3907x over previous
#include <cuda_runtime.h>
#include <cuda_bf16.h>
#include <math.h>
#include <stdint.h>

#define NN   20000
#define EE   400000
#define ET   (EE + NN)
#define HH   10
#define FF   78
#define HID  780
#define BB   200
#define SEQ  1000
#define VOC  26
#define EMB  128
#define NF   32
#define KS   8
#define COUT 993
#define KPA  128   // padded K for GAT gemm (78 -> 128)
#define KPG  832   // padded K for GCN gemm (780 -> 832)

// ---------------- scratch ----------------
__device__ float g_h  [NN * HID];
__device__ float g_h2 [NN * HID];
__device__ float g_x2 [NN * HID];
__device__ float g_as [NN * HH];
__device__ float g_ad [NN * HH];
__device__ float g_e  [(long)ET * HH];       // alpha, CSR-ordered
__device__ float g_xg [BB * HID];
__device__ float g_t1 [BB * 1500];
__device__ float g_xc [BB * 256];
__device__ float g_t2 [BB * 1024];
__device__ float g_t3 [BB * 512];
__device__ float g_t4 [BB * 256];
__device__ float g_t5 [BB * 128];
__device__ float g_P  [VOC * NF * KS];
__device__ float g_R  [(long)VOC * SEQ * 128];
__device__ float g_biasY[128];
__device__ int   g_cnt[NN];
__device__ int   g_off[NN + 1];
__device__ int   g_srcA[ET];
__device__ int   g_start[BB + 1];
__device__ float g_dinv[NN];
__device__ __nv_bfloat16 g_Axh[(long)NN * KPA];
__device__ __nv_bfloat16 g_Axl[(long)NN * KPA];
__device__ __nv_bfloat16 g_Bah[(long)HID * KPA];
__device__ __nv_bfloat16 g_Bal[(long)HID * KPA];
__device__ __nv_bfloat16 g_Agh[(long)NN * KPG];
__device__ __nv_bfloat16 g_Agl[(long)NN * KPG];
__device__ __nv_bfloat16 g_Bgh[(long)HID * KPG];
__device__ __nv_bfloat16 g_Bgl[(long)HID * KPG];

// ---------------- helpers ----------------
__device__ __forceinline__ uint32_t smem_u32(const void* p) {
    uint32_t a;
    asm("{ .reg .u64 t; cvta.to.shared.u64 t, %1; cvt.u32.u64 %0, t; }" : "=r"(a) : "l"(p));
    return a;
}
__device__ __forceinline__ void cpasync16(uint32_t dst, const void* src, int nbytes) {
    asm volatile("cp.async.cg.shared.global [%0], [%1], 16, %2;"
                 :: "r"(dst), "l"(__cvta_generic_to_global(src)), "r"(nbytes) : "memory");
}
__device__ __forceinline__ void ldm4(uint32_t* r, uint32_t addr) {
    asm volatile("ldmatrix.sync.aligned.m8n8.x4.shared.b16 {%0,%1,%2,%3}, [%4];"
                 : "=r"(r[0]), "=r"(r[1]), "=r"(r[2]), "=r"(r[3]) : "r"(addr));
}
__device__ __forceinline__ void mma16816(float* c, const uint32_t* a, uint32_t b0, uint32_t b1) {
    asm volatile("mma.sync.aligned.m16n8k16.row.col.f32.bf16.bf16.f32 "
                 "{%0,%1,%2,%3}, {%4,%5,%6,%7}, {%8,%9}, {%0,%1,%2,%3};"
                 : "+f"(c[0]), "+f"(c[1]), "+f"(c[2]), "+f"(c[3])
                 : "r"(a[0]), "r"(a[1]), "r"(a[2]), "r"(a[3]), "r"(b0), "r"(b1));
}

// ---------------- f32x2 packed FMA (small MLP GEMMs) ----------------
#define PK2(d, lo, hi) asm("mov.b64 %0, {%1,%2};" : "=l"(d) : "r"(__float_as_uint(lo)), "r"(__float_as_uint(hi)))
#define FMA2(d, a, b)  asm("fma.rn.f32x2 %0, %1, %2, %3;" : "=l"(d) : "l"(a), "l"(b), "l"(d))
#define UPK2(lo, hi, s) { unsigned int u0_, u1_; asm("mov.b64 {%0,%1}, %2;" : "=r"(u0_), "=r"(u1_) : "l"(s)); lo = __uint_as_float(u0_); hi = __uint_as_float(u1_); }

// ---------------- utility ----------------
__global__ void kfill(float* p, float v, int n) {
    int i = blockIdx.x * blockDim.x + threadIdx.x;
    if (i < n) p[i] = v;
}
__global__ void kfillI(int* p, int v, int n) {
    int i = blockIdx.x * blockDim.x + threadIdx.x;
    if (i < n) p[i] = v;
}

// ============ bf16x3 tensor-core GEMM via mma.sync ============
// C[M,N] = A[M,Kp] * Bt[N,Kp]^T ; A=Ah+Al, B=Bh+Bl; compute hh+hl+lh in fp32 acc.
#define KC 32
#define ASTR 40                       // bf16 units per smem row (32 + 8 pad)
#define HALF_BYTES (128 * ASTR * 2)   // 10240
#define STAGE_BYTES (4 * HALF_BYTES)  // Ah, Al, Bh, Bl
#define GEMM_SMEM (2 * STAGE_BYTES)   // 81920

__global__ void __launch_bounds__(256)
gemm_mma(const __nv_bfloat16* __restrict__ Ah, const __nv_bfloat16* __restrict__ Al,
         const __nv_bfloat16* __restrict__ Bh, const __nv_bfloat16* __restrict__ Bl,
         float* __restrict__ C, int M, int N, int Kp, int NC, int ldc) {
    extern __shared__ char smem_raw[];
    uint32_t sb = smem_u32(smem_raw);
    int tid = threadIdx.x, w = tid >> 5, l = tid & 31;
    int m0 = blockIdx.y * 128, n0 = blockIdx.x * 128;
    int wm = w & 3, wn = w >> 2;       // warp tile: rows wm*32..+31, cols wn*64..+63

    float acc[2][8][4];
#pragma unroll
    for (int i = 0; i < 2; i++)
#pragma unroll
        for (int j = 0; j < 8; j++)
#pragma unroll
            for (int q = 0; q < 4; q++) acc[i][j][q] = 0.f;

    auto issue = [&](int c) {
        int k0 = c * KC;
        uint32_t st = sb + (uint32_t)(c & 1) * STAGE_BYTES;
#pragma unroll
        for (int p = 0; p < 2; p++) {
            int f = tid + p * 256;
            int row = f >> 2, c16 = f & 3;
            uint32_t doff = (uint32_t)(row * (ASTR * 2) + c16 * 16);
            int am = m0 + row;
            int amc = am < M ? am : M - 1;
            int av = am < M ? 16 : 0;
            long aoff = (long)amc * Kp + k0 + c16 * 8;
            cpasync16(st + doff, Ah + aoff, av);
            cpasync16(st + HALF_BYTES + doff, Al + aoff, av);
            int bn = n0 + row;
            int bnc = bn < N ? bn : N - 1;
            int bv = bn < N ? 16 : 0;
            long boff = (long)bnc * Kp + k0 + c16 * 8;
            cpasync16(st + 2 * HALF_BYTES + doff, Bh + boff, bv);
            cpasync16(st + 3 * HALF_BYTES + doff, Bl + boff, bv);
        }
        asm volatile("cp.async.commit_group;" ::: "memory");
    };

    issue(0);
    for (int c = 0; c < NC; c++) {
        if (c + 1 < NC) {
            issue(c + 1);
            asm volatile("cp.async.wait_group 1;" ::: "memory");
        } else {
            asm volatile("cp.async.wait_group 0;" ::: "memory");
        }
        __syncthreads();
        uint32_t st = sb + (uint32_t)(c & 1) * STAGE_BYTES;
#pragma unroll
        for (int k16 = 0; k16 < 2; k16++) {
            int lrow = l & 15, lcb = l >> 4;   // ldmatrix row / col-block
            uint32_t coff = (uint32_t)((k16 * 16 + lcb * 8) * 2);
            // B fragments: 4 pairs of n8 tiles, hi and lo
            uint32_t bh[4][4], bl[4][4];
#pragma unroll
            for (int nt2 = 0; nt2 < 4; nt2++) {
                uint32_t roff = (uint32_t)((wn * 64 + nt2 * 16 + lrow) * (ASTR * 2));
                ldm4(bh[nt2], st + 2 * HALF_BYTES + roff + coff);
                ldm4(bl[nt2], st + 3 * HALF_BYTES + roff + coff);
            }
#pragma unroll
            for (int mt = 0; mt < 2; mt++) {
                uint32_t roff = (uint32_t)((wm * 32 + mt * 16 + lrow) * (ASTR * 2));
                uint32_t ah[4], al[4];
                ldm4(ah, st + roff + coff);
                ldm4(al, st + HALF_BYTES + roff + coff);
#pragma unroll
                for (int nt = 0; nt < 8; nt++) {
                    int nt2 = nt >> 1, sel = nt & 1;
                    uint32_t b0h = bh[nt2][sel], b1h = bh[nt2][sel + 2];
                    uint32_t b0l = bl[nt2][sel], b1l = bl[nt2][sel + 2];
                    mma16816(acc[mt][nt], ah, b0h, b1h);   // hi*hi
                    mma16816(acc[mt][nt], ah, b0l, b1l);   // hi*lo
                    mma16816(acc[mt][nt], al, b0h, b1h);   // lo*hi
                }
            }
        }
        __syncthreads();
    }

    // epilogue
#pragma unroll
    for (int mt = 0; mt < 2; mt++) {
#pragma unroll
        for (int nt = 0; nt < 8; nt++) {
            int row = m0 + wm * 32 + mt * 16 + (l >> 2);
            int col = n0 + wn * 64 + nt * 8 + 2 * (l & 3);
            float* cp0 = C + (long)row * ldc + col;
            if (row < M) {
                if (col + 1 < N) { cp0[0] = acc[mt][nt][0]; cp0[1] = acc[mt][nt][1]; }
                else if (col < N) cp0[0] = acc[mt][nt][0];
            }
            int row2 = row + 8;
            float* cp1 = C + (long)row2 * ldc + col;
            if (row2 < M) {
                if (col + 1 < N) { cp1[0] = acc[mt][nt][2]; cp1[1] = acc[mt][nt][3]; }
                else if (col < N) cp1[0] = acc[mt][nt][2];
            }
        }
    }
}

// ---------------- bf16 splits ----------------
__global__ void k_split(const float* __restrict__ src, __nv_bfloat16* __restrict__ dh,
                        __nv_bfloat16* __restrict__ dl, int M, int Ksrc, int Kp) {
    long i = (long)blockIdx.x * blockDim.x + threadIdx.x;
    if (i >= (long)M * Kp) return;
    int m = (int)(i / Kp), k = (int)(i % Kp);
    float v = (k < Ksrc) ? src[(long)m * Ksrc + k] : 0.f;
    __nv_bfloat16 h = __float2bfloat16(v);
    dh[i] = h;
    dl[i] = __float2bfloat16(v - __bfloat162float(h));
}
__global__ void k_splitT(const float* __restrict__ W, __nv_bfloat16* __restrict__ dh,
                         __nv_bfloat16* __restrict__ dl, int K, int N, int Kp) {
    long i = (long)blockIdx.x * blockDim.x + threadIdx.x;
    if (i >= (long)N * Kp) return;
    int n = (int)(i / Kp), k = (int)(i % Kp);
    float v = (k < K) ? W[(long)k * N + n] : 0.f;
    __nv_bfloat16 h = __float2bfloat16(v);
    dh[i] = h;
    dl[i] = __float2bfloat16(v - __bfloat162float(h));
}

// ---------------- SGEMM (FFMA2) for small MLP layers ----------------
#define BKg 16
__global__ void __launch_bounds__(256)
sgemm2(const float* __restrict__ A, const float* __restrict__ B,
       float* __restrict__ C, const float* __restrict__ bias,
       int M, int N, int K, int lda, int ldb, int ldc, int coff, int relu) {
    __shared__ float As[2][BKg][132];
    __shared__ float Bs[2][BKg][128];
    int tid = threadIdx.x;
    int m0 = blockIdx.y * 128, n0 = blockIdx.x * 128;
    int ty = tid >> 4, tx = tid & 15;

    unsigned long long acc2[8][4];
#pragma unroll
    for (int i = 0; i < 8; i++)
#pragma unroll
        for (int j = 0; j < 4; j++) acc2[i][j] = 0ull;

    float4 ra[2], rb[2];
    auto loadStage = [&](int kT) {
#pragma unroll
        for (int p = 0; p < 2; p++) {
            int f = tid + p * 256;
            int m = f >> 2, kq = f & 3;
            int gm = m0 + m, gk = kT + kq * 4;
            const float* ap = A + (long)gm * lda + gk;
            if (gm < M && gk + 3 < K) ra[p] = *(const float4*)ap;
            else {
                ra[p].x = (gm < M && gk     < K) ? ap[0] : 0.f;
                ra[p].y = (gm < M && gk + 1 < K) ? ap[1] : 0.f;
                ra[p].z = (gm < M && gk + 2 < K) ? ap[2] : 0.f;
                ra[p].w = (gm < M && gk + 3 < K) ? ap[3] : 0.f;
            }
        }
#pragma unroll
        for (int p = 0; p < 2; p++) {
            int f = tid + p * 256;
            int kr = f >> 5, nq = f & 31;
            int gk = kT + kr, gn = n0 + nq * 4;
            const float* bp = B + (long)gk * ldb + gn;
            if (gk < K && gn + 3 < N) rb[p] = *(const float4*)bp;
            else {
                rb[p].x = (gk < K && gn     < N) ? bp[0] : 0.f;
                rb[p].y = (gk < K && gn + 1 < N) ? bp[1] : 0.f;
                rb[p].z = (gk < K && gn + 2 < N) ? bp[2] : 0.f;
                rb[p].w = (gk < K && gn + 3 < N) ? bp[3] : 0.f;
            }
        }
    };
    auto storeStage = [&](int buf) {
#pragma unroll
        for (int p = 0; p < 2; p++) {
            int f = tid + p * 256;
            int m = f >> 2, kq = f & 3;
            As[buf][kq * 4 + 0][m] = ra[p].x;
            As[buf][kq * 4 + 1][m] = ra[p].y;
            As[buf][kq * 4 + 2][m] = ra[p].z;
            As[buf][kq * 4 + 3][m] = ra[p].w;
        }
#pragma unroll
        for (int p = 0; p < 2; p++) {
            int f = tid + p * 256;
            int kr = f >> 5, nq = f & 31;
            *(float4*)&Bs[buf][kr][nq * 4] = rb[p];
        }
    };

    int buf = 0;
    loadStage(0);
    storeStage(0);
    __syncthreads();

    for (int kT = 0;;) {
        int kN = kT + BKg;
        bool more = kN < K;
        if (more) loadStage(kN);
#pragma unroll
        for (int kk = 0; kk < BKg; kk++) {
            float4 a0 = *(const float4*)&As[buf][kk][ty * 8];
            float4 a1 = *(const float4*)&As[buf][kk][ty * 8 + 4];
            float4 b0 = *(const float4*)&Bs[buf][kk][tx * 8];
            float4 b1 = *(const float4*)&Bs[buf][kk][tx * 8 + 4];
            unsigned long long bp0, bp1, bp2, bp3;
            PK2(bp0, b0.x, b0.y); PK2(bp1, b0.z, b0.w);
            PK2(bp2, b1.x, b1.y); PK2(bp3, b1.z, b1.w);
            float av[8] = {a0.x, a0.y, a0.z, a0.w, a1.x, a1.y, a1.z, a1.w};
#pragma unroll
            for (int i = 0; i < 8; i++) {
                unsigned long long aa;
                PK2(aa, av[i], av[i]);
                FMA2(acc2[i][0], aa, bp0);
                FMA2(acc2[i][1], aa, bp1);
                FMA2(acc2[i][2], aa, bp2);
                FMA2(acc2[i][3], aa, bp3);
            }
        }
        if (!more) break;
        storeStage(buf ^ 1);
        buf ^= 1; kT = kN;
        __syncthreads();
    }

#pragma unroll
    for (int i = 0; i < 8; i++) {
        int row = m0 + ty * 8 + i;
        if (row >= M) continue;
        float cv[8];
        UPK2(cv[0], cv[1], acc2[i][0]);
        UPK2(cv[2], cv[3], acc2[i][1]);
        UPK2(cv[4], cv[5], acc2[i][2]);
        UPK2(cv[6], cv[7], acc2[i][3]);
#pragma unroll
        for (int j = 0; j < 8; j++) {
            int col = n0 + tx * 8 + j;
            if (col >= N) continue;
            float v = cv[j] + (bias ? bias[col] : 0.f);
            if (relu) v = fmaxf(v, 0.f);
            C[(long)row * ldc + coff + col] = v;
        }
    }
}

// ---------------- GAT attention coefficients ----------------
__global__ void k_attn_coef(const float* __restrict__ aS, const float* __restrict__ aD) {
    int g = blockIdx.x * blockDim.x + threadIdx.x;
    if (g >= NN * HH) return;
    int n = g / HH, h = g % HH;
    const float* hp = g_h + (long)n * HID + h * FF;
    float s = 0.f, d = 0.f;
#pragma unroll 13
    for (int f = 0; f < FF; f++) {
        float hv = hp[f];
        s += hv * aS[h * FF + f];
        d += hv * aD[h * FF + f];
    }
    g_as[g] = s;
    g_ad[g] = d;
}

// ---------------- CSR build ----------------
__global__ void k_count(const int* __restrict__ edge) {
    int i = blockIdx.x * blockDim.x + threadIdx.x;
    if (i >= ET) return;
    int dst = (i < EE) ? edge[EE + i] : i - EE;
    atomicAdd(&g_cnt[dst], 1);
}
__global__ void k_scan() {
    __shared__ int part[256];
    int tid = threadIdx.x;
    const int chunk = (NN + 255) / 256;
    int lo = tid * chunk, hi = min(lo + chunk, NN);
    int s = 0;
    for (int n = lo; n < hi; n++) s += g_cnt[n];
    part[tid] = s;
    __syncthreads();
    if (tid == 0) {
        int r = 0;
        for (int i = 0; i < 256; i++) { int t = part[i]; part[i] = r; r += t; }
        g_off[NN] = r;
    }
    __syncthreads();
    int r = part[tid];
    for (int n = lo; n < hi; n++) {
        g_off[n] = r;
        int c = g_cnt[n];
        r += c;
        g_dinv[n] = rsqrtf((float)(c > 0 ? c : 1));
    }
}
__global__ void k_scatter(const int* __restrict__ edge) {
    int i = blockIdx.x * blockDim.x + threadIdx.x;
    if (i >= ET) return;
    int src = (i < EE) ? edge[i]      : i - EE;
    int dst = (i < EE) ? edge[EE + i] : i - EE;
    int pos = g_off[dst] + atomicAdd(&g_cnt[dst], 1);
    g_srcA[pos] = src;
}

// ---------------- per-node softmax (smem atomics only) ----------------
__device__ __forceinline__ uint32_t fmapU(float f) {
    uint32_t u = __float_as_uint(f);
    return u ^ (uint32_t)(((int)u >> 31) | 0x80000000);
}
__device__ __forceinline__ float finvU(uint32_t u) {
    return (u & 0x80000000u) ? __uint_as_float(u ^ 0x80000000u) : __uint_as_float(~u);
}
__global__ void __launch_bounds__(128) k_soft() {
    __shared__ uint32_t sm[HH];
    __shared__ float sden[HH];
    int n = blockIdx.x, t = threadIdx.x;
    int lo = g_off[n], tot = (g_off[n + 1] - lo) * HH;
    if (t < HH) { sm[t] = fmapU(-INFINITY); sden[t] = 0.f; }
    __syncthreads();
    for (int p = t; p < tot; p += 128) {
        int i = p / HH, h = p % HH;
        int src = g_srcA[lo + i];
        float e = g_as[src * HH + h] + g_ad[n * HH + h];
        e = (e > 0.f) ? e : 0.2f * e;
        g_e[(long)(lo + i) * HH + h] = e;
        atomicMax(&sm[h], fmapU(e));
    }
    __syncthreads();
    for (int p = t; p < tot; p += 128) {
        int i = p / HH, h = p % HH;
        long idx = (long)(lo + i) * HH + h;
        float ex = expf(g_e[idx] - finvU(sm[h]));
        g_e[idx] = ex;
        atomicAdd(&sden[h], ex);
    }
    __syncthreads();
    for (int p = t; p < tot; p += 128) {
        int i = p / HH, h = p % HH;
        long idx = (long)(lo + i) * HH + h;
        g_e[idx] = g_e[idx] / sden[h];
    }
}

// ---------------- GAT aggregation (float4, fused bias+relu+bf16 split) ----------------
__global__ void __launch_bounds__(256) k_gat_agg(const float* __restrict__ gat_b) {
    int n = blockIdx.x, t = threadIdx.x;
    if (t >= 208) return;
    if (t >= 195) {  // pad cols 780..831 of the bf16 split
        __nv_bfloat16 z = __float2bfloat16(0.f);
        long base = (long)n * KPG + t * 4;
#pragma unroll
        for (int c = 0; c < 4; c++) { g_Agh[base + c] = z; g_Agl[base + c] = z; }
        return;
    }
    int q = t * 4;
    int h0 = q / FF, h1 = (q + 1) / FF, h2 = (q + 2) / FF, h3 = (q + 3) / FF;
    float ax = 0.f, ay = 0.f, az = 0.f, aw = 0.f;
    int lo = g_off[n], hi = g_off[n + 1];
    for (int idx = lo; idx < hi; idx++) {
        int s = g_srcA[idx];
        float4 hv = *(const float4*)(g_h + (long)s * HID + q);
        const float* __restrict__ al = g_e + (long)idx * HH;
        ax += hv.x * al[h0];
        ay += hv.y * al[h1];
        az += hv.z * al[h2];
        aw += hv.w * al[h3];
    }
    float v[4];
    v[0] = fmaxf(ax + gat_b[q + 0], 0.f);
    v[1] = fmaxf(ay + gat_b[q + 1], 0.f);
    v[2] = fmaxf(az + gat_b[q + 2], 0.f);
    v[3] = fmaxf(aw + gat_b[q + 3], 0.f);
    long base = (long)n * KPG + q;
#pragma unroll
    for (int c = 0; c < 4; c++) {
        __nv_bfloat16 hb = __float2bfloat16(v[c]);
        g_Agh[base + c] = hb;
        g_Agl[base + c] = __float2bfloat16(v[c] - __bfloat162float(hb));
    }
}

// ---------------- GCN aggregation (float4) ----------------
__global__ void __launch_bounds__(256) k_gcn_agg(const float* __restrict__ gcn_b) {
    int n = blockIdx.x, t = threadIdx.x;
    if (t >= 195) return;
    int q = t * 4;
    float dn = g_dinv[n];
    float ax = 0.f, ay = 0.f, az = 0.f, aw = 0.f;
    int lo = g_off[n], hi = g_off[n + 1];
    for (int idx = lo; idx < hi; idx++) {
        int s = g_srcA[idx];
        float norm = dn * g_dinv[s];
        float4 hv = *(const float4*)(g_h2 + (long)s * HID + q);
        ax += hv.x * norm;
        ay += hv.y * norm;
        az += hv.z * norm;
        aw += hv.w * norm;
    }
    float4 o;
    o.x = fmaxf(ax + gcn_b[q + 0], 0.f);
    o.y = fmaxf(ay + gcn_b[q + 1], 0.f);
    o.z = fmaxf(az + gcn_b[q + 2], 0.f);
    o.w = fmaxf(aw + gcn_b[q + 3], 0.f);
    *(float4*)(g_x2 + (long)n * HID + q) = o;
}

// ---------------- pool ----------------
__global__ void k_startK(const int* __restrict__ batch) {
    int n = blockIdx.x * blockDim.x + threadIdx.x;
    if (n >= NN) return;
    int b = batch[n];
    if (n == 0) {
        for (int bb = 0; bb <= b; bb++) g_start[bb] = 0;
    } else {
        int pb = batch[n - 1];
        if (pb != b) for (int bb = pb + 1; bb <= b; bb++) g_start[bb] = n;
    }
    if (n == NN - 1) {
        for (int bb = b + 1; bb <= BB; bb++) g_start[bb] = NN;
    }
}
__global__ void k_pool2() {
    int b = blockIdx.x, j = threadIdx.x;
    if (j >= HID) return;
    int lo = g_start[b], hi = g_start[b + 1];
    float s = 0.f;
    for (int n = lo; n < hi; n++) s += g_x2[(long)n * HID + j];
    g_xg[(long)b * HID + j] = s;
}

// ---------------- protein branch ----------------
__global__ void k_P(const float* __restrict__ emb, const float* __restrict__ cW) {
    int g = blockIdx.x * blockDim.x + threadIdx.x;
    if (g >= VOC * NF * KS) return;
    int v = g / (NF * KS), r = g % (NF * KS);
    int o = r / KS, k = r % KS;
    float s = 0.f;
#pragma unroll 16
    for (int e = 0; e < EMB; e++)
        s += emb[v * EMB + e] * cW[o * EMB * KS + e * KS + k];
    g_P[g] = s;
}
__global__ void k_biasY_init(const float* __restrict__ fxt_b) {
    g_biasY[threadIdx.x] = fxt_b[threadIdx.x];
}
__global__ void k_biasY_acc(const float* __restrict__ fxtW, const float* __restrict__ cb) {
    int o = blockIdx.x, c = blockIdx.y, j = threadIdx.x;
    int t0 = c * 125, t1 = min(t0 + 125, COUT);
    float p = 0.f;
    for (int t = t0; t < t1; t++)
        p += fxtW[((long)(o * COUT + t)) * 128 + j];
    atomicAdd(&g_biasY[j], cb[o] * p);
}
__global__ void k_R(const float* __restrict__ fxtW) {
    __shared__ float Ps[VOC * NF * KS];
    int s = blockIdx.x, j = threadIdx.x;
    for (int idx = j; idx < VOC * NF * KS; idx += 128) Ps[idx] = g_P[idx];
    __syncthreads();
    float acc[VOC];
#pragma unroll
    for (int v = 0; v < VOC; v++) acc[v] = 0.f;
    int kmin = (s > COUT - 1) ? (s - (COUT - 1)) : 0;
    int kmax = (s < KS - 1) ? s : (KS - 1);
    for (int o = 0; o < NF; o++) {
        for (int k = kmin; k <= kmax; k++) {
            float w = fxtW[((long)(o * COUT + s - k)) * 128 + j];
#pragma unroll
            for (int v = 0; v < VOC; v++)
                acc[v] += Ps[v * (NF * KS) + o * KS + k] * w;
        }
    }
#pragma unroll
    for (int v = 0; v < VOC; v++)
        g_R[((long)v * SEQ + s) * 128 + j] = acc[v];
}
__global__ void k_Y(const int* __restrict__ target) {
    int b = blockIdx.x, ch = blockIdx.y, j = threadIdx.x;
    int s0 = ch * 125, s1 = s0 + 125;
    float acc = (ch == 0) ? g_biasY[j] : 0.f;
#pragma unroll 5
    for (int s = s0; s < s1; s++) {
        int v = target[b * SEQ + s];
        acc += g_R[((long)v * SEQ + s) * 128 + j];
    }
    atomicAdd(&g_xc[b * 256 + 128 + j], acc);
}

// ---------------- output ----------------
__global__ void k_out(const float* __restrict__ oW, const float* __restrict__ ob,
                      float* __restrict__ out) {
    __shared__ float red[4];
    int b = blockIdx.x, j = threadIdx.x;
    float v = g_t5[b * 128 + j] * oW[j];
#pragma unroll
    for (int off = 16; off; off >>= 1) v += __shfl_down_sync(0xffffffffu, v, off);
    if ((j & 31) == 0) red[j >> 5] = v;
    __syncthreads();
    if (j == 0) out[b] = red[0] + red[1] + red[2] + red[3] + ob[0];
}

// ---------------- host ----------------
static inline dim3 ggrid(long n, int t) { return dim3((unsigned)((n + t - 1) / t)); }

extern "C" void kernel_launch(void* const* d_in, const int* in_sizes, int n_in,
                              void* d_out, int out_size) {
    const float* x      = (const float*)d_in[0];
    const int*   edge   = (const int*)  d_in[1];
    const int*   batch  = (const int*)  d_in[2];
    const int*   target = (const int*)  d_in[3];
    const float* gat_W  = (const float*)d_in[4];
    const float* a_src  = (const float*)d_in[5];
    const float* a_dst  = (const float*)d_in[6];
    const float* gat_b  = (const float*)d_in[7];
    const float* gcn_W  = (const float*)d_in[8];
    const float* gcn_b  = (const float*)d_in[9];
    const float* fcg1_W = (const float*)d_in[10];
    const float* fcg1_b = (const float*)d_in[11];
    const float* fcg2_W = (const float*)d_in[12];
    const float* fcg2_b = (const float*)d_in[13];
    const float* emb    = (const float*)d_in[14];
    const float* cW     = (const float*)d_in[15];
    const float* cb     = (const float*)d_in[16];
    const float* fxt_W  = (const float*)d_in[17];
    const float* fxt_b  = (const float*)d_in[18];
    const float* f1_W   = (const float*)d_in[19];
    const float* f1_b   = (const float*)d_in[20];
    const float* f2_W   = (const float*)d_in[21];
    const float* f2_b   = (const float*)d_in[22];
    const float* f3_W   = (const float*)d_in[23];
    const float* f3_b   = (const float*)d_in[24];
    const float* f4_W   = (const float*)d_in[25];
    const float* f4_b   = (const float*)d_in[26];
    const float* o_W    = (const float*)d_in[27];
    const float* o_b    = (const float*)d_in[28];
    float* out = (float*)d_out;

    float *p_h, *p_h2, *p_xg, *p_t1, *p_xc, *p_t2, *p_t3, *p_t4, *p_t5;
    int* p_cnt;
    __nv_bfloat16 *p_Axh, *p_Axl, *p_Bah, *p_Bal, *p_Agh, *p_Agl, *p_Bgh, *p_Bgl;
    cudaGetSymbolAddress((void**)&p_h,   g_h);
    cudaGetSymbolAddress((void**)&p_h2,  g_h2);
    cudaGetSymbolAddress((void**)&p_xg,  g_xg);
    cudaGetSymbolAddress((void**)&p_t1,  g_t1);
    cudaGetSymbolAddress((void**)&p_xc,  g_xc);
    cudaGetSymbolAddress((void**)&p_t2,  g_t2);
    cudaGetSymbolAddress((void**)&p_t3,  g_t3);
    cudaGetSymbolAddress((void**)&p_t4,  g_t4);
    cudaGetSymbolAddress((void**)&p_t5,  g_t5);
    cudaGetSymbolAddress((void**)&p_cnt, g_cnt);
    cudaGetSymbolAddress((void**)&p_Axh, g_Axh);
    cudaGetSymbolAddress((void**)&p_Axl, g_Axl);
    cudaGetSymbolAddress((void**)&p_Bah, g_Bah);
    cudaGetSymbolAddress((void**)&p_Bal, g_Bal);
    cudaGetSymbolAddress((void**)&p_Agh, g_Agh);
    cudaGetSymbolAddress((void**)&p_Agl, g_Agl);
    cudaGetSymbolAddress((void**)&p_Bgh, g_Bgh);
    cudaGetSymbolAddress((void**)&p_Bgl, g_Bgl);

    cudaFuncSetAttribute(gemm_mma, cudaFuncAttributeMaxDynamicSharedMemorySize, GEMM_SMEM);

    // ---- init ----
    kfillI<<<ggrid(NN, 256), 256>>>(p_cnt, 0, NN);
    kfill<<<ggrid(BB * 256, 256), 256>>>(p_xc, 0.f, BB * 256);

    // ---- protein precompute ----
    k_P<<<ggrid(VOC * NF * KS, 256), 256>>>(emb, cW);
    k_biasY_init<<<1, 128>>>(fxt_b);
    k_biasY_acc<<<dim3(NF, 8), 128>>>(fxt_W, cb);
    k_R<<<SEQ, 128>>>(fxt_W);

    // ---- bf16 splits ----
    k_split<<<ggrid((long)NN * KPA, 256), 256>>>(x, p_Axh, p_Axl, NN, FF, KPA);
    k_splitT<<<ggrid((long)HID * KPA, 256), 256>>>(gat_W, p_Bah, p_Bal, FF, HID, KPA);
    k_splitT<<<ggrid((long)HID * KPG, 256), 256>>>(gcn_W, p_Bgh, p_Bgl, HID, HID, KPG);

    // ---- GAT GEMM (tensor cores via mma.sync) ----
    gemm_mma<<<dim3(7, 157), 256, GEMM_SMEM>>>(p_Axh, p_Axl, p_Bah, p_Bal,
                                               p_h, NN, HID, KPA, KPA / KC, HID);

    // ---- attention ----
    k_attn_coef<<<ggrid(NN * HH, 256), 256>>>(a_src, a_dst);

    // ---- CSR build ----
    k_count<<<ggrid(ET, 256), 256>>>(edge);
    k_scan<<<1, 256>>>();
    kfillI<<<ggrid(NN, 256), 256>>>(p_cnt, 0, NN);
    k_scatter<<<ggrid(ET, 256), 256>>>(edge);

    // ---- softmax + aggregation ----
    k_soft<<<NN, 128>>>();
    k_gat_agg<<<NN, 256>>>(gat_b);

    // ---- GCN GEMM + aggregation ----
    gemm_mma<<<dim3(7, 157), 256, GEMM_SMEM>>>(p_Agh, p_Agl, p_Bgh, p_Bgl,
                                               p_h2, NN, HID, KPG, KPG / KC, HID);
    k_gcn_agg<<<NN, 256>>>(gcn_b);

    // ---- pool ----
    k_startK<<<ggrid(NN, 256), 256>>>(batch);
    k_pool2<<<BB, HID>>>();

    // ---- graph MLP head ----
    sgemm2<<<dim3(12, 2), 256>>>(p_xg, fcg1_W, p_t1, fcg1_b, BB, 1500, HID, HID, 1500, 1500, 0, 1);
    sgemm2<<<dim3(1, 2), 256>>>(p_t1, fcg2_W, p_xc, fcg2_b, BB, 128, 1500, 1500, 128, 256, 0, 0);

    // ---- protein gather ----
    k_Y<<<dim3(BB, 8), 128>>>(target);

    // ---- fusion MLP ----
    sgemm2<<<dim3(8, 2), 256>>>(p_xc, f1_W, p_t2, f1_b, BB, 1024, 256, 256, 1024, 1024, 0, 1);
    sgemm2<<<dim3(4, 2), 256>>>(p_t2, f2_W, p_t3, f2_b, BB, 512, 1024, 1024, 512, 512, 0, 1);
    sgemm2<<<dim3(2, 2), 256>>>(p_t3, f3_W, p_t4, f3_b, BB, 256, 512, 512, 256, 256, 0, 1);
    sgemm2<<<dim3(1, 2), 256>>>(p_t4, f4_W, p_t5, f4_b, BB, 128, 256, 256, 128, 128, 0, 1);
    k_out<<<BB, 128>>>(o_W, o_b, out);
}

// round 5
// speedup vs baseline: 4.5012x; 1.0811x over previous
#include <cuda_runtime.h>
#include <cuda_fp16.h>
#include <math.h>
#include <stdint.h>

#define NN   20000
#define EE   400000
#define ET   (EE + NN)
#define HH   10
#define FF   78
#define HID  780
#define BB   200
#define SEQ  1000
#define VOC  26
#define EMB  128
#define NF   32
#define KS   8
#define COUT 993
#define KPA  128
#define KPG  832
#define DMAX 256

// ---------------- scratch ----------------
__device__ float g_h  [NN * HID];
__device__ float g_h2 [NN * HID];
__device__ float g_as [NN * HH];
__device__ float g_ad [NN * HH];
__device__ float g_e  [(long)ET * HH];   // big-degree fallback only
__device__ float g_xg [BB * HID];
__device__ float g_t1 [BB * 1500];
__device__ float g_xc [BB * 256];
__device__ float g_t2 [BB * 1024];
__device__ float g_t3 [BB * 512];
__device__ float g_t4 [BB * 256];
__device__ float g_t5 [BB * 128];
__device__ float g_P  [VOC * NF * KS];
__device__ float g_R  [(long)VOC * SEQ * 128];
__device__ float g_biasY[128];
__device__ int   g_cnt[NN];
__device__ int   g_off[NN + 1];
__device__ int   g_srcA[ET];
__device__ float g_dinv[NN];
__device__ __half g_Axh[(long)NN * KPA];
__device__ __half g_Axl[(long)NN * KPA];
__device__ __half g_Bah[(long)HID * KPA];
__device__ __half g_Agh[(long)NN * KPG];
__device__ __half g_Agl[(long)NN * KPG];
__device__ __half g_Bgh[(long)HID * KPG];

// ---------------- helpers ----------------
__device__ __forceinline__ uint32_t smem_u32(const void* p) {
    uint32_t a;
    asm("{ .reg .u64 t; cvta.to.shared.u64 t, %1; cvt.u32.u64 %0, t; }" : "=r"(a) : "l"(p));
    return a;
}
__device__ __forceinline__ void cpasync16(uint32_t dst, const void* src, int nbytes) {
    asm volatile("cp.async.cg.shared.global [%0], [%1], 16, %2;"
                 :: "r"(dst), "l"(__cvta_generic_to_global(src)), "r"(nbytes) : "memory");
}
__device__ __forceinline__ void ldm4(uint32_t* r, uint32_t addr) {
    asm volatile("ldmatrix.sync.aligned.m8n8.x4.shared.b16 {%0,%1,%2,%3}, [%4];"
                 : "=r"(r[0]), "=r"(r[1]), "=r"(r[2]), "=r"(r[3]) : "r"(addr));
}
__device__ __forceinline__ void mma16816h(float* c, const uint32_t* a, uint32_t b0, uint32_t b1) {
    asm volatile("mma.sync.aligned.m16n8k16.row.col.f32.f16.f16.f32 "
                 "{%0,%1,%2,%3}, {%4,%5,%6,%7}, {%8,%9}, {%0,%1,%2,%3};"
                 : "+f"(c[0]), "+f"(c[1]), "+f"(c[2]), "+f"(c[3])
                 : "r"(a[0]), "r"(a[1]), "r"(a[2]), "r"(a[3]), "r"(b0), "r"(b1));
}

#define PK2(d, lo, hi) asm("mov.b64 %0, {%1,%2};" : "=l"(d) : "r"(__float_as_uint(lo)), "r"(__float_as_uint(hi)))
#define FMA2(d, a, b)  asm("fma.rn.f32x2 %0, %1, %2, %3;" : "=l"(d) : "l"(a), "l"(b), "l"(d))
#define UPK2(lo, hi, s) { unsigned int u0_, u1_; asm("mov.b64 {%0,%1}, %2;" : "=r"(u0_), "=r"(u1_) : "l"(s)); lo = __uint_as_float(u0_); hi = __uint_as_float(u1_); }

// ---------------- fused zero-init ----------------
__global__ void k_init0() {
    int i = blockIdx.x * blockDim.x + threadIdx.x;
    if (i < BB * HID) g_xg[i] = 0.f;
    if (i < BB * 256) g_xc[i] = 0.f;
    if (i < 128)      g_biasY[i] = 0.f;
    if (i < NN)       g_cnt[i] = 0;
}

// ============ fp16 2-term tensor-core GEMM: C = (Ah+Al) * Bh^T ============
#define KC 32
#define ASTR 40                       // fp16 units per smem row (32 + 8 pad)
#define HALF_BYTES (128 * ASTR * 2)   // 10240
#define STAGE_BYTES (3 * HALF_BYTES)  // Ah, Al, Bh
#define GEMM_SMEM (2 * STAGE_BYTES)   // 61440

__global__ void __launch_bounds__(256)
gemm_mma(const __half* __restrict__ Ah, const __half* __restrict__ Al,
         const __half* __restrict__ Bh,
         float* __restrict__ C, int M, int N, int Kp, int NC, int ldc) {
    extern __shared__ char smem_raw[];
    uint32_t sb = smem_u32(smem_raw);
    int tid = threadIdx.x, w = tid >> 5, l = tid & 31;
    int m0 = blockIdx.y * 128, n0 = blockIdx.x * 128;
    int wm = w & 3, wn = w >> 2;

    float acc[2][8][4];
#pragma unroll
    for (int i = 0; i < 2; i++)
#pragma unroll
        for (int j = 0; j < 8; j++)
#pragma unroll
            for (int q = 0; q < 4; q++) acc[i][j][q] = 0.f;

    auto issue = [&](int c) {
        int k0 = c * KC;
        uint32_t st = sb + (uint32_t)(c & 1) * STAGE_BYTES;
#pragma unroll
        for (int p = 0; p < 2; p++) {
            int f = tid + p * 256;
            int row = f >> 2, c16 = f & 3;
            uint32_t doff = (uint32_t)(row * (ASTR * 2) + c16 * 16);
            int am = m0 + row;
            int amc = am < M ? am : M - 1;
            int av = am < M ? 16 : 0;
            long aoff = (long)amc * Kp + k0 + c16 * 8;
            cpasync16(st + doff, Ah + aoff, av);
            cpasync16(st + HALF_BYTES + doff, Al + aoff, av);
            int bn = n0 + row;
            int bnc = bn < N ? bn : N - 1;
            int bv = bn < N ? 16 : 0;
            cpasync16(st + 2 * HALF_BYTES + doff, Bh + (long)bnc * Kp + k0 + c16 * 8, bv);
        }
        asm volatile("cp.async.commit_group;" ::: "memory");
    };

    issue(0);
    for (int c = 0; c < NC; c++) {
        if (c + 1 < NC) {
            issue(c + 1);
            asm volatile("cp.async.wait_group 1;" ::: "memory");
        } else {
            asm volatile("cp.async.wait_group 0;" ::: "memory");
        }
        __syncthreads();
        uint32_t st = sb + (uint32_t)(c & 1) * STAGE_BYTES;
        int lrow = l & 15, lcb = l >> 4;
#pragma unroll
        for (int k16 = 0; k16 < 2; k16++) {
            uint32_t coff = (uint32_t)((k16 * 16 + lcb * 8) * 2);
            uint32_t bh[4][4];
#pragma unroll
            for (int nt2 = 0; nt2 < 4; nt2++) {
                uint32_t roff = (uint32_t)((wn * 64 + nt2 * 16 + lrow) * (ASTR * 2));
                ldm4(bh[nt2], st + 2 * HALF_BYTES + roff + coff);
            }
#pragma unroll
            for (int mt = 0; mt < 2; mt++) {
                uint32_t roff = (uint32_t)((wm * 32 + mt * 16 + lrow) * (ASTR * 2));
                uint32_t ah[4], al[4];
                ldm4(ah, st + roff + coff);
                ldm4(al, st + HALF_BYTES + roff + coff);
#pragma unroll
                for (int nt = 0; nt < 8; nt++) {
                    int nt2 = nt >> 1, sel = nt & 1;
                    uint32_t b0 = bh[nt2][sel], b1 = bh[nt2][sel + 2];
                    mma16816h(acc[mt][nt], ah, b0, b1);
                    mma16816h(acc[mt][nt], al, b0, b1);
                }
            }
        }
        __syncthreads();
    }

#pragma unroll
    for (int mt = 0; mt < 2; mt++) {
#pragma unroll
        for (int nt = 0; nt < 8; nt++) {
            int row = m0 + wm * 32 + mt * 16 + (l >> 2);
            int col = n0 + wn * 64 + nt * 8 + 2 * (l & 3);
            float* cp0 = C + (long)row * ldc + col;
            if (row < M) {
                if (col + 1 < N) { cp0[0] = acc[mt][nt][0]; cp0[1] = acc[mt][nt][1]; }
                else if (col < N) cp0[0] = acc[mt][nt][0];
            }
            int row2 = row + 8;
            float* cp1 = C + (long)row2 * ldc + col;
            if (row2 < M) {
                if (col + 1 < N) { cp1[0] = acc[mt][nt][2]; cp1[1] = acc[mt][nt][3]; }
                else if (col < N) cp1[0] = acc[mt][nt][2];
            }
        }
    }
}

// ---------------- fp16 splits ----------------
__global__ void k_split(const float* __restrict__ src, __half* __restrict__ dh,
                        __half* __restrict__ dl, int M, int Ksrc, int Kp) {
    long i = (long)blockIdx.x * blockDim.x + threadIdx.x;
    if (i >= (long)M * Kp) return;
    int m = (int)(i / Kp), k = (int)(i % Kp);
    float v = (k < Ksrc) ? src[(long)m * Ksrc + k] : 0.f;
    __half h = __float2half_rn(v);
    dh[i] = h;
    dl[i] = __float2half_rn(v - __half2float(h));
}
__global__ void k_splitT(const float* __restrict__ W, __half* __restrict__ dh,
                         int K, int N, int Kp) {
    long i = (long)blockIdx.x * blockDim.x + threadIdx.x;
    if (i >= (long)N * Kp) return;
    int n = (int)(i / Kp), k = (int)(i % Kp);
    float v = (k < K) ? W[(long)k * N + n] : 0.f;
    dh[i] = __float2half_rn(v);
}

// ---------------- SGEMM (FFMA2) for small MLP layers ----------------
#define BKg 16
__global__ void __launch_bounds__(256)
sgemm2(const float* __restrict__ A, const float* __restrict__ B,
       float* __restrict__ C, const float* __restrict__ bias,
       int M, int N, int K, int lda, int ldb, int ldc, int coff, int relu) {
    __shared__ float As[2][BKg][132];
    __shared__ float Bs[2][BKg][128];
    int tid = threadIdx.x;
    int m0 = blockIdx.y * 128, n0 = blockIdx.x * 128;
    int ty = tid >> 4, tx = tid & 15;

    unsigned long long acc2[8][4];
#pragma unroll
    for (int i = 0; i < 8; i++)
#pragma unroll
        for (int j = 0; j < 4; j++) acc2[i][j] = 0ull;

    float4 ra[2], rb[2];
    auto loadStage = [&](int kT) {
#pragma unroll
        for (int p = 0; p < 2; p++) {
            int f = tid + p * 256;
            int m = f >> 2, kq = f & 3;
            int gm = m0 + m, gk = kT + kq * 4;
            const float* ap = A + (long)gm * lda + gk;
            if (gm < M && gk + 3 < K) ra[p] = *(const float4*)ap;
            else {
                ra[p].x = (gm < M && gk     < K) ? ap[0] : 0.f;
                ra[p].y = (gm < M && gk + 1 < K) ? ap[1] : 0.f;
                ra[p].z = (gm < M && gk + 2 < K) ? ap[2] : 0.f;
                ra[p].w = (gm < M && gk + 3 < K) ? ap[3] : 0.f;
            }
        }
#pragma unroll
        for (int p = 0; p < 2; p++) {
            int f = tid + p * 256;
            int kr = f >> 5, nq = f & 31;
            int gk = kT + kr, gn = n0 + nq * 4;
            const float* bp = B + (long)gk * ldb + gn;
            if (gk < K && gn + 3 < N) rb[p] = *(const float4*)bp;
            else {
                rb[p].x = (gk < K && gn     < N) ? bp[0] : 0.f;
                rb[p].y = (gk < K && gn + 1 < N) ? bp[1] : 0.f;
                rb[p].z = (gk < K && gn + 2 < N) ? bp[2] : 0.f;
                rb[p].w = (gk < K && gn + 3 < N) ? bp[3] : 0.f;
            }
        }
    };
    auto storeStage = [&](int buf) {
#pragma unroll
        for (int p = 0; p < 2; p++) {
            int f = tid + p * 256;
            int m = f >> 2, kq = f & 3;
            As[buf][kq * 4 + 0][m] = ra[p].x;
            As[buf][kq * 4 + 1][m] = ra[p].y;
            As[buf][kq * 4 + 2][m] = ra[p].z;
            As[buf][kq * 4 + 3][m] = ra[p].w;
        }
#pragma unroll
        for (int p = 0; p < 2; p++) {
            int f = tid + p * 256;
            int kr = f >> 5, nq = f & 31;
            *(float4*)&Bs[buf][kr][nq * 4] = rb[p];
        }
    };

    int buf = 0;
    loadStage(0);
    storeStage(0);
    __syncthreads();

    for (int kT = 0;;) {
        int kN = kT + BKg;
        bool more = kN < K;
        if (more) loadStage(kN);
#pragma unroll
        for (int kk = 0; kk < BKg; kk++) {
            float4 a0 = *(const float4*)&As[buf][kk][ty * 8];
            float4 a1 = *(const float4*)&As[buf][kk][ty * 8 + 4];
            float4 b0 = *(const float4*)&Bs[buf][kk][tx * 8];
            float4 b1 = *(const float4*)&Bs[buf][kk][tx * 8 + 4];
            unsigned long long bp0, bp1, bp2, bp3;
            PK2(bp0, b0.x, b0.y); PK2(bp1, b0.z, b0.w);
            PK2(bp2, b1.x, b1.y); PK2(bp3, b1.z, b1.w);
            float av[8] = {a0.x, a0.y, a0.z, a0.w, a1.x, a1.y, a1.z, a1.w};
#pragma unroll
            for (int i = 0; i < 8; i++) {
                unsigned long long aa;
                PK2(aa, av[i], av[i]);
                FMA2(acc2[i][0], aa, bp0);
                FMA2(acc2[i][1], aa, bp1);
                FMA2(acc2[i][2], aa, bp2);
                FMA2(acc2[i][3], aa, bp3);
            }
        }
        if (!more) break;
        storeStage(buf ^ 1);
        buf ^= 1; kT = kN;
        __syncthreads();
    }

#pragma unroll
    for (int i = 0; i < 8; i++) {
        int row = m0 + ty * 8 + i;
        if (row >= M) continue;
        float cv[8];
        UPK2(cv[0], cv[1], acc2[i][0]);
        UPK2(cv[2], cv[3], acc2[i][1]);
        UPK2(cv[4], cv[5], acc2[i][2]);
        UPK2(cv[6], cv[7], acc2[i][3]);
#pragma unroll
        for (int j = 0; j < 8; j++) {
            int col = n0 + tx * 8 + j;
            if (col >= N) continue;
            float v = cv[j] + (bias ? bias[col] : 0.f);
            if (relu) v = fmaxf(v, 0.f);
            C[(long)row * ldc + coff + col] = v;
        }
    }
}

// ---------------- GAT attention coefficients ----------------
__global__ void k_attn_coef(const float* __restrict__ aS, const float* __restrict__ aD) {
    int g = blockIdx.x * blockDim.x + threadIdx.x;
    if (g >= NN * HH) return;
    int n = g / HH, h = g % HH;
    const float* hp = g_h + (long)n * HID + h * FF;
    float s = 0.f, d = 0.f;
#pragma unroll 13
    for (int f = 0; f < FF; f++) {
        float hv = hp[f];
        s += hv * aS[h * FF + f];
        d += hv * aD[h * FF + f];
    }
    g_as[g] = s;
    g_ad[g] = d;
}

// ---------------- CSR build ----------------
__global__ void k_count(const int* __restrict__ edge) {
    int i = blockIdx.x * blockDim.x + threadIdx.x;
    if (i >= ET) return;
    int dst = (i < EE) ? edge[EE + i] : i - EE;
    atomicAdd(&g_cnt[dst], 1);
}
__global__ void k_scan() {
    __shared__ int part[256];
    int tid = threadIdx.x;
    const int chunk = (NN + 255) / 256;
    int lo = tid * chunk, hi = min(lo + chunk, NN);
    int s = 0;
    for (int n = lo; n < hi; n++) s += g_cnt[n];
    part[tid] = s;
    __syncthreads();
    if (tid == 0) {
        int r = 0;
        for (int i = 0; i < 256; i++) { int t = part[i]; part[i] = r; r += t; }
        g_off[NN] = r;
    }
    __syncthreads();
    int r = part[tid];
    for (int n = lo; n < hi; n++) {
        g_off[n] = r;
        int c = g_cnt[n];
        g_cnt[n] = 0;                 // self-zero for scatter pass
        r += c;
        g_dinv[n] = rsqrtf((float)(c > 0 ? c : 1));
    }
}
__global__ void k_scatter(const int* __restrict__ edge) {
    int i = blockIdx.x * blockDim.x + threadIdx.x;
    if (i >= ET) return;
    int src = (i < EE) ? edge[i]      : i - EE;
    int dst = (i < EE) ? edge[EE + i] : i - EE;
    int pos = g_off[dst] + atomicAdd(&g_cnt[dst], 1);
    g_srcA[pos] = src;
}

// ---------------- fused softmax + GAT aggregation (+bias,relu,fp16 split) ----------------
__device__ __forceinline__ uint32_t fmapU(float f) {
    uint32_t u = __float_as_uint(f);
    return u ^ (uint32_t)(((int)u >> 31) | 0x80000000);
}
__device__ __forceinline__ float finvU(uint32_t u) {
    return (u & 0x80000000u) ? __uint_as_float(u ^ 0x80000000u) : __uint_as_float(~u);
}
__global__ void __launch_bounds__(256) k_gat_soft_agg(const float* __restrict__ gat_b) {
    __shared__ float sal[DMAX * HH];
    __shared__ uint32_t sm[HH];
    __shared__ float sden[HH], sad[HH];
    int n = blockIdx.x, t = threadIdx.x;
    int lo = g_off[n], d = g_off[n + 1] - lo;
    float* ebuf = (d <= DMAX) ? sal : &g_e[(long)lo * HH];
    if (t < HH) { sm[t] = fmapU(-INFINITY); sden[t] = 0.f; sad[t] = g_ad[n * HH + t]; }
    __syncthreads();
    int tot = d * HH;
    for (int p = t; p < tot; p += 256) {
        int i = p / HH, h = p - i * HH;
        int src = g_srcA[lo + i];
        float e = g_as[src * HH + h] + sad[h];
        e = (e > 0.f) ? e : 0.2f * e;
        ebuf[p] = e;
        atomicMax(&sm[h], fmapU(e));
    }
    __syncthreads();
    for (int p = t; p < tot; p += 256) {
        int h = p % HH;
        float ex = expf(ebuf[p] - finvU(sm[h]));
        ebuf[p] = ex;
        atomicAdd(&sden[h], ex);
    }
    __syncthreads();
    if (t < HH) sden[t] = 1.f / sden[t];
    __syncthreads();
    for (int p = t; p < tot; p += 256) ebuf[p] *= sden[p % HH];
    __syncthreads();

    if (t >= 208) return;
    if (t >= 195) {  // pad cols 780..831 of fp16 split
        __half z = __float2half_rn(0.f);
        long base = (long)n * KPG + t * 4;
#pragma unroll
        for (int c = 0; c < 4; c++) { g_Agh[base + c] = z; g_Agl[base + c] = z; }
        return;
    }
    int q = t * 4;
    int h0 = q / FF, h1 = (q + 1) / FF, h2 = (q + 2) / FF, h3 = (q + 3) / FF;
    float ax = 0.f, ay = 0.f, az = 0.f, aw = 0.f;
    for (int idx = 0; idx < d; idx++) {
        int s = g_srcA[lo + idx];
        float4 hv = *(const float4*)(g_h + (long)s * HID + q);
        const float* al = &ebuf[idx * HH];
        ax += hv.x * al[h0];
        ay += hv.y * al[h1];
        az += hv.z * al[h2];
        aw += hv.w * al[h3];
    }
    float v[4];
    v[0] = fmaxf(ax + gat_b[q + 0], 0.f);
    v[1] = fmaxf(ay + gat_b[q + 1], 0.f);
    v[2] = fmaxf(az + gat_b[q + 2], 0.f);
    v[3] = fmaxf(aw + gat_b[q + 3], 0.f);
    long base = (long)n * KPG + q;
#pragma unroll
    for (int c = 0; c < 4; c++) {
        __half hb = __float2half_rn(v[c]);
        g_Agh[base + c] = hb;
        g_Agl[base + c] = __float2half_rn(v[c] - __half2float(hb));
    }
}

// ---------------- fused GCN aggregation + bias/relu + global-add-pool ----------------
__global__ void __launch_bounds__(256) k_gcn_agg_pool(const float* __restrict__ gcn_b,
                                                      const int* __restrict__ batch) {
    int n = blockIdx.x, t = threadIdx.x;
    if (t >= 195) return;
    int b = batch[n];
    int q = t * 4;
    float dn = g_dinv[n];
    float ax = 0.f, ay = 0.f, az = 0.f, aw = 0.f;
    int lo = g_off[n], hi = g_off[n + 1];
    for (int idx = lo; idx < hi; idx++) {
        int s = g_srcA[idx];
        float norm = dn * g_dinv[s];
        float4 hv = *(const float4*)(g_h2 + (long)s * HID + q);
        ax += hv.x * norm;
        ay += hv.y * norm;
        az += hv.z * norm;
        aw += hv.w * norm;
    }
    float* o = g_xg + (long)b * HID + q;
    atomicAdd(o + 0, fmaxf(ax + gcn_b[q + 0], 0.f));
    atomicAdd(o + 1, fmaxf(ay + gcn_b[q + 1], 0.f));
    atomicAdd(o + 2, fmaxf(az + gcn_b[q + 2], 0.f));
    atomicAdd(o + 3, fmaxf(aw + gcn_b[q + 3], 0.f));
}

// ---------------- protein branch ----------------
// blocks [0,256): biasY partial sums; blocks [256, 308): P
__global__ void k_Pbias(const float* __restrict__ emb, const float* __restrict__ cW,
                        const float* __restrict__ fxtW, const float* __restrict__ cb) {
    int bi = blockIdx.x, j = threadIdx.x;
    if (bi < 256) {
        int o = bi >> 3, c = bi & 7;
        int t0 = c * 125, t1 = min(t0 + 125, COUT);
        float p = 0.f;
        for (int t = t0; t < t1; t++)
            p += fxtW[((long)(o * COUT + t)) * 128 + j];
        atomicAdd(&g_biasY[j], cb[o] * p);
    } else {
        int g = (bi - 256) * 128 + j;
        if (g >= VOC * NF * KS) return;
        int v = g / (NF * KS), r = g % (NF * KS);
        int o = r / KS, k = r % KS;
        float s = 0.f;
#pragma unroll 16
        for (int e = 0; e < EMB; e++)
            s += emb[v * EMB + e] * cW[o * EMB * KS + e * KS + k];
        g_P[g] = s;
    }
}
__global__ void k_R(const float* __restrict__ fxtW) {
    __shared__ float Ps[VOC * NF * KS];
    int s = blockIdx.x, j = threadIdx.x;
    for (int idx = j; idx < VOC * NF * KS; idx += 128) Ps[idx] = g_P[idx];
    __syncthreads();
    float acc[VOC];
#pragma unroll
    for (int v = 0; v < VOC; v++) acc[v] = 0.f;
    int kmin = (s > COUT - 1) ? (s - (COUT - 1)) : 0;
    int kmax = (s < KS - 1) ? s : (KS - 1);
    for (int o = 0; o < NF; o++) {
        for (int k = kmin; k <= kmax; k++) {
            float w = fxtW[((long)(o * COUT + s - k)) * 128 + j];
#pragma unroll
            for (int v = 0; v < VOC; v++)
                acc[v] += Ps[v * (NF * KS) + o * KS + k] * w;
        }
    }
#pragma unroll
    for (int v = 0; v < VOC; v++)
        g_R[((long)v * SEQ + s) * 128 + j] = acc[v];
}
__global__ void k_Y(const int* __restrict__ target, const float* __restrict__ fxt_b) {
    int b = blockIdx.x, ch = blockIdx.y, j = threadIdx.x;
    int s0 = ch * 125, s1 = s0 + 125;
    float acc = (ch == 0) ? (g_biasY[j] + fxt_b[j]) : 0.f;
#pragma unroll 5
    for (int s = s0; s < s1; s++) {
        int v = target[b * SEQ + s];
        acc += g_R[((long)v * SEQ + s) * 128 + j];
    }
    atomicAdd(&g_xc[b * 256 + 128 + j], acc);
}

// ---------------- output ----------------
__global__ void k_out(const float* __restrict__ oW, const float* __restrict__ ob,
                      float* __restrict__ out) {
    __shared__ float red[4];
    int b = blockIdx.x, j = threadIdx.x;
    float v = g_t5[b * 128 + j] * oW[j];
#pragma unroll
    for (int off = 16; off; off >>= 1) v += __shfl_down_sync(0xffffffffu, v, off);
    if ((j & 31) == 0) red[j >> 5] = v;
    __syncthreads();
    if (j == 0) out[b] = red[0] + red[1] + red[2] + red[3] + ob[0];
}

// ---------------- host ----------------
static inline dim3 ggrid(long n, int t) { return dim3((unsigned)((n + t - 1) / t)); }

extern "C" void kernel_launch(void* const* d_in, const int* in_sizes, int n_in,
                              void* d_out, int out_size) {
    const float* x      = (const float*)d_in[0];
    const int*   edge   = (const int*)  d_in[1];
    const int*   batch  = (const int*)  d_in[2];
    const int*   target = (const int*)  d_in[3];
    const float* gat_W  = (const float*)d_in[4];
    const float* a_src  = (const float*)d_in[5];
    const float* a_dst  = (const float*)d_in[6];
    const float* gat_b  = (const float*)d_in[7];
    const float* gcn_W  = (const float*)d_in[8];
    const float* gcn_b  = (const float*)d_in[9];
    const float* fcg1_W = (const float*)d_in[10];
    const float* fcg1_b = (const float*)d_in[11];
    const float* fcg2_W = (const float*)d_in[12];
    const float* fcg2_b = (const float*)d_in[13];
    const float* emb    = (const float*)d_in[14];
    const float* cW     = (const float*)d_in[15];
    const float* cb     = (const float*)d_in[16];
    const float* fxt_W  = (const float*)d_in[17];
    const float* fxt_b  = (const float*)d_in[18];
    const float* f1_W   = (const float*)d_in[19];
    const float* f1_b   = (const float*)d_in[20];
    const float* f2_W   = (const float*)d_in[21];
    const float* f2_b   = (const float*)d_in[22];
    const float* f3_W   = (const float*)d_in[23];
    const float* f3_b   = (const float*)d_in[24];
    const float* f4_W   = (const float*)d_in[25];
    const float* f4_b   = (const float*)d_in[26];
    const float* o_W    = (const float*)d_in[27];
    const float* o_b    = (const float*)d_in[28];
    float* out = (float*)d_out;

    float *p_h, *p_h2, *p_xg, *p_t1, *p_xc, *p_t2, *p_t3, *p_t4, *p_t5;
    __half *p_Axh, *p_Axl, *p_Bah, *p_Agh, *p_Agl, *p_Bgh;
    cudaGetSymbolAddress((void**)&p_h,   g_h);
    cudaGetSymbolAddress((void**)&p_h2,  g_h2);
    cudaGetSymbolAddress((void**)&p_xg,  g_xg);
    cudaGetSymbolAddress((void**)&p_t1,  g_t1);
    cudaGetSymbolAddress((void**)&p_xc,  g_xc);
    cudaGetSymbolAddress((void**)&p_t2,  g_t2);
    cudaGetSymbolAddress((void**)&p_t3,  g_t3);
    cudaGetSymbolAddress((void**)&p_t4,  g_t4);
    cudaGetSymbolAddress((void**)&p_t5,  g_t5);
    cudaGetSymbolAddress((void**)&p_Axh, g_Axh);
    cudaGetSymbolAddress((void**)&p_Axl, g_Axl);
    cudaGetSymbolAddress((void**)&p_Bah, g_Bah);
    cudaGetSymbolAddress((void**)&p_Agh, g_Agh);
    cudaGetSymbolAddress((void**)&p_Agl, g_Agl);
    cudaGetSymbolAddress((void**)&p_Bgh, g_Bgh);

    cudaFuncSetAttribute(gemm_mma, cudaFuncAttributeMaxDynamicSharedMemorySize, GEMM_SMEM);

    // 1: zero init
    k_init0<<<ggrid(BB * HID, 256), 256>>>();
    // 2: protein P + biasY partials
    k_Pbias<<<308, 128>>>(emb, cW, fxt_W, cb);
    // 3-5: fp16 splits
    k_split<<<ggrid((long)NN * KPA, 256), 256>>>(x, p_Axh, p_Axl, NN, FF, KPA);
    k_splitT<<<ggrid((long)HID * KPA, 256), 256>>>(gat_W, p_Bah, FF, HID, KPA);
    k_splitT<<<ggrid((long)HID * KPG, 256), 256>>>(gcn_W, p_Bgh, HID, HID, KPG);
    // 6: GAT GEMM (position 6 for ncu -s 5 -c 1)
    gemm_mma<<<dim3(7, 157), 256, GEMM_SMEM>>>(p_Axh, p_Axl, p_Bah,
                                               p_h, NN, HID, KPA, KPA / KC, HID);
    // 7: protein R table
    k_R<<<SEQ, 128>>>(fxt_W);
    // 8: attention coefficients
    k_attn_coef<<<ggrid(NN * HH, 256), 256>>>(a_src, a_dst);
    // 9-11: CSR build
    k_count<<<ggrid(ET, 256), 256>>>(edge);
    k_scan<<<1, 256>>>();
    k_scatter<<<ggrid(ET, 256), 256>>>(edge);
    // 12: fused softmax + GAT aggregation
    k_gat_soft_agg<<<NN, 256>>>(gat_b);
    // 13: GCN GEMM
    gemm_mma<<<dim3(7, 157), 256, GEMM_SMEM>>>(p_Agh, p_Agl, p_Bgh,
                                               p_h2, NN, HID, KPG, KPG / KC, HID);
    // 14: fused GCN aggregation + pool
    k_gcn_agg_pool<<<NN, 256>>>(gcn_b, batch);
    // 15-16: graph MLP head
    sgemm2<<<dim3(12, 2), 256>>>(p_xg, fcg1_W, p_t1, fcg1_b, BB, 1500, HID, HID, 1500, 1500, 0, 1);
    sgemm2<<<dim3(1, 2), 256>>>(p_t1, fcg2_W, p_xc, fcg2_b, BB, 128, 1500, 1500, 128, 256, 0, 0);
    // 17: protein gather
    k_Y<<<dim3(BB, 8), 128>>>(target, fxt_b);
    // 18-21: fusion MLP
    sgemm2<<<dim3(8, 2), 256>>>(p_xc, f1_W, p_t2, f1_b, BB, 1024, 256, 256, 1024, 1024, 0, 1);
    sgemm2<<<dim3(4, 2), 256>>>(p_t2, f2_W, p_t3, f2_b, BB, 512, 1024, 1024, 512, 512, 0, 1);
    sgemm2<<<dim3(2, 2), 256>>>(p_t3, f3_W, p_t4, f3_b, BB, 256, 512, 512, 256, 256, 0, 1);
    sgemm2<<<dim3(1, 2), 256>>>(p_t4, f4_W, p_t5, f4_b, BB, 128, 256, 256, 128, 128, 0, 1);
    // 22: output
    k_out<<<BB, 128>>>(o_W, o_b, out);
}

// round 6
// speedup vs baseline: 5.6611x; 1.2577x over previous
#include <cuda_runtime.h>
#include <cuda_fp16.h>
#include <math.h>
#include <stdint.h>

#define NN   20000
#define EE   400000
#define ET   (EE + NN)
#define HH   10
#define FF   78
#define HID  780
#define BB   200
#define SEQ  1000
#define VOC  26
#define EMB  128
#define NF   32
#define KS   8
#define COUT 993
#define KPA  128
#define KPG  832
#define DMAX 256

// ---------------- scratch ----------------
__device__ __half g_hH [(long)NN * HID];      // GAT gemm out (fp16)
__device__ __half g_h2H[(long)NN * HID];      // GCN gemm out (fp16)
__device__ float g_as [NN * HH];
__device__ float g_ad [NN * HH];
__device__ float g_e  [(long)ET * HH];        // big-degree fallback only
__device__ float g_xg [BB * HID];
__device__ float g_t1 [BB * 1500];
__device__ float g_xc [BB * 256];
__device__ float g_t2 [BB * 1024];
__device__ float g_t3 [BB * 512];
__device__ float g_t4 [BB * 256];
__device__ float g_t5 [BB * 128];
__device__ float g_P  [VOC * NF * KS];
__device__ float g_R  [(long)VOC * SEQ * 128];
__device__ float g_biasY[128];
__device__ int   g_cnt[NN];
__device__ int   g_off[NN + 1];
__device__ int   g_srcA[ET];
__device__ float g_dinv[NN];
__device__ __half g_Axh[(long)NN * KPA];
__device__ __half g_Bah[(long)HID * KPA];
__device__ __half g_Ag [(long)NN * KPG];
__device__ __half g_Bgh[(long)HID * KPG];

// ---------------- helpers ----------------
__device__ __forceinline__ uint32_t smem_u32(const void* p) {
    uint32_t a;
    asm("{ .reg .u64 t; cvta.to.shared.u64 t, %1; cvt.u32.u64 %0, t; }" : "=r"(a) : "l"(p));
    return a;
}
__device__ __forceinline__ void cpasync16(uint32_t dst, const void* src, int nbytes) {
    asm volatile("cp.async.cg.shared.global [%0], [%1], 16, %2;"
                 :: "r"(dst), "l"(__cvta_generic_to_global(src)), "r"(nbytes) : "memory");
}
__device__ __forceinline__ void ldm4(uint32_t* r, uint32_t addr) {
    asm volatile("ldmatrix.sync.aligned.m8n8.x4.shared.b16 {%0,%1,%2,%3}, [%4];"
                 : "=r"(r[0]), "=r"(r[1]), "=r"(r[2]), "=r"(r[3]) : "r"(addr));
}
__device__ __forceinline__ void mma16816h(float* c, const uint32_t* a, uint32_t b0, uint32_t b1) {
    asm volatile("mma.sync.aligned.m16n8k16.row.col.f32.f16.f16.f32 "
                 "{%0,%1,%2,%3}, {%4,%5,%6,%7}, {%8,%9}, {%0,%1,%2,%3};"
                 : "+f"(c[0]), "+f"(c[1]), "+f"(c[2]), "+f"(c[3])
                 : "r"(a[0]), "r"(a[1]), "r"(a[2]), "r"(a[3]), "r"(b0), "r"(b1));
}

#define PK2(d, lo, hi) asm("mov.b64 %0, {%1,%2};" : "=l"(d) : "r"(__float_as_uint(lo)), "r"(__float_as_uint(hi)))
#define FMA2(d, a, b)  asm("fma.rn.f32x2 %0, %1, %2, %3;" : "=l"(d) : "l"(a), "l"(b), "l"(d))
#define UPK2(lo, hi, s) { unsigned int u0_, u1_; asm("mov.b64 {%0,%1}, %2;" : "=r"(u0_), "=r"(u1_) : "l"(s)); lo = __uint_as_float(u0_); hi = __uint_as_float(u1_); }

// ---------------- fused zero-init ----------------
__global__ void k_init0() {
    int i = blockIdx.x * blockDim.x + threadIdx.x;
    if (i < BB * HID) g_xg[i] = 0.f;
    if (i < BB * 256) g_xc[i] = 0.f;
    if (i < 128)      g_biasY[i] = 0.f;
    if (i < NN)       g_cnt[i] = 0;
}

// ============ pure fp16 tensor-core GEMM: C(half) = A * B^T ============
#define KC 32
#define ASTR 40                       // fp16 units per smem row (32 + 8 pad)
#define HALF_BYTES (128 * ASTR * 2)   // 10240
#define STAGE_BYTES (2 * HALF_BYTES)  // A, B
#define GEMM_SMEM (2 * STAGE_BYTES)   // 40960

__global__ void __launch_bounds__(256)
gemm_mma(const __half* __restrict__ Ah, const __half* __restrict__ Bh,
         __half* __restrict__ C, int M, int N, int Kp, int NC, int ldc) {
    extern __shared__ char smem_raw[];
    uint32_t sb = smem_u32(smem_raw);
    int tid = threadIdx.x, w = tid >> 5, l = tid & 31;
    int m0 = blockIdx.y * 128, n0 = blockIdx.x * 128;
    int wm = w & 3, wn = w >> 2;

    float acc[2][8][4];
#pragma unroll
    for (int i = 0; i < 2; i++)
#pragma unroll
        for (int j = 0; j < 8; j++)
#pragma unroll
            for (int q = 0; q < 4; q++) acc[i][j][q] = 0.f;

    auto issue = [&](int c) {
        int k0 = c * KC;
        uint32_t st = sb + (uint32_t)(c & 1) * STAGE_BYTES;
#pragma unroll
        for (int p = 0; p < 2; p++) {
            int f = tid + p * 256;
            int row = f >> 2, c16 = f & 3;
            uint32_t doff = (uint32_t)(row * (ASTR * 2) + c16 * 16);
            int am = m0 + row;
            int amc = am < M ? am : M - 1;
            int av = am < M ? 16 : 0;
            cpasync16(st + doff, Ah + (long)amc * Kp + k0 + c16 * 8, av);
            int bn = n0 + row;
            int bnc = bn < N ? bn : N - 1;
            int bv = bn < N ? 16 : 0;
            cpasync16(st + HALF_BYTES + doff, Bh + (long)bnc * Kp + k0 + c16 * 8, bv);
        }
        asm volatile("cp.async.commit_group;" ::: "memory");
    };

    issue(0);
    for (int c = 0; c < NC; c++) {
        if (c + 1 < NC) {
            issue(c + 1);
            asm volatile("cp.async.wait_group 1;" ::: "memory");
        } else {
            asm volatile("cp.async.wait_group 0;" ::: "memory");
        }
        __syncthreads();
        uint32_t st = sb + (uint32_t)(c & 1) * STAGE_BYTES;
        int lrow = l & 15, lcb = l >> 4;
#pragma unroll
        for (int k16 = 0; k16 < 2; k16++) {
            uint32_t coff = (uint32_t)((k16 * 16 + lcb * 8) * 2);
            uint32_t bh[4][4];
#pragma unroll
            for (int nt2 = 0; nt2 < 4; nt2++) {
                uint32_t roff = (uint32_t)((wn * 64 + nt2 * 16 + lrow) * (ASTR * 2));
                ldm4(bh[nt2], st + HALF_BYTES + roff + coff);
            }
#pragma unroll
            for (int mt = 0; mt < 2; mt++) {
                uint32_t roff = (uint32_t)((wm * 32 + mt * 16 + lrow) * (ASTR * 2));
                uint32_t ah[4];
                ldm4(ah, st + roff + coff);
#pragma unroll
                for (int nt = 0; nt < 8; nt++) {
                    int nt2 = nt >> 1, sel = nt & 1;
                    mma16816h(acc[mt][nt], ah, bh[nt2][sel], bh[nt2][sel + 2]);
                }
            }
        }
        __syncthreads();
    }

    // epilogue: fp16 half2 stores (N even, col always even)
#pragma unroll
    for (int mt = 0; mt < 2; mt++) {
#pragma unroll
        for (int nt = 0; nt < 8; nt++) {
            int row = m0 + wm * 32 + mt * 16 + (l >> 2);
            int col = n0 + wn * 64 + nt * 8 + 2 * (l & 3);
            if (col < N) {
                if (row < M)
                    *(__half2*)(C + (long)row * ldc + col) =
                        __floats2half2_rn(acc[mt][nt][0], acc[mt][nt][1]);
                int row2 = row + 8;
                if (row2 < M)
                    *(__half2*)(C + (long)row2 * ldc + col) =
                        __floats2half2_rn(acc[mt][nt][2], acc[mt][nt][3]);
            }
        }
    }
}

// ---------------- fp16 conversions ----------------
__global__ void k_half(const float* __restrict__ src, __half* __restrict__ dh,
                       int M, int Ksrc, int Kp) {
    long i = (long)blockIdx.x * blockDim.x + threadIdx.x;
    if (i >= (long)M * Kp) return;
    int m = (int)(i / Kp), k = (int)(i % Kp);
    dh[i] = __float2half_rn((k < Ksrc) ? src[(long)m * Ksrc + k] : 0.f);
}
__global__ void k_halfT(const float* __restrict__ W, __half* __restrict__ dh,
                        int K, int N, int Kp) {
    long i = (long)blockIdx.x * blockDim.x + threadIdx.x;
    if (i >= (long)N * Kp) return;
    int n = (int)(i / Kp), k = (int)(i % Kp);
    dh[i] = __float2half_rn((k < K) ? W[(long)k * N + n] : 0.f);
}

// ---------------- SGEMM (FFMA2) for small MLP layers ----------------
#define BKg 16
__global__ void __launch_bounds__(256)
sgemm2(const float* __restrict__ A, const float* __restrict__ B,
       float* __restrict__ C, const float* __restrict__ bias,
       int M, int N, int K, int lda, int ldb, int ldc, int coff, int relu) {
    __shared__ float As[2][BKg][132];
    __shared__ float Bs[2][BKg][128];
    int tid = threadIdx.x;
    int m0 = blockIdx.y * 128, n0 = blockIdx.x * 128;
    int ty = tid >> 4, tx = tid & 15;

    unsigned long long acc2[8][4];
#pragma unroll
    for (int i = 0; i < 8; i++)
#pragma unroll
        for (int j = 0; j < 4; j++) acc2[i][j] = 0ull;

    float4 ra[2], rb[2];
    auto loadStage = [&](int kT) {
#pragma unroll
        for (int p = 0; p < 2; p++) {
            int f = tid + p * 256;
            int m = f >> 2, kq = f & 3;
            int gm = m0 + m, gk = kT + kq * 4;
            const float* ap = A + (long)gm * lda + gk;
            if (gm < M && gk + 3 < K) ra[p] = *(const float4*)ap;
            else {
                ra[p].x = (gm < M && gk     < K) ? ap[0] : 0.f;
                ra[p].y = (gm < M && gk + 1 < K) ? ap[1] : 0.f;
                ra[p].z = (gm < M && gk + 2 < K) ? ap[2] : 0.f;
                ra[p].w = (gm < M && gk + 3 < K) ? ap[3] : 0.f;
            }
        }
#pragma unroll
        for (int p = 0; p < 2; p++) {
            int f = tid + p * 256;
            int kr = f >> 5, nq = f & 31;
            int gk = kT + kr, gn = n0 + nq * 4;
            const float* bp = B + (long)gk * ldb + gn;
            if (gk < K && gn + 3 < N) rb[p] = *(const float4*)bp;
            else {
                rb[p].x = (gk < K && gn     < N) ? bp[0] : 0.f;
                rb[p].y = (gk < K && gn + 1 < N) ? bp[1] : 0.f;
                rb[p].z = (gk < K && gn + 2 < N) ? bp[2] : 0.f;
                rb[p].w = (gk < K && gn + 3 < N) ? bp[3] : 0.f;
            }
        }
    };
    auto storeStage = [&](int buf) {
#pragma unroll
        for (int p = 0; p < 2; p++) {
            int f = tid + p * 256;
            int m = f >> 2, kq = f & 3;
            As[buf][kq * 4 + 0][m] = ra[p].x;
            As[buf][kq * 4 + 1][m] = ra[p].y;
            As[buf][kq * 4 + 2][m] = ra[p].z;
            As[buf][kq * 4 + 3][m] = ra[p].w;
        }
#pragma unroll
        for (int p = 0; p < 2; p++) {
            int f = tid + p * 256;
            int kr = f >> 5, nq = f & 31;
            *(float4*)&Bs[buf][kr][nq * 4] = rb[p];
        }
    };

    int buf = 0;
    loadStage(0);
    storeStage(0);
    __syncthreads();

    for (int kT = 0;;) {
        int kN = kT + BKg;
        bool more = kN < K;
        if (more) loadStage(kN);
#pragma unroll
        for (int kk = 0; kk < BKg; kk++) {
            float4 a0 = *(const float4*)&As[buf][kk][ty * 8];
            float4 a1 = *(const float4*)&As[buf][kk][ty * 8 + 4];
            float4 b0 = *(const float4*)&Bs[buf][kk][tx * 8];
            float4 b1 = *(const float4*)&Bs[buf][kk][tx * 8 + 4];
            unsigned long long bp0, bp1, bp2, bp3;
            PK2(bp0, b0.x, b0.y); PK2(bp1, b0.z, b0.w);
            PK2(bp2, b1.x, b1.y); PK2(bp3, b1.z, b1.w);
            float av[8] = {a0.x, a0.y, a0.z, a0.w, a1.x, a1.y, a1.z, a1.w};
#pragma unroll
            for (int i = 0; i < 8; i++) {
                unsigned long long aa;
                PK2(aa, av[i], av[i]);
                FMA2(acc2[i][0], aa, bp0);
                FMA2(acc2[i][1], aa, bp1);
                FMA2(acc2[i][2], aa, bp2);
                FMA2(acc2[i][3], aa, bp3);
            }
        }
        if (!more) break;
        storeStage(buf ^ 1);
        buf ^= 1; kT = kN;
        __syncthreads();
    }

#pragma unroll
    for (int i = 0; i < 8; i++) {
        int row = m0 + ty * 8 + i;
        if (row >= M) continue;
        float cv[8];
        UPK2(cv[0], cv[1], acc2[i][0]);
        UPK2(cv[2], cv[3], acc2[i][1]);
        UPK2(cv[4], cv[5], acc2[i][2]);
        UPK2(cv[6], cv[7], acc2[i][3]);
#pragma unroll
        for (int j = 0; j < 8; j++) {
            int col = n0 + tx * 8 + j;
            if (col >= N) continue;
            float v = cv[j] + (bias ? bias[col] : 0.f);
            if (relu) v = fmaxf(v, 0.f);
            C[(long)row * ldc + coff + col] = v;
        }
    }
}

// ---------------- GAT attention coefficients (fp16 h) ----------------
__global__ void k_attn_coef(const float* __restrict__ aS, const float* __restrict__ aD) {
    int g = blockIdx.x * blockDim.x + threadIdx.x;
    if (g >= NN * HH) return;
    int n = g / HH, h = g % HH;
    const __half2* hp = (const __half2*)(g_hH + (long)n * HID + h * FF);
    float s = 0.f, d = 0.f;
#pragma unroll 13
    for (int f2 = 0; f2 < FF / 2; f2++) {
        float2 hv = __half22float2(hp[f2]);
        s += hv.x * aS[h * FF + 2 * f2] + hv.y * aS[h * FF + 2 * f2 + 1];
        d += hv.x * aD[h * FF + 2 * f2] + hv.y * aD[h * FF + 2 * f2 + 1];
    }
    g_as[g] = s;
    g_ad[g] = d;
}

// ---------------- CSR build ----------------
__global__ void k_count(const int* __restrict__ edge) {
    int i = blockIdx.x * blockDim.x + threadIdx.x;
    if (i >= ET) return;
    int dst = (i < EE) ? edge[EE + i] : i - EE;
    atomicAdd(&g_cnt[dst], 1);
}
__global__ void k_scan() {
    __shared__ int part[256];
    int tid = threadIdx.x;
    const int chunk = (NN + 255) / 256;
    int lo = tid * chunk, hi = min(lo + chunk, NN);
    int s = 0;
    for (int n = lo; n < hi; n++) s += g_cnt[n];
    part[tid] = s;
    __syncthreads();
    if (tid == 0) {
        int r = 0;
        for (int i = 0; i < 256; i++) { int t = part[i]; part[i] = r; r += t; }
        g_off[NN] = r;
    }
    __syncthreads();
    int r = part[tid];
    for (int n = lo; n < hi; n++) {
        g_off[n] = r;
        int c = g_cnt[n];
        g_cnt[n] = 0;
        r += c;
        g_dinv[n] = rsqrtf((float)(c > 0 ? c : 1));
    }
}
__global__ void k_scatter(const int* __restrict__ edge) {
    int i = blockIdx.x * blockDim.x + threadIdx.x;
    if (i >= ET) return;
    int src = (i < EE) ? edge[i]      : i - EE;
    int dst = (i < EE) ? edge[EE + i] : i - EE;
    int pos = g_off[dst] + atomicAdd(&g_cnt[dst], 1);
    g_srcA[pos] = src;
}

// ---------------- fused softmax + GAT aggregation (fp16 in/out) ----------------
__device__ __forceinline__ uint32_t fmapU(float f) {
    uint32_t u = __float_as_uint(f);
    return u ^ (uint32_t)(((int)u >> 31) | 0x80000000);
}
__device__ __forceinline__ float finvU(uint32_t u) {
    return (u & 0x80000000u) ? __uint_as_float(u ^ 0x80000000u) : __uint_as_float(~u);
}
__global__ void __launch_bounds__(256) k_gat_soft_agg(const float* __restrict__ gat_b) {
    __shared__ float sal[DMAX * HH];
    __shared__ uint32_t sm[HH];
    __shared__ float sden[HH], sad[HH];
    int n = blockIdx.x, t = threadIdx.x;
    int lo = g_off[n], d = g_off[n + 1] - lo;
    float* ebuf = (d <= DMAX) ? sal : &g_e[(long)lo * HH];
    if (t < HH) { sm[t] = fmapU(-INFINITY); sden[t] = 0.f; sad[t] = g_ad[n * HH + t]; }
    __syncthreads();
    int tot = d * HH;
    for (int p = t; p < tot; p += 256) {
        int i = p / HH, h = p - i * HH;
        int src = g_srcA[lo + i];
        float e = g_as[src * HH + h] + sad[h];
        e = (e > 0.f) ? e : 0.2f * e;
        ebuf[p] = e;
        atomicMax(&sm[h], fmapU(e));
    }
    __syncthreads();
    for (int p = t; p < tot; p += 256) {
        int h = p % HH;
        float ex = expf(ebuf[p] - finvU(sm[h]));
        ebuf[p] = ex;
        atomicAdd(&sden[h], ex);
    }
    __syncthreads();
    if (t < HH) sden[t] = 1.f / sden[t];
    __syncthreads();
    for (int p = t; p < tot; p += 256) ebuf[p] *= sden[p % HH];
    __syncthreads();

    if (t >= 208) return;
    long base = (long)n * KPG + t * 4;
    if (t >= 195) {  // pad cols 780..831
        __half2 z = __floats2half2_rn(0.f, 0.f);
        *(__half2*)(g_Ag + base) = z;
        *(__half2*)(g_Ag + base + 2) = z;
        return;
    }
    int q = t * 4;
    int h0 = q / FF, h1 = (q + 1) / FF, h2 = (q + 2) / FF, h3 = (q + 3) / FF;
    float ax = 0.f, ay = 0.f, az = 0.f, aw = 0.f;
    for (int idx = 0; idx < d; idx++) {
        int s = g_srcA[lo + idx];
        uint2 u = *(const uint2*)(g_hH + (long)s * HID + q);
        float2 v01 = __half22float2(*(__half2*)&u.x);
        float2 v23 = __half22float2(*(__half2*)&u.y);
        const float* al = &ebuf[idx * HH];
        ax += v01.x * al[h0];
        ay += v01.y * al[h1];
        az += v23.x * al[h2];
        aw += v23.y * al[h3];
    }
    float v0 = fmaxf(ax + gat_b[q + 0], 0.f);
    float v1 = fmaxf(ay + gat_b[q + 1], 0.f);
    float v2 = fmaxf(az + gat_b[q + 2], 0.f);
    float v3 = fmaxf(aw + gat_b[q + 3], 0.f);
    *(__half2*)(g_Ag + base)     = __floats2half2_rn(v0, v1);
    *(__half2*)(g_Ag + base + 2) = __floats2half2_rn(v2, v3);
}

// ---------------- fused GCN aggregation + bias/relu + pool (fp16 in) ----------------
__global__ void __launch_bounds__(256) k_gcn_agg_pool(const float* __restrict__ gcn_b,
                                                      const int* __restrict__ batch) {
    int n = blockIdx.x, t = threadIdx.x;
    if (t >= 195) return;
    int b = batch[n];
    int q = t * 4;
    float dn = g_dinv[n];
    float ax = 0.f, ay = 0.f, az = 0.f, aw = 0.f;
    int lo = g_off[n], hi = g_off[n + 1];
    for (int idx = lo; idx < hi; idx++) {
        int s = g_srcA[idx];
        float norm = dn * g_dinv[s];
        uint2 u = *(const uint2*)(g_h2H + (long)s * HID + q);
        float2 v01 = __half22float2(*(__half2*)&u.x);
        float2 v23 = __half22float2(*(__half2*)&u.y);
        ax += v01.x * norm;
        ay += v01.y * norm;
        az += v23.x * norm;
        aw += v23.y * norm;
    }
    float* o = g_xg + (long)b * HID + q;
    atomicAdd(o + 0, fmaxf(ax + gcn_b[q + 0], 0.f));
    atomicAdd(o + 1, fmaxf(ay + gcn_b[q + 1], 0.f));
    atomicAdd(o + 2, fmaxf(az + gcn_b[q + 2], 0.f));
    atomicAdd(o + 3, fmaxf(aw + gcn_b[q + 3], 0.f));
}

// ---------------- protein branch ----------------
__global__ void k_Pbias(const float* __restrict__ emb, const float* __restrict__ cW,
                        const float* __restrict__ fxtW, const float* __restrict__ cb) {
    int bi = blockIdx.x, j = threadIdx.x;
    if (bi < 256) {
        int o = bi >> 3, c = bi & 7;
        int t0 = c * 125, t1 = min(t0 + 125, COUT);
        float p = 0.f;
        for (int t = t0; t < t1; t++)
            p += fxtW[((long)(o * COUT + t)) * 128 + j];
        atomicAdd(&g_biasY[j], cb[o] * p);
    } else {
        int g = (bi - 256) * 128 + j;
        if (g >= VOC * NF * KS) return;
        int v = g / (NF * KS), r = g % (NF * KS);
        int o = r / KS, k = r % KS;
        float s = 0.f;
#pragma unroll 16
        for (int e = 0; e < EMB; e++)
            s += emb[v * EMB + e] * cW[o * EMB * KS + e * KS + k];
        g_P[g] = s;
    }
}
__global__ void k_R(const float* __restrict__ fxtW) {
    __shared__ float Ps[VOC * NF * KS];
    int s = blockIdx.x, j = threadIdx.x;
    for (int idx = j; idx < VOC * NF * KS; idx += 128) Ps[idx] = g_P[idx];
    __syncthreads();
    float acc[VOC];
#pragma unroll
    for (int v = 0; v < VOC; v++) acc[v] = 0.f;
    int kmin = (s > COUT - 1) ? (s - (COUT - 1)) : 0;
    int kmax = (s < KS - 1) ? s : (KS - 1);
    for (int o = 0; o < NF; o++) {
        for (int k = kmin; k <= kmax; k++) {
            float w = fxtW[((long)(o * COUT + s - k)) * 128 + j];
#pragma unroll
            for (int v = 0; v < VOC; v++)
                acc[v] += Ps[v * (NF * KS) + o * KS + k] * w;
        }
    }
#pragma unroll
    for (int v = 0; v < VOC; v++)
        g_R[((long)v * SEQ + s) * 128 + j] = acc[v];
}
__global__ void k_Y(const int* __restrict__ target, const float* __restrict__ fxt_b) {
    int b = blockIdx.x, ch = blockIdx.y, j = threadIdx.x;
    int s0 = ch * 125, s1 = s0 + 125;
    float acc = (ch == 0) ? (g_biasY[j] + fxt_b[j]) : 0.f;
#pragma unroll 5
    for (int s = s0; s < s1; s++) {
        int v = target[b * SEQ + s];
        acc += g_R[((long)v * SEQ + s) * 128 + j];
    }
    atomicAdd(&g_xc[b * 256 + 128 + j], acc);
}

// ---------------- output ----------------
__global__ void k_out(const float* __restrict__ oW, const float* __restrict__ ob,
                      float* __restrict__ out) {
    __shared__ float red[4];
    int b = blockIdx.x, j = threadIdx.x;
    float v = g_t5[b * 128 + j] * oW[j];
#pragma unroll
    for (int off = 16; off; off >>= 1) v += __shfl_down_sync(0xffffffffu, v, off);
    if ((j & 31) == 0) red[j >> 5] = v;
    __syncthreads();
    if (j == 0) out[b] = red[0] + red[1] + red[2] + red[3] + ob[0];
}

// ---------------- host ----------------
static inline dim3 ggrid(long n, int t) { return dim3((unsigned)((n + t - 1) / t)); }

extern "C" void kernel_launch(void* const* d_in, const int* in_sizes, int n_in,
                              void* d_out, int out_size) {
    const float* x      = (const float*)d_in[0];
    const int*   edge   = (const int*)  d_in[1];
    const int*   batch  = (const int*)  d_in[2];
    const int*   target = (const int*)  d_in[3];
    const float* gat_W  = (const float*)d_in[4];
    const float* a_src  = (const float*)d_in[5];
    const float* a_dst  = (const float*)d_in[6];
    const float* gat_b  = (const float*)d_in[7];
    const float* gcn_W  = (const float*)d_in[8];
    const float* gcn_b  = (const float*)d_in[9];
    const float* fcg1_W = (const float*)d_in[10];
    const float* fcg1_b = (const float*)d_in[11];
    const float* fcg2_W = (const float*)d_in[12];
    const float* fcg2_b = (const float*)d_in[13];
    const float* emb    = (const float*)d_in[14];
    const float* cW     = (const float*)d_in[15];
    const float* cb     = (const float*)d_in[16];
    const float* fxt_W  = (const float*)d_in[17];
    const float* fxt_b  = (const float*)d_in[18];
    const float* f1_W   = (const float*)d_in[19];
    const float* f1_b   = (const float*)d_in[20];
    const float* f2_W   = (const float*)d_in[21];
    const float* f2_b   = (const float*)d_in[22];
    const float* f3_W   = (const float*)d_in[23];
    const float* f3_b   = (const float*)d_in[24];
    const float* f4_W   = (const float*)d_in[25];
    const float* f4_b   = (const float*)d_in[26];
    const float* o_W    = (const float*)d_in[27];
    const float* o_b    = (const float*)d_in[28];
    float* out = (float*)d_out;

    float *p_xg, *p_t1, *p_xc, *p_t2, *p_t3, *p_t4, *p_t5;
    __half *p_hH, *p_h2H, *p_Axh, *p_Bah, *p_Ag, *p_Bgh;
    cudaGetSymbolAddress((void**)&p_hH,  g_hH);
    cudaGetSymbolAddress((void**)&p_h2H, g_h2H);
    cudaGetSymbolAddress((void**)&p_xg,  g_xg);
    cudaGetSymbolAddress((void**)&p_t1,  g_t1);
    cudaGetSymbolAddress((void**)&p_xc,  g_xc);
    cudaGetSymbolAddress((void**)&p_t2,  g_t2);
    cudaGetSymbolAddress((void**)&p_t3,  g_t3);
    cudaGetSymbolAddress((void**)&p_t4,  g_t4);
    cudaGetSymbolAddress((void**)&p_t5,  g_t5);
    cudaGetSymbolAddress((void**)&p_Axh, g_Axh);
    cudaGetSymbolAddress((void**)&p_Bah, g_Bah);
    cudaGetSymbolAddress((void**)&p_Ag,  g_Ag);
    cudaGetSymbolAddress((void**)&p_Bgh, g_Bgh);

    static cudaStream_t s1, s2;
    static cudaEvent_t eF, e1, e2;
    static int inited = 0;
    if (!inited) {
        cudaStreamCreateWithFlags(&s1, cudaStreamNonBlocking);
        cudaStreamCreateWithFlags(&s2, cudaStreamNonBlocking);
        cudaEventCreateWithFlags(&eF, cudaEventDisableTiming);
        cudaEventCreateWithFlags(&e1, cudaEventDisableTiming);
        cudaEventCreateWithFlags(&e2, cudaEventDisableTiming);
        cudaFuncSetAttribute(gemm_mma, cudaFuncAttributeMaxDynamicSharedMemorySize, GEMM_SMEM);
        inited = 1;
    }

    // fork point
    k_init0<<<ggrid(BB * HID, 256), 256>>>();
    cudaEventRecord(eF, 0);
    cudaStreamWaitEvent(s1, eF, 0);
    cudaStreamWaitEvent(s2, eF, 0);

    // s1: CSR build (independent of GEMMs)
    k_count<<<ggrid(ET, 256), 256, 0, s1>>>(edge);
    k_scan<<<1, 256, 0, s1>>>();
    k_scatter<<<ggrid(ET, 256), 256, 0, s1>>>(edge);
    cudaEventRecord(e1, s1);

    // s2: protein branch
    k_Pbias<<<308, 128, 0, s2>>>(emb, cW, fxt_W, cb);
    k_R<<<SEQ, 128, 0, s2>>>(fxt_W);
    k_Y<<<dim3(BB, 8), 128, 0, s2>>>(target, fxt_b);
    cudaEventRecord(e2, s2);

    // main stream: graph branch
    k_half<<<ggrid((long)NN * KPA, 256), 256>>>(x, p_Axh, NN, FF, KPA);
    k_halfT<<<ggrid((long)HID * KPA, 256), 256>>>(gat_W, p_Bah, FF, HID, KPA);
    k_halfT<<<ggrid((long)HID * KPG, 256), 256>>>(gcn_W, p_Bgh, HID, HID, KPG);
    gemm_mma<<<dim3(7, 157), 256, GEMM_SMEM>>>(p_Axh, p_Bah, p_hH, NN, HID, KPA, KPA / KC, HID);
    k_attn_coef<<<ggrid(NN * HH, 256), 256>>>(a_src, a_dst);
    cudaStreamWaitEvent(0, e1, 0);
    k_gat_soft_agg<<<NN, 256>>>(gat_b);
    gemm_mma<<<dim3(7, 157), 256, GEMM_SMEM>>>(p_Ag, p_Bgh, p_h2H, NN, HID, KPG, KPG / KC, HID);
    k_gcn_agg_pool<<<NN, 256>>>(gcn_b, batch);
    sgemm2<<<dim3(12, 2), 256>>>(p_xg, fcg1_W, p_t1, fcg1_b, BB, 1500, HID, HID, 1500, 1500, 0, 1);
    sgemm2<<<dim3(1, 2), 256>>>(p_t1, fcg2_W, p_xc, fcg2_b, BB, 128, 1500, 1500, 128, 256, 0, 0);
    cudaStreamWaitEvent(0, e2, 0);
    sgemm2<<<dim3(8, 2), 256>>>(p_xc, f1_W, p_t2, f1_b, BB, 1024, 256, 256, 1024, 1024, 0, 1);
    sgemm2<<<dim3(4, 2), 256>>>(p_t2, f2_W, p_t3, f2_b, BB, 512, 1024, 1024, 512, 512, 0, 1);
    sgemm2<<<dim3(2, 2), 256>>>(p_t3, f3_W, p_t4, f3_b, BB, 256, 512, 512, 256, 256, 0, 1);
    sgemm2<<<dim3(1, 2), 256>>>(p_t4, f4_W, p_t5, f4_b, BB, 128, 256, 256, 128, 128, 0, 1);
    k_out<<<BB, 128>>>(o_W, o_b, out);
}

// round 7
// speedup vs baseline: 5.7360x; 1.0132x over previous
#include <cuda_runtime.h>
#include <cuda_fp16.h>
#include <math.h>
#include <stdint.h>

#define NN   20000
#define EE   400000
#define ET   (EE + NN)
#define HH   10
#define FF   78
#define HID  780
#define BB   200
#define SEQ  1000
#define VOC  26
#define EMB  128
#define NF   32
#define KS   8
#define COUT 993
#define KPA  128
#define KPG  832
#define DMAX 256

// ---------------- scratch ----------------
__device__ __half g_hH [(long)NN * HID];
__device__ __half g_h2H[(long)NN * HID];
__device__ float g_as [NN * HH];
__device__ float g_ad [NN * HH];
__device__ float g_e  [(long)ET * HH];
__device__ float g_xg [BB * HID];
__device__ float g_t1 [BB * 1500];
__device__ float g_xc [BB * 256];
__device__ float g_t2 [BB * 1024];
__device__ float g_t3 [BB * 512];
__device__ float g_t4 [BB * 256];
__device__ float g_t5 [BB * 128];
__device__ float g_P  [VOC * NF * KS];
__device__ float g_R  [(long)VOC * SEQ * 128];
__device__ float g_biasY[128];
__device__ int   g_cnt[NN];        // zero at load; invariant: zero at kernel_launch entry
__device__ int   g_off[NN + 1];
__device__ int   g_srcA[ET];
__device__ float g_dinv[NN];
__device__ __half g_Axh[(long)NN * KPA];
__device__ __half g_Bah[(long)HID * KPA];
__device__ __half g_Ag [(long)NN * KPG];
__device__ __half g_Bgh[(long)HID * KPG];

// ---------------- helpers ----------------
__device__ __forceinline__ uint32_t smem_u32(const void* p) {
    uint32_t a;
    asm("{ .reg .u64 t; cvta.to.shared.u64 t, %1; cvt.u32.u64 %0, t; }" : "=r"(a) : "l"(p));
    return a;
}
__device__ __forceinline__ void cpasync16(uint32_t dst, const void* src, int nbytes) {
    asm volatile("cp.async.cg.shared.global [%0], [%1], 16, %2;"
                 :: "r"(dst), "l"(__cvta_generic_to_global(src)), "r"(nbytes) : "memory");
}
__device__ __forceinline__ void ldm4(uint32_t* r, uint32_t addr) {
    asm volatile("ldmatrix.sync.aligned.m8n8.x4.shared.b16 {%0,%1,%2,%3}, [%4];"
                 : "=r"(r[0]), "=r"(r[1]), "=r"(r[2]), "=r"(r[3]) : "r"(addr));
}
__device__ __forceinline__ void mma16816h(float* c, const uint32_t* a, uint32_t b0, uint32_t b1) {
    asm volatile("mma.sync.aligned.m16n8k16.row.col.f32.f16.f16.f32 "
                 "{%0,%1,%2,%3}, {%4,%5,%6,%7}, {%8,%9}, {%0,%1,%2,%3};"
                 : "+f"(c[0]), "+f"(c[1]), "+f"(c[2]), "+f"(c[3])
                 : "r"(a[0]), "r"(a[1]), "r"(a[2]), "r"(a[3]), "r"(b0), "r"(b1));
}

#define PK2(d, lo, hi) asm("mov.b64 %0, {%1,%2};" : "=l"(d) : "r"(__float_as_uint(lo)), "r"(__float_as_uint(hi)))
#define FMA2(d, a, b)  asm("fma.rn.f32x2 %0, %1, %2, %3;" : "=l"(d) : "l"(a), "l"(b), "l"(d))
#define UPK2(lo, hi, s) { unsigned int u0_, u1_; asm("mov.b64 {%0,%1}, %2;" : "=r"(u0_), "=r"(u1_) : "l"(s)); lo = __uint_as_float(u0_); hi = __uint_as_float(u1_); }

// ---------------- zero-init (xg + biasY only) ----------------
__global__ void k_init0() {
    int i = blockIdx.x * blockDim.x + threadIdx.x;
    if (i < BB * HID) g_xg[i] = 0.f;
    if (i < 128)      g_biasY[i] = 0.f;
}

// ============ pure fp16 tensor-core GEMM ============
#define KC 32
#define ASTR 40
#define HALF_BYTES (128 * ASTR * 2)
#define STAGE_BYTES (2 * HALF_BYTES)
#define GEMM_SMEM (2 * STAGE_BYTES)

__global__ void __launch_bounds__(256)
gemm_mma(const __half* __restrict__ Ah, const __half* __restrict__ Bh,
         __half* __restrict__ C, int M, int N, int Kp, int NC, int ldc) {
    extern __shared__ char smem_raw[];
    uint32_t sb = smem_u32(smem_raw);
    int tid = threadIdx.x, w = tid >> 5, l = tid & 31;
    int m0 = blockIdx.y * 128, n0 = blockIdx.x * 128;
    int wm = w & 3, wn = w >> 2;

    float acc[2][8][4];
#pragma unroll
    for (int i = 0; i < 2; i++)
#pragma unroll
        for (int j = 0; j < 8; j++)
#pragma unroll
            for (int q = 0; q < 4; q++) acc[i][j][q] = 0.f;

    auto issue = [&](int c) {
        int k0 = c * KC;
        uint32_t st = sb + (uint32_t)(c & 1) * STAGE_BYTES;
#pragma unroll
        for (int p = 0; p < 2; p++) {
            int f = tid + p * 256;
            int row = f >> 2, c16 = f & 3;
            uint32_t doff = (uint32_t)(row * (ASTR * 2) + c16 * 16);
            int am = m0 + row;
            int amc = am < M ? am : M - 1;
            int av = am < M ? 16 : 0;
            cpasync16(st + doff, Ah + (long)amc * Kp + k0 + c16 * 8, av);
            int bn = n0 + row;
            int bnc = bn < N ? bn : N - 1;
            int bv = bn < N ? 16 : 0;
            cpasync16(st + HALF_BYTES + doff, Bh + (long)bnc * Kp + k0 + c16 * 8, bv);
        }
        asm volatile("cp.async.commit_group;" ::: "memory");
    };

    issue(0);
    for (int c = 0; c < NC; c++) {
        if (c + 1 < NC) {
            issue(c + 1);
            asm volatile("cp.async.wait_group 1;" ::: "memory");
        } else {
            asm volatile("cp.async.wait_group 0;" ::: "memory");
        }
        __syncthreads();
        uint32_t st = sb + (uint32_t)(c & 1) * STAGE_BYTES;
        int lrow = l & 15, lcb = l >> 4;
#pragma unroll
        for (int k16 = 0; k16 < 2; k16++) {
            uint32_t coff = (uint32_t)((k16 * 16 + lcb * 8) * 2);
            uint32_t bh[4][4];
#pragma unroll
            for (int nt2 = 0; nt2 < 4; nt2++) {
                uint32_t roff = (uint32_t)((wn * 64 + nt2 * 16 + lrow) * (ASTR * 2));
                ldm4(bh[nt2], st + HALF_BYTES + roff + coff);
            }
#pragma unroll
            for (int mt = 0; mt < 2; mt++) {
                uint32_t roff = (uint32_t)((wm * 32 + mt * 16 + lrow) * (ASTR * 2));
                uint32_t ah[4];
                ldm4(ah, st + roff + coff);
#pragma unroll
                for (int nt = 0; nt < 8; nt++) {
                    int nt2 = nt >> 1, sel = nt & 1;
                    mma16816h(acc[mt][nt], ah, bh[nt2][sel], bh[nt2][sel + 2]);
                }
            }
        }
        __syncthreads();
    }

#pragma unroll
    for (int mt = 0; mt < 2; mt++) {
#pragma unroll
        for (int nt = 0; nt < 8; nt++) {
            int row = m0 + wm * 32 + mt * 16 + (l >> 2);
            int col = n0 + wn * 64 + nt * 8 + 2 * (l & 3);
            if (col < N) {
                if (row < M)
                    *(__half2*)(C + (long)row * ldc + col) =
                        __floats2half2_rn(acc[mt][nt][0], acc[mt][nt][1]);
                int row2 = row + 8;
                if (row2 < M)
                    *(__half2*)(C + (long)row2 * ldc + col) =
                        __floats2half2_rn(acc[mt][nt][2], acc[mt][nt][3]);
            }
        }
    }
}

// ---------------- fp16 conversions ----------------
__global__ void k_half(const float* __restrict__ src, __half* __restrict__ dh,
                       int M, int Ksrc, int Kp) {
    long i = (long)blockIdx.x * blockDim.x + threadIdx.x;
    if (i >= (long)M * Kp) return;
    int m = (int)(i / Kp), k = (int)(i % Kp);
    dh[i] = __float2half_rn((k < Ksrc) ? src[(long)m * Ksrc + k] : 0.f);
}
__global__ void k_halfT(const float* __restrict__ W, __half* __restrict__ dh,
                        int K, int N, int Kp) {
    long i = (long)blockIdx.x * blockDim.x + threadIdx.x;
    if (i >= (long)N * Kp) return;
    int n = (int)(i / Kp), k = (int)(i % Kp);
    dh[i] = __float2half_rn((k < K) ? W[(long)k * N + n] : 0.f);
}

// ---------------- SGEMM (FFMA2) for small MLP layers ----------------
#define BKg 16
__global__ void __launch_bounds__(256)
sgemm2(const float* __restrict__ A, const float* __restrict__ B,
       float* __restrict__ C, const float* __restrict__ bias,
       int M, int N, int K, int lda, int ldb, int ldc, int coff, int relu) {
    __shared__ float As[2][BKg][132];
    __shared__ float Bs[2][BKg][128];
    int tid = threadIdx.x;
    int m0 = blockIdx.y * 128, n0 = blockIdx.x * 128;
    int ty = tid >> 4, tx = tid & 15;

    unsigned long long acc2[8][4];
#pragma unroll
    for (int i = 0; i < 8; i++)
#pragma unroll
        for (int j = 0; j < 4; j++) acc2[i][j] = 0ull;

    float4 ra[2], rb[2];
    auto loadStage = [&](int kT) {
#pragma unroll
        for (int p = 0; p < 2; p++) {
            int f = tid + p * 256;
            int m = f >> 2, kq = f & 3;
            int gm = m0 + m, gk = kT + kq * 4;
            const float* ap = A + (long)gm * lda + gk;
            if (gm < M && gk + 3 < K) ra[p] = *(const float4*)ap;
            else {
                ra[p].x = (gm < M && gk     < K) ? ap[0] : 0.f;
                ra[p].y = (gm < M && gk + 1 < K) ? ap[1] : 0.f;
                ra[p].z = (gm < M && gk + 2 < K) ? ap[2] : 0.f;
                ra[p].w = (gm < M && gk + 3 < K) ? ap[3] : 0.f;
            }
        }
#pragma unroll
        for (int p = 0; p < 2; p++) {
            int f = tid + p * 256;
            int kr = f >> 5, nq = f & 31;
            int gk = kT + kr, gn = n0 + nq * 4;
            const float* bp = B + (long)gk * ldb + gn;
            if (gk < K && gn + 3 < N) rb[p] = *(const float4*)bp;
            else {
                rb[p].x = (gk < K && gn     < N) ? bp[0] : 0.f;
                rb[p].y = (gk < K && gn + 1 < N) ? bp[1] : 0.f;
                rb[p].z = (gk < K && gn + 2 < N) ? bp[2] : 0.f;
                rb[p].w = (gk < K && gn + 3 < N) ? bp[3] : 0.f;
            }
        }
    };
    auto storeStage = [&](int buf) {
#pragma unroll
        for (int p = 0; p < 2; p++) {
            int f = tid + p * 256;
            int m = f >> 2, kq = f & 3;
            As[buf][kq * 4 + 0][m] = ra[p].x;
            As[buf][kq * 4 + 1][m] = ra[p].y;
            As[buf][kq * 4 + 2][m] = ra[p].z;
            As[buf][kq * 4 + 3][m] = ra[p].w;
        }
#pragma unroll
        for (int p = 0; p < 2; p++) {
            int f = tid + p * 256;
            int kr = f >> 5, nq = f & 31;
            *(float4*)&Bs[buf][kr][nq * 4] = rb[p];
        }
    };

    int buf = 0;
    loadStage(0);
    storeStage(0);
    __syncthreads();

    for (int kT = 0;;) {
        int kN = kT + BKg;
        bool more = kN < K;
        if (more) loadStage(kN);
#pragma unroll
        for (int kk = 0; kk < BKg; kk++) {
            float4 a0 = *(const float4*)&As[buf][kk][ty * 8];
            float4 a1 = *(const float4*)&As[buf][kk][ty * 8 + 4];
            float4 b0 = *(const float4*)&Bs[buf][kk][tx * 8];
            float4 b1 = *(const float4*)&Bs[buf][kk][tx * 8 + 4];
            unsigned long long bp0, bp1, bp2, bp3;
            PK2(bp0, b0.x, b0.y); PK2(bp1, b0.z, b0.w);
            PK2(bp2, b1.x, b1.y); PK2(bp3, b1.z, b1.w);
            float av[8] = {a0.x, a0.y, a0.z, a0.w, a1.x, a1.y, a1.z, a1.w};
#pragma unroll
            for (int i = 0; i < 8; i++) {
                unsigned long long aa;
                PK2(aa, av[i], av[i]);
                FMA2(acc2[i][0], aa, bp0);
                FMA2(acc2[i][1], aa, bp1);
                FMA2(acc2[i][2], aa, bp2);
                FMA2(acc2[i][3], aa, bp3);
            }
        }
        if (!more) break;
        storeStage(buf ^ 1);
        buf ^= 1; kT = kN;
        __syncthreads();
    }

#pragma unroll
    for (int i = 0; i < 8; i++) {
        int row = m0 + ty * 8 + i;
        if (row >= M) continue;
        float cv[8];
        UPK2(cv[0], cv[1], acc2[i][0]);
        UPK2(cv[2], cv[3], acc2[i][1]);
        UPK2(cv[4], cv[5], acc2[i][2]);
        UPK2(cv[6], cv[7], acc2[i][3]);
#pragma unroll
        for (int j = 0; j < 8; j++) {
            int col = n0 + tx * 8 + j;
            if (col >= N) continue;
            float v = cv[j] + (bias ? bias[col] : 0.f);
            if (relu) v = fmaxf(v, 0.f);
            C[(long)row * ldc + coff + col] = v;
        }
    }
}

// ---------------- GAT attention coefficients ----------------
__global__ void k_attn_coef(const float* __restrict__ aS, const float* __restrict__ aD) {
    int g = blockIdx.x * blockDim.x + threadIdx.x;
    if (g >= NN * HH) return;
    int n = g / HH, h = g % HH;
    const __half2* hp = (const __half2*)(g_hH + (long)n * HID + h * FF);
    float s = 0.f, d = 0.f;
#pragma unroll 13
    for (int f2 = 0; f2 < FF / 2; f2++) {
        float2 hv = __half22float2(hp[f2]);
        s += hv.x * aS[h * FF + 2 * f2] + hv.y * aS[h * FF + 2 * f2 + 1];
        d += hv.x * aD[h * FF + 2 * f2] + hv.y * aD[h * FF + 2 * f2 + 1];
    }
    g_as[g] = s;
    g_ad[g] = d;
}

// ---------------- CSR build (self-restoring counters) ----------------
__global__ void k_count(const int* __restrict__ edge) {
    int i = blockIdx.x * blockDim.x + threadIdx.x;
    if (i >= ET) return;
    int dst = (i < EE) ? edge[EE + i] : i - EE;
    atomicAdd(&g_cnt[dst], 1);
}
__global__ void k_scan() {
    __shared__ int part[256];
    int tid = threadIdx.x;
    const int chunk = (NN + 255) / 256;
    int lo = tid * chunk, hi = min(lo + chunk, NN);
    int s = 0;
    for (int n = lo; n < hi; n++) s += g_cnt[n];
    part[tid] = s;
    __syncthreads();
    if (tid == 0) {
        int r = 0;
        for (int i = 0; i < 256; i++) { int t = part[i]; part[i] = r; r += t; }
        g_off[NN] = r;
    }
    __syncthreads();
    int r = part[tid];
    for (int n = lo; n < hi; n++) {
        g_off[n] = r;
        int c = g_cnt[n];
        r += c;
        g_dinv[n] = rsqrtf((float)(c > 0 ? c : 1));
    }
}
__global__ void k_scatter(const int* __restrict__ edge) {
    int i = blockIdx.x * blockDim.x + threadIdx.x;
    if (i >= ET) return;
    int src = (i < EE) ? edge[i]      : i - EE;
    int dst = (i < EE) ? edge[EE + i] : i - EE;
    int old = atomicSub(&g_cnt[dst], 1);     // ends at 0 -> invariant restored
    g_srcA[g_off[dst] + old - 1] = src;
}

// ---------------- fused softmax + GAT aggregation (MLP-4) ----------------
__device__ __forceinline__ uint32_t fmapU(float f) {
    uint32_t u = __float_as_uint(f);
    return u ^ (uint32_t)(((int)u >> 31) | 0x80000000);
}
__device__ __forceinline__ float finvU(uint32_t u) {
    return (u & 0x80000000u) ? __uint_as_float(u ^ 0x80000000u) : __uint_as_float(~u);
}
__global__ void __launch_bounds__(256) k_gat_soft_agg(const float* __restrict__ gat_b) {
    __shared__ float sal[DMAX * HH];
    __shared__ int ssrc[DMAX];
    __shared__ uint32_t sm[HH];
    __shared__ float sden[HH], sad[HH];
    int n = blockIdx.x, t = threadIdx.x;
    int lo = g_off[n], d = g_off[n + 1] - lo;
    bool small = (d <= DMAX);
    float* ebuf = small ? sal : &g_e[(long)lo * HH];
    const int* sp = small ? ssrc : &g_srcA[lo];
    if (t < HH) { sm[t] = fmapU(-INFINITY); sden[t] = 0.f; sad[t] = g_ad[n * HH + t]; }
    if (small)
        for (int i = t; i < d; i += 256) ssrc[i] = g_srcA[lo + i];
    __syncthreads();
    int tot = d * HH;
    for (int p = t; p < tot; p += 256) {
        int i = p / HH, h = p - i * HH;
        int src = sp[i];
        float e = g_as[src * HH + h] + sad[h];
        e = (e > 0.f) ? e : 0.2f * e;
        ebuf[p] = e;
        atomicMax(&sm[h], fmapU(e));
    }
    __syncthreads();
    for (int p = t; p < tot; p += 256) {
        int h = p % HH;
        float ex = expf(ebuf[p] - finvU(sm[h]));
        ebuf[p] = ex;
        atomicAdd(&sden[h], ex);
    }
    __syncthreads();
    if (t < HH) sden[t] = 1.f / sden[t];
    __syncthreads();
    for (int p = t; p < tot; p += 256) ebuf[p] *= sden[p % HH];
    __syncthreads();

    if (t >= 208) return;
    long base = (long)n * KPG + t * 4;
    if (t >= 195) {
        __half2 z = __floats2half2_rn(0.f, 0.f);
        *(__half2*)(g_Ag + base) = z;
        *(__half2*)(g_Ag + base + 2) = z;
        return;
    }
    int q = t * 4;
    int h0 = q / FF, h1 = (q + 1) / FF, h2 = (q + 2) / FF, h3 = (q + 3) / FF;
    float ax = 0.f, ay = 0.f, az = 0.f, aw = 0.f;
    int idx = 0;
    for (; idx + 3 < d; idx += 4) {
        int s0 = sp[idx], s1 = sp[idx + 1], s2 = sp[idx + 2], s3 = sp[idx + 3];
        uint2 u0 = *(const uint2*)(g_hH + (long)s0 * HID + q);
        uint2 u1 = *(const uint2*)(g_hH + (long)s1 * HID + q);
        uint2 u2 = *(const uint2*)(g_hH + (long)s2 * HID + q);
        uint2 u3 = *(const uint2*)(g_hH + (long)s3 * HID + q);
        const float* a0 = &ebuf[idx * HH];
        const float* a1 = &ebuf[(idx + 1) * HH];
        const float* a2 = &ebuf[(idx + 2) * HH];
        const float* a3 = &ebuf[(idx + 3) * HH];
        float2 v01, v23;
        v01 = __half22float2(*(__half2*)&u0.x); v23 = __half22float2(*(__half2*)&u0.y);
        ax += v01.x * a0[h0]; ay += v01.y * a0[h1]; az += v23.x * a0[h2]; aw += v23.y * a0[h3];
        v01 = __half22float2(*(__half2*)&u1.x); v23 = __half22float2(*(__half2*)&u1.y);
        ax += v01.x * a1[h0]; ay += v01.y * a1[h1]; az += v23.x * a1[h2]; aw += v23.y * a1[h3];
        v01 = __half22float2(*(__half2*)&u2.x); v23 = __half22float2(*(__half2*)&u2.y);
        ax += v01.x * a2[h0]; ay += v01.y * a2[h1]; az += v23.x * a2[h2]; aw += v23.y * a2[h3];
        v01 = __half22float2(*(__half2*)&u3.x); v23 = __half22float2(*(__half2*)&u3.y);
        ax += v01.x * a3[h0]; ay += v01.y * a3[h1]; az += v23.x * a3[h2]; aw += v23.y * a3[h3];
    }
    for (; idx < d; idx++) {
        int s = sp[idx];
        uint2 u = *(const uint2*)(g_hH + (long)s * HID + q);
        float2 v01 = __half22float2(*(__half2*)&u.x);
        float2 v23 = __half22float2(*(__half2*)&u.y);
        const float* al = &ebuf[idx * HH];
        ax += v01.x * al[h0]; ay += v01.y * al[h1]; az += v23.x * al[h2]; aw += v23.y * al[h3];
    }
    float v0 = fmaxf(ax + gat_b[q + 0], 0.f);
    float v1 = fmaxf(ay + gat_b[q + 1], 0.f);
    float v2 = fmaxf(az + gat_b[q + 2], 0.f);
    float v3 = fmaxf(aw + gat_b[q + 3], 0.f);
    *(__half2*)(g_Ag + base)     = __floats2half2_rn(v0, v1);
    *(__half2*)(g_Ag + base + 2) = __floats2half2_rn(v2, v3);
}

// ---------------- fused GCN aggregation + bias/relu + pool (MLP-4) ----------------
__global__ void __launch_bounds__(256) k_gcn_agg_pool(const float* __restrict__ gcn_b,
                                                      const int* __restrict__ batch) {
    int n = blockIdx.x, t = threadIdx.x;
    if (t >= 195) return;
    int b = batch[n];
    int q = t * 4;
    float dn = g_dinv[n];
    float ax = 0.f, ay = 0.f, az = 0.f, aw = 0.f;
    int lo = g_off[n], hi = g_off[n + 1];
    int idx = lo;
    for (; idx + 3 < hi; idx += 4) {
        int s0 = g_srcA[idx], s1 = g_srcA[idx + 1], s2 = g_srcA[idx + 2], s3 = g_srcA[idx + 3];
        float n0 = g_dinv[s0], n1 = g_dinv[s1], n2 = g_dinv[s2], n3 = g_dinv[s3];
        uint2 u0 = *(const uint2*)(g_h2H + (long)s0 * HID + q);
        uint2 u1 = *(const uint2*)(g_h2H + (long)s1 * HID + q);
        uint2 u2 = *(const uint2*)(g_h2H + (long)s2 * HID + q);
        uint2 u3 = *(const uint2*)(g_h2H + (long)s3 * HID + q);
        float2 v01, v23;
        n0 *= dn; n1 *= dn; n2 *= dn; n3 *= dn;
        v01 = __half22float2(*(__half2*)&u0.x); v23 = __half22float2(*(__half2*)&u0.y);
        ax += v01.x * n0; ay += v01.y * n0; az += v23.x * n0; aw += v23.y * n0;
        v01 = __half22float2(*(__half2*)&u1.x); v23 = __half22float2(*(__half2*)&u1.y);
        ax += v01.x * n1; ay += v01.y * n1; az += v23.x * n1; aw += v23.y * n1;
        v01 = __half22float2(*(__half2*)&u2.x); v23 = __half22float2(*(__half2*)&u2.y);
        ax += v01.x * n2; ay += v01.y * n2; az += v23.x * n2; aw += v23.y * n2;
        v01 = __half22float2(*(__half2*)&u3.x); v23 = __half22float2(*(__half2*)&u3.y);
        ax += v01.x * n3; ay += v01.y * n3; az += v23.x * n3; aw += v23.y * n3;
    }
    for (; idx < hi; idx++) {
        int s = g_srcA[idx];
        float norm = dn * g_dinv[s];
        uint2 u = *(const uint2*)(g_h2H + (long)s * HID + q);
        float2 v01 = __half22float2(*(__half2*)&u.x);
        float2 v23 = __half22float2(*(__half2*)&u.y);
        ax += v01.x * norm; ay += v01.y * norm; az += v23.x * norm; aw += v23.y * norm;
    }
    float* o = g_xg + (long)b * HID + q;
    atomicAdd(o + 0, fmaxf(ax + gcn_b[q + 0], 0.f));
    atomicAdd(o + 1, fmaxf(ay + gcn_b[q + 1], 0.f));
    atomicAdd(o + 2, fmaxf(az + gcn_b[q + 2], 0.f));
    atomicAdd(o + 3, fmaxf(aw + gcn_b[q + 3], 0.f));
}

// ---------------- protein branch ----------------
__global__ void k_Pbias(const float* __restrict__ emb, const float* __restrict__ cW,
                        const float* __restrict__ fxtW, const float* __restrict__ cb) {
    int bi = blockIdx.x, j = threadIdx.x;
    if (bi < 256) {
        int o = bi >> 3, c = bi & 7;
        int t0 = c * 125, t1 = min(t0 + 125, COUT);
        float p = 0.f;
        for (int t = t0; t < t1; t++)
            p += fxtW[((long)(o * COUT + t)) * 128 + j];
        atomicAdd(&g_biasY[j], cb[o] * p);
    } else {
        int g = (bi - 256) * 128 + j;
        if (g >= VOC * NF * KS) return;
        int v = g / (NF * KS), r = g % (NF * KS);
        int o = r / KS, k = r % KS;
        float s = 0.f;
#pragma unroll 16
        for (int e = 0; e < EMB; e++)
            s += emb[v * EMB + e] * cW[o * EMB * KS + e * KS + k];
        g_P[g] = s;
    }
}
__global__ void k_R(const float* __restrict__ fxtW) {
    __shared__ float Ps[VOC * NF * KS];
    int s = blockIdx.x, j = threadIdx.x;
    for (int idx = j; idx < VOC * NF * KS; idx += 128) Ps[idx] = g_P[idx];
    __syncthreads();
    float acc[VOC];
#pragma unroll
    for (int v = 0; v < VOC; v++) acc[v] = 0.f;
    int kmin = (s > COUT - 1) ? (s - (COUT - 1)) : 0;
    int kmax = (s < KS - 1) ? s : (KS - 1);
    for (int o = 0; o < NF; o++) {
        for (int k = kmin; k <= kmax; k++) {
            float w = fxtW[((long)(o * COUT + s - k)) * 128 + j];
#pragma unroll
            for (int v = 0; v < VOC; v++)
                acc[v] += Ps[v * (NF * KS) + o * KS + k] * w;
        }
    }
#pragma unroll
    for (int v = 0; v < VOC; v++)
        g_R[((long)v * SEQ + s) * 128 + j] = acc[v];
}
// direct-write gather (no atomics, unroll-4)
__global__ void k_Y(const int* __restrict__ target, const float* __restrict__ fxt_b) {
    __shared__ int sv[SEQ];
    int b = blockIdx.x, j = threadIdx.x;
    for (int i = j; i < SEQ; i += 128) sv[i] = target[b * SEQ + i];
    __syncthreads();
    float acc = g_biasY[j] + fxt_b[j];
    for (int s = 0; s < SEQ; s += 4) {
        float r0 = g_R[((long)sv[s]     * SEQ + s)     * 128 + j];
        float r1 = g_R[((long)sv[s + 1] * SEQ + s + 1) * 128 + j];
        float r2 = g_R[((long)sv[s + 2] * SEQ + s + 2) * 128 + j];
        float r3 = g_R[((long)sv[s + 3] * SEQ + s + 3) * 128 + j];
        acc += (r0 + r1) + (r2 + r3);
    }
    g_xc[b * 256 + 128 + j] = acc;
}

// ---------------- output ----------------
__global__ void k_out(const float* __restrict__ oW, const float* __restrict__ ob,
                      float* __restrict__ out) {
    __shared__ float red[4];
    int b = blockIdx.x, j = threadIdx.x;
    float v = g_t5[b * 128 + j] * oW[j];
#pragma unroll
    for (int off = 16; off; off >>= 1) v += __shfl_down_sync(0xffffffffu, v, off);
    if ((j & 31) == 0) red[j >> 5] = v;
    __syncthreads();
    if (j == 0) out[b] = red[0] + red[1] + red[2] + red[3] + ob[0];
}

// ---------------- host ----------------
static inline dim3 ggrid(long n, int t) { return dim3((unsigned)((n + t - 1) / t)); }

extern "C" void kernel_launch(void* const* d_in, const int* in_sizes, int n_in,
                              void* d_out, int out_size) {
    const float* x      = (const float*)d_in[0];
    const int*   edge   = (const int*)  d_in[1];
    const int*   batch  = (const int*)  d_in[2];
    const int*   target = (const int*)  d_in[3];
    const float* gat_W  = (const float*)d_in[4];
    const float* a_src  = (const float*)d_in[5];
    const float* a_dst  = (const float*)d_in[6];
    const float* gat_b  = (const float*)d_in[7];
    const float* gcn_W  = (const float*)d_in[8];
    const float* gcn_b  = (const float*)d_in[9];
    const float* fcg1_W = (const float*)d_in[10];
    const float* fcg1_b = (const float*)d_in[11];
    const float* fcg2_W = (const float*)d_in[12];
    const float* fcg2_b = (const float*)d_in[13];
    const float* emb    = (const float*)d_in[14];
    const float* cW     = (const float*)d_in[15];
    const float* cb     = (const float*)d_in[16];
    const float* fxt_W  = (const float*)d_in[17];
    const float* fxt_b  = (const float*)d_in[18];
    const float* f1_W   = (const float*)d_in[19];
    const float* f1_b   = (const float*)d_in[20];
    const float* f2_W   = (const float*)d_in[21];
    const float* f2_b   = (const float*)d_in[22];
    const float* f3_W   = (const float*)d_in[23];
    const float* f3_b   = (const float*)d_in[24];
    const float* f4_W   = (const float*)d_in[25];
    const float* f4_b   = (const float*)d_in[26];
    const float* o_W    = (const float*)d_in[27];
    const float* o_b    = (const float*)d_in[28];
    float* out = (float*)d_out;

    float *p_xg, *p_t1, *p_xc, *p_t2, *p_t3, *p_t4, *p_t5;
    __half *p_hH, *p_h2H, *p_Axh, *p_Bah, *p_Ag, *p_Bgh;
    cudaGetSymbolAddress((void**)&p_hH,  g_hH);
    cudaGetSymbolAddress((void**)&p_h2H, g_h2H);
    cudaGetSymbolAddress((void**)&p_xg,  g_xg);
    cudaGetSymbolAddress((void**)&p_t1,  g_t1);
    cudaGetSymbolAddress((void**)&p_xc,  g_xc);
    cudaGetSymbolAddress((void**)&p_t2,  g_t2);
    cudaGetSymbolAddress((void**)&p_t3,  g_t3);
    cudaGetSymbolAddress((void**)&p_t4,  g_t4);
    cudaGetSymbolAddress((void**)&p_t5,  g_t5);
    cudaGetSymbolAddress((void**)&p_Axh, g_Axh);
    cudaGetSymbolAddress((void**)&p_Bah, g_Bah);
    cudaGetSymbolAddress((void**)&p_Ag,  g_Ag);
    cudaGetSymbolAddress((void**)&p_Bgh, g_Bgh);

    static cudaStream_t s1, s2;
    static cudaEvent_t eF, e0, e1, e2;
    static int inited = 0;
    if (!inited) {
        cudaStreamCreateWithFlags(&s1, cudaStreamNonBlocking);
        cudaStreamCreateWithFlags(&s2, cudaStreamNonBlocking);
        cudaEventCreateWithFlags(&eF, cudaEventDisableTiming);
        cudaEventCreateWithFlags(&e0, cudaEventDisableTiming);
        cudaEventCreateWithFlags(&e1, cudaEventDisableTiming);
        cudaEventCreateWithFlags(&e2, cudaEventDisableTiming);
        cudaFuncSetAttribute(gemm_mma, cudaFuncAttributeMaxDynamicSharedMemorySize, GEMM_SMEM);
        inited = 1;
    }

    // fork immediately: CSR needs nothing (g_cnt invariant zero)
    cudaEventRecord(eF, 0);
    cudaStreamWaitEvent(s1, eF, 0);

    // main: conversions (launches 1-3)
    k_half<<<ggrid((long)NN * KPA, 256), 256>>>(x, p_Axh, NN, FF, KPA);
    k_halfT<<<ggrid((long)HID * KPA, 256), 256>>>(gat_W, p_Bah, FF, HID, KPA);
    k_halfT<<<ggrid((long)HID * KPG, 256), 256>>>(gcn_W, p_Bgh, HID, HID, KPG);
    // s1: CSR count+scan (4-5)
    k_count<<<ggrid(ET, 256), 256, 0, s1>>>(edge);
    k_scan<<<1, 256, 0, s1>>>();
    // main: GAT GEMM (launch 6 — profiled by ncu -s 5 -c 1)
    gemm_mma<<<dim3(7, 157), 256, GEMM_SMEM>>>(p_Axh, p_Bah, p_hH, NN, HID, KPA, KPA / KC, HID);
    // s1: scatter (7)
    k_scatter<<<ggrid(ET, 256), 256, 0, s1>>>(edge);
    cudaEventRecord(e1, s1);
    // main: init (8) + fork protein
    k_init0<<<ggrid(BB * HID, 256), 256>>>();
    cudaEventRecord(e0, 0);
    cudaStreamWaitEvent(s2, e0, 0);
    k_Pbias<<<308, 128, 0, s2>>>(emb, cW, fxt_W, cb);
    k_R<<<SEQ, 128, 0, s2>>>(fxt_W);
    k_Y<<<BB, 128, 0, s2>>>(target, fxt_b);
    cudaEventRecord(e2, s2);
    // main: graph branch
    k_attn_coef<<<ggrid(NN * HH, 256), 256>>>(a_src, a_dst);
    cudaStreamWaitEvent(0, e1, 0);
    k_gat_soft_agg<<<NN, 256>>>(gat_b);
    gemm_mma<<<dim3(7, 157), 256, GEMM_SMEM>>>(p_Ag, p_Bgh, p_h2H, NN, HID, KPG, KPG / KC, HID);
    k_gcn_agg_pool<<<NN, 256>>>(gcn_b, batch);
    sgemm2<<<dim3(12, 2), 256>>>(p_xg, fcg1_W, p_t1, fcg1_b, BB, 1500, HID, HID, 1500, 1500, 0, 1);
    sgemm2<<<dim3(1, 2), 256>>>(p_t1, fcg2_W, p_xc, fcg2_b, BB, 128, 1500, 1500, 128, 256, 0, 0);
    cudaStreamWaitEvent(0, e2, 0);
    sgemm2<<<dim3(8, 2), 256>>>(p_xc, f1_W, p_t2, f1_b, BB, 1024, 256, 256, 1024, 1024, 0, 1);
    sgemm2<<<dim3(4, 2), 256>>>(p_t2, f2_W, p_t3, f2_b, BB, 512, 1024, 1024, 512, 512, 0, 1);
    sgemm2<<<dim3(2, 2), 256>>>(p_t3, f3_W, p_t4, f3_b, BB, 256, 512, 512, 256, 256, 0, 1);
    sgemm2<<<dim3(1, 2), 256>>>(p_t4, f4_W, p_t5, f4_b, BB, 128, 256, 256, 128, 128, 0, 1);
    k_out<<<BB, 128>>>(o_W, o_b, out);
}

// round 8
// speedup vs baseline: 8.9967x; 1.5685x over previous
#include <cuda_runtime.h>
#include <cuda_fp16.h>
#include <math.h>
#include <stdint.h>

#define NN   20000
#define EE   400000
#define ET   (EE + NN)
#define HH   10
#define FF   78
#define HID  780
#define NEXT 800      // GAT gemm N: 780 feature cols + 10 a_src + 10 a_dst
#define BB   200
#define SEQ  1000
#define VOC  26
#define EMB  128
#define NF   32
#define KS   8
#define COUT 993
#define KPA  128
#define KPG  832
#define DMAX 256

// ---------------- scratch ----------------
__device__ __half g_hH [(long)NN * NEXT];     // GAT gemm out (cols 0..779 used)
__device__ __half g_h2H[(long)NN * HID];
__device__ float g_asad[NN * 20];             // fp32 attn coefs: [n][0..9]=a_s, [10..19]=a_d
__device__ float g_e  [(long)ET * HH];
__device__ float g_xg [BB * HID];
__device__ float g_t1 [BB * 1500];
__device__ float g_xc [BB * 256];
__device__ float g_t2 [BB * 1024];
__device__ float g_t3 [BB * 512];
__device__ float g_t4 [BB * 256];
__device__ float g_t5 [BB * 128];
__device__ float g_P  [VOC * NF * KS];
__device__ float g_R  [(long)VOC * SEQ * 128];
__device__ float g_biasY[128];
__device__ int   g_cnt[NN];        // invariant: zero at kernel_launch entry
__device__ int   g_off[NN + 1];
__device__ int   g_srcA[ET];
__device__ float g_dinv[NN];
__device__ __half g_Axh[(long)NN * KPA];
__device__ __half g_Bah[(long)NEXT * KPA];
__device__ __half g_Ag [(long)NN * KPG];
__device__ __half g_Bgh[(long)HID * KPG];

// ---------------- helpers ----------------
__device__ __forceinline__ uint32_t smem_u32(const void* p) {
    uint32_t a;
    asm("{ .reg .u64 t; cvta.to.shared.u64 t, %1; cvt.u32.u64 %0, t; }" : "=r"(a) : "l"(p));
    return a;
}
__device__ __forceinline__ void cpasync16(uint32_t dst, const void* src, int nbytes) {
    asm volatile("cp.async.cg.shared.global [%0], [%1], 16, %2;"
                 :: "r"(dst), "l"(__cvta_generic_to_global(src)), "r"(nbytes) : "memory");
}
__device__ __forceinline__ void ldm4(uint32_t* r, uint32_t addr) {
    asm volatile("ldmatrix.sync.aligned.m8n8.x4.shared.b16 {%0,%1,%2,%3}, [%4];"
                 : "=r"(r[0]), "=r"(r[1]), "=r"(r[2]), "=r"(r[3]) : "r"(addr));
}
__device__ __forceinline__ void mma16816h(float* c, const uint32_t* a, uint32_t b0, uint32_t b1) {
    asm volatile("mma.sync.aligned.m16n8k16.row.col.f32.f16.f16.f32 "
                 "{%0,%1,%2,%3}, {%4,%5,%6,%7}, {%8,%9}, {%0,%1,%2,%3};"
                 : "+f"(c[0]), "+f"(c[1]), "+f"(c[2]), "+f"(c[3])
                 : "r"(a[0]), "r"(a[1]), "r"(a[2]), "r"(a[3]), "r"(b0), "r"(b1));
}

// ---------------- zero-init ----------------
__global__ void k_init0() {
    int i = blockIdx.x * blockDim.x + threadIdx.x;
    if (i < BB * HID) g_xg[i] = 0.f;
    if (i < 128)      g_biasY[i] = 0.f;
}

// ---------------- merged prep: fp16 conversions + attn-proj rows ----------------
#define PB_A 10000
#define PB_B 390
#define PB_E 20
#define PB_G 2535
__global__ void __launch_bounds__(256) k_prep(const float* __restrict__ x,
                                              const float* __restrict__ gat_W,
                                              const float* __restrict__ gcn_W,
                                              const float* __restrict__ aS,
                                              const float* __restrict__ aD) {
    int bid = blockIdx.x, t = threadIdx.x;
    if (bid < PB_A) {
        int i = bid * 256 + t;
        int m = i >> 7, k = i & 127;
        g_Axh[i] = __float2half_rn(k < FF ? x[(long)m * FF + k] : 0.f);
    } else if (bid < PB_A + PB_B) {
        int i = (bid - PB_A) * 256 + t;
        int n = i >> 7, k = i & 127;
        g_Bah[i] = __float2half_rn(k < FF ? gat_W[(long)k * HID + n] : 0.f);
    } else if (bid < PB_A + PB_B + PB_E) {
        int i = bid - (PB_A + PB_B);        // 0..19
        int k = t;                           // 0..127
        if (k >= 128) return;
        int h = i % 10;
        const float* av = ((i < 10) ? aS : aD) + h * FF;
        float s = 0.f;
        if (k < FF) {
            const float* wr = gat_W + (long)k * HID + h * FF;
#pragma unroll 13
            for (int f = 0; f < FF; f++) s += wr[f] * av[f];
        }
        g_Bah[(long)(HID + i) * KPA + k] = __float2half_rn(s);
    } else {
        int i = (bid - (PB_A + PB_B + PB_E)) * 256 + t;
        int n = i / KPG, k = i - n * KPG;
        g_Bgh[i] = __float2half_rn(k < HID ? gcn_W[(long)k * HID + n] : 0.f);
    }
}

// ============ fp16 tensor-core GEMM (optional fp32 aux columns) ============
#define KC 32
#define ASTR 40
#define HALF_BYTES (128 * ASTR * 2)
#define STAGE_BYTES (2 * HALF_BYTES)
#define GEMM_SMEM (2 * STAGE_BYTES)

__global__ void __launch_bounds__(256)
gemm_mma(const __half* __restrict__ Ah, const __half* __restrict__ Bh,
         __half* __restrict__ C, int M, int N, int Kp, int NC, int ldc,
         float* __restrict__ aux, int auxcol) {
    extern __shared__ char smem_raw[];
    uint32_t sb = smem_u32(smem_raw);
    int tid = threadIdx.x, w = tid >> 5, l = tid & 31;
    int m0 = blockIdx.y * 128, n0 = blockIdx.x * 128;
    int wm = w & 3, wn = w >> 2;

    float acc[2][8][4];
#pragma unroll
    for (int i = 0; i < 2; i++)
#pragma unroll
        for (int j = 0; j < 8; j++)
#pragma unroll
            for (int q = 0; q < 4; q++) acc[i][j][q] = 0.f;

    auto issue = [&](int c) {
        int k0 = c * KC;
        uint32_t st = sb + (uint32_t)(c & 1) * STAGE_BYTES;
#pragma unroll
        for (int p = 0; p < 2; p++) {
            int f = tid + p * 256;
            int row = f >> 2, c16 = f & 3;
            uint32_t doff = (uint32_t)(row * (ASTR * 2) + c16 * 16);
            int am = m0 + row;
            int amc = am < M ? am : M - 1;
            int av = am < M ? 16 : 0;
            cpasync16(st + doff, Ah + (long)amc * Kp + k0 + c16 * 8, av);
            int bn = n0 + row;
            int bnc = bn < N ? bn : N - 1;
            int bv = bn < N ? 16 : 0;
            cpasync16(st + HALF_BYTES + doff, Bh + (long)bnc * Kp + k0 + c16 * 8, bv);
        }
        asm volatile("cp.async.commit_group;" ::: "memory");
    };

    issue(0);
    for (int c = 0; c < NC; c++) {
        if (c + 1 < NC) {
            issue(c + 1);
            asm volatile("cp.async.wait_group 1;" ::: "memory");
        } else {
            asm volatile("cp.async.wait_group 0;" ::: "memory");
        }
        __syncthreads();
        uint32_t st = sb + (uint32_t)(c & 1) * STAGE_BYTES;
        int lrow = l & 15, lcb = l >> 4;
#pragma unroll
        for (int k16 = 0; k16 < 2; k16++) {
            uint32_t coff = (uint32_t)((k16 * 16 + lcb * 8) * 2);
            uint32_t bh[4][4];
#pragma unroll
            for (int nt2 = 0; nt2 < 4; nt2++) {
                uint32_t roff = (uint32_t)((wn * 64 + nt2 * 16 + lrow) * (ASTR * 2));
                ldm4(bh[nt2], st + HALF_BYTES + roff + coff);
            }
#pragma unroll
            for (int mt = 0; mt < 2; mt++) {
                uint32_t roff = (uint32_t)((wm * 32 + mt * 16 + lrow) * (ASTR * 2));
                uint32_t ah[4];
                ldm4(ah, st + roff + coff);
#pragma unroll
                for (int nt = 0; nt < 8; nt++) {
                    int nt2 = nt >> 1, sel = nt & 1;
                    mma16816h(acc[mt][nt], ah, bh[nt2][sel], bh[nt2][sel + 2]);
                }
            }
        }
        __syncthreads();
    }

#pragma unroll
    for (int mt = 0; mt < 2; mt++) {
#pragma unroll
        for (int nt = 0; nt < 8; nt++) {
            int row = m0 + wm * 32 + mt * 16 + (l >> 2);
            int col = n0 + wn * 64 + nt * 8 + 2 * (l & 3);
            if (col < N) {
                if (col >= auxcol) {
                    int ac = col - auxcol;
                    if (row < M) {
                        aux[row * 20 + ac]     = acc[mt][nt][0];
                        aux[row * 20 + ac + 1] = acc[mt][nt][1];
                    }
                    int row2 = row + 8;
                    if (row2 < M) {
                        aux[row2 * 20 + ac]     = acc[mt][nt][2];
                        aux[row2 * 20 + ac + 1] = acc[mt][nt][3];
                    }
                } else {
                    if (row < M)
                        *(__half2*)(C + (long)row * ldc + col) =
                            __floats2half2_rn(acc[mt][nt][0], acc[mt][nt][1]);
                    int row2 = row + 8;
                    if (row2 < M)
                        *(__half2*)(C + (long)row2 * ldc + col) =
                            __floats2half2_rn(acc[mt][nt][2], acc[mt][nt][3]);
                }
            }
        }
    }
}

// ---------------- latency-optimized skinny GEMM: C[M,N] = A[M,K] @ W[K,N] ----------------
// grid (ceil(N/64), M/8), 256 threads = 4 K-slices x 64 cols. M multiple of 8.
__global__ void __launch_bounds__(256)
mlp8(const float* __restrict__ A, const float* __restrict__ W,
     float* __restrict__ C, const float* __restrict__ bias,
     int M, int N, int K, int lda, int ldc, int coff, int relu) {
    __shared__ float sact[8 * 1504];
    int t = threadIdx.x;
    int j = t & 63, kc = t >> 6;
    int jg = blockIdx.x * 64 + j;
    int r0 = blockIdx.y * 8;

    for (int i = t; i < 8 * K; i += 256) {
        int r = i / K, k = i - r * K;
        int row = r0 + r;
        sact[i] = (row < M) ? A[(long)row * lda + k] : 0.f;
    }
    __syncthreads();

    float acc[8];
#pragma unroll
    for (int r = 0; r < 8; r++) acc[r] = 0.f;
    if (jg < N) {
        for (int k = kc; k < K; k += 4) {
            float wv = W[(long)k * N + jg];
            const float* ar = &sact[k];
#pragma unroll
            for (int r = 0; r < 8; r++) acc[r] += ar[r * K] * wv;
        }
    }
    __syncthreads();
    // reduce 4 kc partials via smem (reuse sact)
    float* red = sact;
#pragma unroll
    for (int r = 0; r < 8; r++) red[(j * 4 + kc) + r * 256] = acc[r];
    __syncthreads();
    if (kc == 0 && jg < N) {
        float b = bias ? bias[jg] : 0.f;
#pragma unroll
        for (int r = 0; r < 8; r++) {
            int row = r0 + r;
            if (row >= M) break;
            float v = red[j * 4 + r * 256] + red[j * 4 + 1 + r * 256]
                    + red[j * 4 + 2 + r * 256] + red[j * 4 + 3 + r * 256] + b;
            if (relu) v = fmaxf(v, 0.f);
            C[(long)row * ldc + coff + jg] = v;
        }
    }
}

// ---------------- CSR build (self-restoring counters) ----------------
__global__ void k_count(const int* __restrict__ edge) {
    int i = blockIdx.x * blockDim.x + threadIdx.x;
    if (i >= ET) return;
    int dst = (i < EE) ? edge[EE + i] : i - EE;
    atomicAdd(&g_cnt[dst], 1);
}
__global__ void k_scan() {
    __shared__ int part[256];
    int tid = threadIdx.x;
    const int chunk = (NN + 255) / 256;
    int lo = tid * chunk, hi = min(lo + chunk, NN);
    int s = 0;
    for (int n = lo; n < hi; n++) s += g_cnt[n];
    part[tid] = s;
    __syncthreads();
    if (tid == 0) {
        int r = 0;
        for (int i = 0; i < 256; i++) { int t = part[i]; part[i] = r; r += t; }
        g_off[NN] = r;
    }
    __syncthreads();
    int r = part[tid];
    for (int n = lo; n < hi; n++) {
        g_off[n] = r;
        int c = g_cnt[n];
        r += c;
        g_dinv[n] = rsqrtf((float)(c > 0 ? c : 1));
    }
}
__global__ void k_scatter(const int* __restrict__ edge) {
    int i = blockIdx.x * blockDim.x + threadIdx.x;
    if (i >= ET) return;
    int src = (i < EE) ? edge[i]      : i - EE;
    int dst = (i < EE) ? edge[EE + i] : i - EE;
    int old = atomicSub(&g_cnt[dst], 1);
    g_srcA[g_off[dst] + old - 1] = src;
}

// ---------------- fused softmax + GAT aggregation ----------------
__device__ __forceinline__ uint32_t fmapU(float f) {
    uint32_t u = __float_as_uint(f);
    return u ^ (uint32_t)(((int)u >> 31) | 0x80000000);
}
__device__ __forceinline__ float finvU(uint32_t u) {
    return (u & 0x80000000u) ? __uint_as_float(u ^ 0x80000000u) : __uint_as_float(~u);
}
__global__ void __launch_bounds__(256) k_gat_soft_agg(const float* __restrict__ gat_b) {
    __shared__ float sal[DMAX * HH];
    __shared__ int ssrc[DMAX];
    __shared__ uint32_t sm[HH];
    __shared__ float sden[HH], sad[HH];
    int n = blockIdx.x, t = threadIdx.x;
    int lo = g_off[n], d = g_off[n + 1] - lo;
    bool small = (d <= DMAX);
    float* ebuf = small ? sal : &g_e[(long)lo * HH];
    const int* sp = small ? ssrc : &g_srcA[lo];
    if (t < HH) { sm[t] = fmapU(-INFINITY); sden[t] = 0.f; sad[t] = g_asad[n * 20 + 10 + t]; }
    if (small)
        for (int i = t; i < d; i += 256) ssrc[i] = g_srcA[lo + i];
    __syncthreads();
    int tot = d * HH;
    for (int p = t; p < tot; p += 256) {
        int i = p / HH, h = p - i * HH;
        int src = sp[i];
        float e = g_asad[src * 20 + h] + sad[h];
        e = (e > 0.f) ? e : 0.2f * e;
        ebuf[p] = e;
        atomicMax(&sm[h], fmapU(e));
    }
    __syncthreads();
    for (int p = t; p < tot; p += 256) {
        int h = p % HH;
        float ex = expf(ebuf[p] - finvU(sm[h]));
        ebuf[p] = ex;
        atomicAdd(&sden[h], ex);
    }
    __syncthreads();
    if (t < HH) sden[t] = 1.f / sden[t];
    __syncthreads();
    for (int p = t; p < tot; p += 256) ebuf[p] *= sden[p % HH];
    __syncthreads();

    if (t >= 208) return;
    long base = (long)n * KPG + t * 4;
    if (t >= 195) {
        __half2 z = __floats2half2_rn(0.f, 0.f);
        *(__half2*)(g_Ag + base) = z;
        *(__half2*)(g_Ag + base + 2) = z;
        return;
    }
    int q = t * 4;
    int h0 = q / FF, h1 = (q + 1) / FF, h2 = (q + 2) / FF, h3 = (q + 3) / FF;
    float ax = 0.f, ay = 0.f, az = 0.f, aw = 0.f;
    for (int idx = 0; idx < d; idx++) {
        int s = sp[idx];
        uint2 u = *(const uint2*)(g_hH + (long)s * NEXT + q);
        float2 v01 = __half22float2(*(__half2*)&u.x);
        float2 v23 = __half22float2(*(__half2*)&u.y);
        const float* al = &ebuf[idx * HH];
        ax += v01.x * al[h0]; ay += v01.y * al[h1]; az += v23.x * al[h2]; aw += v23.y * al[h3];
    }
    float v0 = fmaxf(ax + gat_b[q + 0], 0.f);
    float v1 = fmaxf(ay + gat_b[q + 1], 0.f);
    float v2 = fmaxf(az + gat_b[q + 2], 0.f);
    float v3 = fmaxf(aw + gat_b[q + 3], 0.f);
    *(__half2*)(g_Ag + base)     = __floats2half2_rn(v0, v1);
    *(__half2*)(g_Ag + base + 2) = __floats2half2_rn(v2, v3);
}

// ---------------- fused GCN aggregation + bias/relu + pool ----------------
__global__ void __launch_bounds__(256) k_gcn_agg_pool(const float* __restrict__ gcn_b,
                                                      const int* __restrict__ batch) {
    int n = blockIdx.x, t = threadIdx.x;
    if (t >= 195) return;
    int b = batch[n];
    int q = t * 4;
    float dn = g_dinv[n];
    float ax = 0.f, ay = 0.f, az = 0.f, aw = 0.f;
    int lo = g_off[n], hi = g_off[n + 1];
    for (int idx = lo; idx < hi; idx++) {
        int s = g_srcA[idx];
        float norm = dn * g_dinv[s];
        uint2 u = *(const uint2*)(g_h2H + (long)s * HID + q);
        float2 v01 = __half22float2(*(__half2*)&u.x);
        float2 v23 = __half22float2(*(__half2*)&u.y);
        ax += v01.x * norm; ay += v01.y * norm; az += v23.x * norm; aw += v23.y * norm;
    }
    float* o = g_xg + (long)b * HID + q;
    atomicAdd(o + 0, fmaxf(ax + gcn_b[q + 0], 0.f));
    atomicAdd(o + 1, fmaxf(ay + gcn_b[q + 1], 0.f));
    atomicAdd(o + 2, fmaxf(az + gcn_b[q + 2], 0.f));
    atomicAdd(o + 3, fmaxf(aw + gcn_b[q + 3], 0.f));
}

// ---------------- protein branch ----------------
__global__ void k_Pbias(const float* __restrict__ emb, const float* __restrict__ cW,
                        const float* __restrict__ fxtW, const float* __restrict__ cb) {
    int bi = blockIdx.x, j = threadIdx.x;
    if (bi < 256) {
        int o = bi >> 3, c = bi & 7;
        int t0 = c * 125, t1 = min(t0 + 125, COUT);
        float p = 0.f;
        for (int t = t0; t < t1; t++)
            p += fxtW[((long)(o * COUT + t)) * 128 + j];
        atomicAdd(&g_biasY[j], cb[o] * p);
    } else {
        int g = (bi - 256) * 128 + j;
        if (g >= VOC * NF * KS) return;
        int v = g / (NF * KS), r = g % (NF * KS);
        int o = r / KS, k = r % KS;
        float s = 0.f;
#pragma unroll 16
        for (int e = 0; e < EMB; e++)
            s += emb[v * EMB + e] * cW[o * EMB * KS + e * KS + k];
        g_P[g] = s;
    }
}
__global__ void k_R(const float* __restrict__ fxtW) {
    __shared__ float Ps[VOC * NF * KS];
    int s = blockIdx.x, j = threadIdx.x;
    for (int idx = j; idx < VOC * NF * KS; idx += 128) Ps[idx] = g_P[idx];
    __syncthreads();
    float acc[VOC];
#pragma unroll
    for (int v = 0; v < VOC; v++) acc[v] = 0.f;
    int kmin = (s > COUT - 1) ? (s - (COUT - 1)) : 0;
    int kmax = (s < KS - 1) ? s : (KS - 1);
    for (int o = 0; o < NF; o++) {
        for (int k = kmin; k <= kmax; k++) {
            float w = fxtW[((long)(o * COUT + s - k)) * 128 + j];
#pragma unroll
            for (int v = 0; v < VOC; v++)
                acc[v] += Ps[v * (NF * KS) + o * KS + k] * w;
        }
    }
#pragma unroll
    for (int v = 0; v < VOC; v++)
        g_R[((long)v * SEQ + s) * 128 + j] = acc[v];
}
__global__ void k_Y(const int* __restrict__ target, const float* __restrict__ fxt_b) {
    __shared__ int sv[SEQ];
    int b = blockIdx.x, j = threadIdx.x;
    for (int i = j; i < SEQ; i += 128) sv[i] = target[b * SEQ + i];
    __syncthreads();
    float acc = g_biasY[j] + fxt_b[j];
    for (int s = 0; s < SEQ; s += 4) {
        float r0 = g_R[((long)sv[s]     * SEQ + s)     * 128 + j];
        float r1 = g_R[((long)sv[s + 1] * SEQ + s + 1) * 128 + j];
        float r2 = g_R[((long)sv[s + 2] * SEQ + s + 2) * 128 + j];
        float r3 = g_R[((long)sv[s + 3] * SEQ + s + 3) * 128 + j];
        acc += (r0 + r1) + (r2 + r3);
    }
    g_xc[b * 256 + 128 + j] = acc;
}

// ---------------- output ----------------
__global__ void k_out(const float* __restrict__ oW, const float* __restrict__ ob,
                      float* __restrict__ out) {
    __shared__ float red[4];
    int b = blockIdx.x, j = threadIdx.x;
    float v = g_t5[b * 128 + j] * oW[j];
#pragma unroll
    for (int off = 16; off; off >>= 1) v += __shfl_down_sync(0xffffffffu, v, off);
    if ((j & 31) == 0) red[j >> 5] = v;
    __syncthreads();
    if (j == 0) out[b] = red[0] + red[1] + red[2] + red[3] + ob[0];
}

// ---------------- host ----------------
static inline dim3 ggrid(long n, int t) { return dim3((unsigned)((n + t - 1) / t)); }

extern "C" void kernel_launch(void* const* d_in, const int* in_sizes, int n_in,
                              void* d_out, int out_size) {
    const float* x      = (const float*)d_in[0];
    const int*   edge   = (const int*)  d_in[1];
    const int*   batch  = (const int*)  d_in[2];
    const int*   target = (const int*)  d_in[3];
    const float* gat_W  = (const float*)d_in[4];
    const float* a_src  = (const float*)d_in[5];
    const float* a_dst  = (const float*)d_in[6];
    const float* gat_b  = (const float*)d_in[7];
    const float* gcn_W  = (const float*)d_in[8];
    const float* gcn_b  = (const float*)d_in[9];
    const float* fcg1_W = (const float*)d_in[10];
    const float* fcg1_b = (const float*)d_in[11];
    const float* fcg2_W = (const float*)d_in[12];
    const float* fcg2_b = (const float*)d_in[13];
    const float* emb    = (const float*)d_in[14];
    const float* cW     = (const float*)d_in[15];
    const float* cb     = (const float*)d_in[16];
    const float* fxt_W  = (const float*)d_in[17];
    const float* fxt_b  = (const float*)d_in[18];
    const float* f1_W   = (const float*)d_in[19];
    const float* f1_b   = (const float*)d_in[20];
    const float* f2_W   = (const float*)d_in[21];
    const float* f2_b   = (const float*)d_in[22];
    const float* f3_W   = (const float*)d_in[23];
    const float* f3_b   = (const float*)d_in[24];
    const float* f4_W   = (const float*)d_in[25];
    const float* f4_b   = (const float*)d_in[26];
    const float* o_W    = (const float*)d_in[27];
    const float* o_b    = (const float*)d_in[28];
    float* out = (float*)d_out;

    float *p_xg, *p_t1, *p_xc, *p_t2, *p_t3, *p_t4, *p_t5, *p_asad;
    __half *p_hH, *p_h2H, *p_Axh, *p_Bah, *p_Ag, *p_Bgh;
    cudaGetSymbolAddress((void**)&p_hH,  g_hH);
    cudaGetSymbolAddress((void**)&p_h2H, g_h2H);
    cudaGetSymbolAddress((void**)&p_asad, g_asad);
    cudaGetSymbolAddress((void**)&p_xg,  g_xg);
    cudaGetSymbolAddress((void**)&p_t1,  g_t1);
    cudaGetSymbolAddress((void**)&p_xc,  g_xc);
    cudaGetSymbolAddress((void**)&p_t2,  g_t2);
    cudaGetSymbolAddress((void**)&p_t3,  g_t3);
    cudaGetSymbolAddress((void**)&p_t4,  g_t4);
    cudaGetSymbolAddress((void**)&p_t5,  g_t5);
    cudaGetSymbolAddress((void**)&p_Axh, g_Axh);
    cudaGetSymbolAddress((void**)&p_Bah, g_Bah);
    cudaGetSymbolAddress((void**)&p_Ag,  g_Ag);
    cudaGetSymbolAddress((void**)&p_Bgh, g_Bgh);

    static cudaStream_t s1, s2;
    static cudaEvent_t eF, e0, e1, eI, e2;
    static int inited = 0;
    if (!inited) {
        cudaStreamCreateWithFlags(&s1, cudaStreamNonBlocking);
        cudaStreamCreateWithFlags(&s2, cudaStreamNonBlocking);
        cudaEventCreateWithFlags(&eF, cudaEventDisableTiming);
        cudaEventCreateWithFlags(&e0, cudaEventDisableTiming);
        cudaEventCreateWithFlags(&e1, cudaEventDisableTiming);
        cudaEventCreateWithFlags(&eI, cudaEventDisableTiming);
        cudaEventCreateWithFlags(&e2, cudaEventDisableTiming);
        cudaFuncSetAttribute(gemm_mma, cudaFuncAttributeMaxDynamicSharedMemorySize, GEMM_SMEM);
        inited = 1;
    }

    cudaEventRecord(eF, 0);
    cudaStreamWaitEvent(s1, eF, 0);
    cudaStreamWaitEvent(s2, eF, 0);

    // 1: merged prep (conversions + attn-proj rows) [main]
    k_prep<<<PB_A + PB_B + PB_E + PB_G, 256>>>(x, gat_W, gcn_W, a_src, a_dst);
    // 2-3: CSR count + scan [s1]
    k_count<<<ggrid(ET, 256), 256, 0, s1>>>(edge);
    k_scan<<<1, 256, 0, s1>>>();
    // 4: GAT GEMM (profiled slot) [main] — N=800 incl. attn cols -> aux fp32
    gemm_mma<<<dim3(7, 157), 256, GEMM_SMEM>>>(p_Axh, p_Bah, p_hH, NN, NEXT, KPA, KPA / KC, NEXT,
                                               p_asad, HID);
    // 5: scatter [s1]
    k_scatter<<<ggrid(ET, 256), 256, 0, s1>>>(edge);
    cudaEventRecord(e1, s1);
    // 6-9: init + protein branch [s2]
    k_init0<<<ggrid(BB * HID, 256), 256, 0, s2>>>();
    cudaEventRecord(eI, s2);
    k_Pbias<<<308, 128, 0, s2>>>(emb, cW, fxt_W, cb);
    k_R<<<SEQ, 128, 0, s2>>>(fxt_W);
    k_Y<<<BB, 128, 0, s2>>>(target, fxt_b);
    cudaEventRecord(e2, s2);
    // main: graph branch
    cudaStreamWaitEvent(0, e1, 0);
    k_gat_soft_agg<<<NN, 256>>>(gat_b);
    gemm_mma<<<dim3(7, 157), 256, GEMM_SMEM>>>(p_Ag, p_Bgh, p_h2H, NN, HID, KPG, KPG / KC, HID,
                                               nullptr, 1 << 30);
    cudaStreamWaitEvent(0, eI, 0);
    k_gcn_agg_pool<<<NN, 256>>>(gcn_b, batch);
    // head: latency-optimized skinny GEMMs
    mlp8<<<dim3(24, 25), 256>>>(p_xg, fcg1_W, p_t1, fcg1_b, BB, 1500, HID, HID, 1500, 0, 1);
    mlp8<<<dim3(2, 25), 256>>>(p_t1, fcg2_W, p_xc, fcg2_b, BB, 128, 1500, 1500, 256, 0, 0);
    cudaStreamWaitEvent(0, e2, 0);
    mlp8<<<dim3(16, 25), 256>>>(p_xc, f1_W, p_t2, f1_b, BB, 1024, 256, 256, 1024, 0, 1);
    mlp8<<<dim3(8, 25), 256>>>(p_t2, f2_W, p_t3, f2_b, BB, 512, 1024, 1024, 512, 0, 1);
    mlp8<<<dim3(4, 25), 256>>>(p_t3, f3_W, p_t4, f3_b, BB, 256, 512, 512, 256, 0, 1);
    mlp8<<<dim3(2, 25), 256>>>(p_t4, f4_W, p_t5, f4_b, BB, 128, 256, 256, 128, 0, 1);
    k_out<<<BB, 128>>>(o_W, o_b, out);
}

// round 9
// speedup vs baseline: 9.4255x; 1.0477x over previous
#include <cuda_runtime.h>
#include <cuda_fp16.h>
#include <math.h>
#include <stdint.h>

#define NN   20000
#define EE   400000
#define ET   (EE + NN)
#define HH   10
#define FF   78
#define HID  780
#define NEXT 800
#define BB   200
#define SEQ  1000
#define VOC  26
#define EMB  128
#define NF   32
#define KS   8
#define COUT 993
#define KPA  128
#define KPG  832
#define DMAX 256

// ---------------- scratch ----------------
__device__ __half g_hH [(long)NN * NEXT];
__device__ __half g_h2H[(long)NN * HID];
__device__ __half g_x2H[(long)NN * HID];      // relu'd GCN agg (fp16), pooled per segment
__device__ float g_asad[NN * 20];
__device__ float g_e  [(long)ET * HH];
__device__ float g_xg [BB * HID];
__device__ float g_t1 [BB * 1500];
__device__ float g_xc [BB * 256];
__device__ float g_t2 [BB * 1024];
__device__ float g_t3 [BB * 512];
__device__ float g_t4 [BB * 256];
__device__ float g_t5 [BB * 128];
__device__ float g_P  [VOC * NF * KS];
__device__ float g_R  [(long)VOC * SEQ * 128];
__device__ float g_biasY[128];
__device__ int   g_cnt[NN];        // invariant: zero at kernel_launch entry
__device__ int   g_off[NN + 1];
__device__ int   g_srcA[ET];
__device__ int   g_start[BB + 1];
__device__ float g_dinv[NN];
__device__ __half g_Axh[(long)NN * KPA];
__device__ __half g_Bah[(long)NEXT * KPA];
__device__ __half g_Ag [(long)NN * KPG];
__device__ __half g_Bgh[(long)HID * KPG];

// ---------------- helpers ----------------
__device__ __forceinline__ uint32_t smem_u32(const void* p) {
    uint32_t a;
    asm("{ .reg .u64 t; cvta.to.shared.u64 t, %1; cvt.u32.u64 %0, t; }" : "=r"(a) : "l"(p));
    return a;
}
__device__ __forceinline__ void cpasync16(uint32_t dst, const void* src, int nbytes) {
    asm volatile("cp.async.cg.shared.global [%0], [%1], 16, %2;"
                 :: "r"(dst), "l"(__cvta_generic_to_global(src)), "r"(nbytes) : "memory");
}
__device__ __forceinline__ void ldm4(uint32_t* r, uint32_t addr) {
    asm volatile("ldmatrix.sync.aligned.m8n8.x4.shared.b16 {%0,%1,%2,%3}, [%4];"
                 : "=r"(r[0]), "=r"(r[1]), "=r"(r[2]), "=r"(r[3]) : "r"(addr));
}
__device__ __forceinline__ void mma16816h(float* c, const uint32_t* a, uint32_t b0, uint32_t b1) {
    asm volatile("mma.sync.aligned.m16n8k16.row.col.f32.f16.f16.f32 "
                 "{%0,%1,%2,%3}, {%4,%5,%6,%7}, {%8,%9}, {%0,%1,%2,%3};"
                 : "+f"(c[0]), "+f"(c[1]), "+f"(c[2]), "+f"(c[3])
                 : "r"(a[0]), "r"(a[1]), "r"(a[2]), "r"(a[3]), "r"(b0), "r"(b1));
}

// ---------------- tiny init: biasY only ----------------
__global__ void k_init0() {
    g_biasY[threadIdx.x] = 0.f;
}

// ---------------- merged prep ----------------
#define PB_A 10000
#define PB_B 390
#define PB_E 20
#define PB_G 2535
__global__ void __launch_bounds__(256) k_prep(const float* __restrict__ x,
                                              const float* __restrict__ gat_W,
                                              const float* __restrict__ gcn_W,
                                              const float* __restrict__ aS,
                                              const float* __restrict__ aD) {
    int bid = blockIdx.x, t = threadIdx.x;
    if (bid < PB_A) {
        int i = bid * 256 + t;
        int m = i >> 7, k = i & 127;
        g_Axh[i] = __float2half_rn(k < FF ? x[(long)m * FF + k] : 0.f);
    } else if (bid < PB_A + PB_B) {
        int i = (bid - PB_A) * 256 + t;
        int n = i >> 7, k = i & 127;
        g_Bah[i] = __float2half_rn(k < FF ? gat_W[(long)k * HID + n] : 0.f);
    } else if (bid < PB_A + PB_B + PB_E) {
        int i = bid - (PB_A + PB_B);
        int k = t;
        if (k >= 128) return;
        int h = i % 10;
        const float* av = ((i < 10) ? aS : aD) + h * FF;
        float s = 0.f;
        if (k < FF) {
            const float* wr = gat_W + (long)k * HID + h * FF;
#pragma unroll 13
            for (int f = 0; f < FF; f++) s += wr[f] * av[f];
        }
        g_Bah[(long)(HID + i) * KPA + k] = __float2half_rn(s);
    } else {
        int i = (bid - (PB_A + PB_B + PB_E)) * 256 + t;
        int n = i / KPG, k = i - n * KPG;
        g_Bgh[i] = __float2half_rn(k < HID ? gcn_W[(long)k * HID + n] : 0.f);
    }
}

// ============ fp16 tensor-core GEMM, 3-stage cp.async pipeline ============
#define KC 32
#define ASTR 40
#define HALF_BYTES (128 * ASTR * 2)
#define STAGE_BYTES (2 * HALF_BYTES)
#define GEMM_SMEM (3 * STAGE_BYTES)       // 61440

__global__ void __launch_bounds__(256)
gemm_mma(const __half* __restrict__ Ah, const __half* __restrict__ Bh,
         __half* __restrict__ C, int M, int N, int Kp, int NC, int ldc,
         float* __restrict__ aux, int auxcol) {
    extern __shared__ char smem_raw[];
    uint32_t sb = smem_u32(smem_raw);
    int tid = threadIdx.x, w = tid >> 5, l = tid & 31;
    int m0 = blockIdx.y * 128, n0 = blockIdx.x * 128;
    int wm = w & 3, wn = w >> 2;

    float acc[2][8][4];
#pragma unroll
    for (int i = 0; i < 2; i++)
#pragma unroll
        for (int j = 0; j < 8; j++)
#pragma unroll
            for (int q = 0; q < 4; q++) acc[i][j][q] = 0.f;

    auto issue = [&](int c) {
        int k0 = c * KC;
        uint32_t st = sb + (uint32_t)(c % 3) * STAGE_BYTES;
#pragma unroll
        for (int p = 0; p < 2; p++) {
            int f = tid + p * 256;
            int row = f >> 2, c16 = f & 3;
            uint32_t doff = (uint32_t)(row * (ASTR * 2) + c16 * 16);
            int am = m0 + row;
            int amc = am < M ? am : M - 1;
            int av = am < M ? 16 : 0;
            cpasync16(st + doff, Ah + (long)amc * Kp + k0 + c16 * 8, av);
            int bn = n0 + row;
            int bnc = bn < N ? bn : N - 1;
            int bv = bn < N ? 16 : 0;
            cpasync16(st + HALF_BYTES + doff, Bh + (long)bnc * Kp + k0 + c16 * 8, bv);
        }
        asm volatile("cp.async.commit_group;" ::: "memory");
    };

    issue(0);
    if (NC > 1) issue(1);
    for (int c = 0; c < NC; c++) {
        if (c + 1 < NC) asm volatile("cp.async.wait_group 1;" ::: "memory");
        else            asm volatile("cp.async.wait_group 0;" ::: "memory");
        __syncthreads();
        if (c + 2 < NC) issue(c + 2);
        uint32_t st = sb + (uint32_t)(c % 3) * STAGE_BYTES;
        int lrow = l & 15, lcb = l >> 4;
#pragma unroll
        for (int k16 = 0; k16 < 2; k16++) {
            uint32_t coff = (uint32_t)((k16 * 16 + lcb * 8) * 2);
            uint32_t bh[4][4];
#pragma unroll
            for (int nt2 = 0; nt2 < 4; nt2++) {
                uint32_t roff = (uint32_t)((wn * 64 + nt2 * 16 + lrow) * (ASTR * 2));
                ldm4(bh[nt2], st + HALF_BYTES + roff + coff);
            }
#pragma unroll
            for (int mt = 0; mt < 2; mt++) {
                uint32_t roff = (uint32_t)((wm * 32 + mt * 16 + lrow) * (ASTR * 2));
                uint32_t ah[4];
                ldm4(ah, st + roff + coff);
#pragma unroll
                for (int nt = 0; nt < 8; nt++) {
                    int nt2 = nt >> 1, sel = nt & 1;
                    mma16816h(acc[mt][nt], ah, bh[nt2][sel], bh[nt2][sel + 2]);
                }
            }
        }
    }

#pragma unroll
    for (int mt = 0; mt < 2; mt++) {
#pragma unroll
        for (int nt = 0; nt < 8; nt++) {
            int row = m0 + wm * 32 + mt * 16 + (l >> 2);
            int col = n0 + wn * 64 + nt * 8 + 2 * (l & 3);
            if (col < N) {
                if (col >= auxcol) {
                    int ac = col - auxcol;
                    if (row < M) {
                        aux[row * 20 + ac]     = acc[mt][nt][0];
                        aux[row * 20 + ac + 1] = acc[mt][nt][1];
                    }
                    int row2 = row + 8;
                    if (row2 < M) {
                        aux[row2 * 20 + ac]     = acc[mt][nt][2];
                        aux[row2 * 20 + ac + 1] = acc[mt][nt][3];
                    }
                } else {
                    if (row < M)
                        *(__half2*)(C + (long)row * ldc + col) =
                            __floats2half2_rn(acc[mt][nt][0], acc[mt][nt][1]);
                    int row2 = row + 8;
                    if (row2 < M)
                        *(__half2*)(C + (long)row2 * ldc + col) =
                            __floats2half2_rn(acc[mt][nt][2], acc[mt][nt][3]);
                }
            }
        }
    }
}

// ---------------- latency-optimized skinny GEMM ----------------
__global__ void __launch_bounds__(256)
mlp8(const float* __restrict__ A, const float* __restrict__ W,
     float* __restrict__ C, const float* __restrict__ bias,
     int M, int N, int K, int lda, int ldc, int coff, int relu) {
    __shared__ float sact[8 * 1504];
    int t = threadIdx.x;
    int j = t & 63, kc = t >> 6;
    int jg = blockIdx.x * 64 + j;
    int r0 = blockIdx.y * 8;

    for (int i = t; i < 8 * K; i += 256) {
        int r = i / K, k = i - r * K;
        int row = r0 + r;
        sact[i] = (row < M) ? A[(long)row * lda + k] : 0.f;
    }
    __syncthreads();

    float acc[8];
#pragma unroll
    for (int r = 0; r < 8; r++) acc[r] = 0.f;
    if (jg < N) {
        for (int k = kc; k < K; k += 4) {
            float wv = W[(long)k * N + jg];
            const float* ar = &sact[k];
#pragma unroll
            for (int r = 0; r < 8; r++) acc[r] += ar[r * K] * wv;
        }
    }
    __syncthreads();
    float* red = sact;
#pragma unroll
    for (int r = 0; r < 8; r++) red[(j * 4 + kc) + r * 256] = acc[r];
    __syncthreads();
    if (kc == 0 && jg < N) {
        float b = bias ? bias[jg] : 0.f;
#pragma unroll
        for (int r = 0; r < 8; r++) {
            int row = r0 + r;
            if (row >= M) break;
            float v = red[j * 4 + r * 256] + red[j * 4 + 1 + r * 256]
                    + red[j * 4 + 2 + r * 256] + red[j * 4 + 3 + r * 256] + b;
            if (relu) v = fmaxf(v, 0.f);
            C[(long)row * ldc + coff + jg] = v;
        }
    }
}

// ---------------- CSR build ----------------
__global__ void k_count(const int* __restrict__ edge) {
    int i = blockIdx.x * blockDim.x + threadIdx.x;
    if (i >= ET) return;
    int dst = (i < EE) ? edge[EE + i] : i - EE;
    atomicAdd(&g_cnt[dst], 1);
}
__global__ void k_scan() {
    __shared__ int part[256];
    int tid = threadIdx.x;
    const int chunk = (NN + 255) / 256;
    int lo = tid * chunk, hi = min(lo + chunk, NN);
    int s = 0;
    for (int n = lo; n < hi; n++) s += g_cnt[n];
    part[tid] = s;
    __syncthreads();
    if (tid == 0) {
        int r = 0;
        for (int i = 0; i < 256; i++) { int t = part[i]; part[i] = r; r += t; }
        g_off[NN] = r;
    }
    __syncthreads();
    int r = part[tid];
    for (int n = lo; n < hi; n++) {
        g_off[n] = r;
        int c = g_cnt[n];
        r += c;
        g_dinv[n] = rsqrtf((float)(c > 0 ? c : 1));
    }
}
__global__ void k_scatter(const int* __restrict__ edge) {
    int i = blockIdx.x * blockDim.x + threadIdx.x;
    if (i >= ET) return;
    int src = (i < EE) ? edge[i]      : i - EE;
    int dst = (i < EE) ? edge[EE + i] : i - EE;
    int old = atomicSub(&g_cnt[dst], 1);
    g_srcA[g_off[dst] + old - 1] = src;
}
// segment boundaries from sorted batch
__global__ void k_startB(const int* __restrict__ batch) {
    int n = blockIdx.x * blockDim.x + threadIdx.x;
    if (n >= NN) return;
    int b = batch[n];
    if (n == 0) {
        for (int bb = 0; bb <= b; bb++) g_start[bb] = 0;
    } else {
        int pb = batch[n - 1];
        if (pb != b) for (int bb = pb + 1; bb <= b; bb++) g_start[bb] = n;
    }
    if (n == NN - 1) {
        for (int bb = b + 1; bb <= BB; bb++) g_start[bb] = NN;
    }
}

// ---------------- fused softmax + GAT aggregation ----------------
__device__ __forceinline__ uint32_t fmapU(float f) {
    uint32_t u = __float_as_uint(f);
    return u ^ (uint32_t)(((int)u >> 31) | 0x80000000);
}
__device__ __forceinline__ float finvU(uint32_t u) {
    return (u & 0x80000000u) ? __uint_as_float(u ^ 0x80000000u) : __uint_as_float(~u);
}
__global__ void __launch_bounds__(256) k_gat_soft_agg(const float* __restrict__ gat_b) {
    __shared__ float sal[DMAX * HH];
    __shared__ int ssrc[DMAX];
    __shared__ uint32_t sm[HH];
    __shared__ float sden[HH], sad[HH];
    int n = blockIdx.x, t = threadIdx.x;
    int lo = g_off[n], d = g_off[n + 1] - lo;
    bool small = (d <= DMAX);
    float* ebuf = small ? sal : &g_e[(long)lo * HH];
    const int* sp = small ? ssrc : &g_srcA[lo];
    if (t < HH) { sm[t] = fmapU(-INFINITY); sden[t] = 0.f; sad[t] = g_asad[n * 20 + 10 + t]; }
    if (small)
        for (int i = t; i < d; i += 256) ssrc[i] = g_srcA[lo + i];
    __syncthreads();
    int tot = d * HH;
    for (int p = t; p < tot; p += 256) {
        int i = p / HH, h = p - i * HH;
        int src = sp[i];
        float e = g_asad[src * 20 + h] + sad[h];
        e = (e > 0.f) ? e : 0.2f * e;
        ebuf[p] = e;
        atomicMax(&sm[h], fmapU(e));
    }
    __syncthreads();
    for (int p = t; p < tot; p += 256) {
        int h = p % HH;
        float ex = expf(ebuf[p] - finvU(sm[h]));
        ebuf[p] = ex;
        atomicAdd(&sden[h], ex);
    }
    __syncthreads();
    if (t < HH) sden[t] = 1.f / sden[t];
    __syncthreads();
    for (int p = t; p < tot; p += 256) ebuf[p] *= sden[p % HH];
    __syncthreads();

    if (t >= 208) return;
    long base = (long)n * KPG + t * 4;
    if (t >= 195) {
        __half2 z = __floats2half2_rn(0.f, 0.f);
        *(__half2*)(g_Ag + base) = z;
        *(__half2*)(g_Ag + base + 2) = z;
        return;
    }
    int q = t * 4;
    int h0 = q / FF, h1 = (q + 1) / FF, h2 = (q + 2) / FF, h3 = (q + 3) / FF;
    float ax = 0.f, ay = 0.f, az = 0.f, aw = 0.f;
    for (int idx = 0; idx < d; idx++) {
        int s = sp[idx];
        uint2 u = *(const uint2*)(g_hH + (long)s * NEXT + q);
        float2 v01 = __half22float2(*(__half2*)&u.x);
        float2 v23 = __half22float2(*(__half2*)&u.y);
        const float* al = &ebuf[idx * HH];
        ax += v01.x * al[h0]; ay += v01.y * al[h1]; az += v23.x * al[h2]; aw += v23.y * al[h3];
    }
    float v0 = fmaxf(ax + gat_b[q + 0], 0.f);
    float v1 = fmaxf(ay + gat_b[q + 1], 0.f);
    float v2 = fmaxf(az + gat_b[q + 2], 0.f);
    float v3 = fmaxf(aw + gat_b[q + 3], 0.f);
    *(__half2*)(g_Ag + base)     = __floats2half2_rn(v0, v1);
    *(__half2*)(g_Ag + base + 2) = __floats2half2_rn(v2, v3);
}

// ---------------- GCN aggregation: relu'd fp16 out, no atomics ----------------
__global__ void __launch_bounds__(256) k_gcn_agg(const float* __restrict__ gcn_b) {
    int n = blockIdx.x, t = threadIdx.x;
    if (t >= 195) return;
    int q = t * 4;
    float dn = g_dinv[n];
    float ax = 0.f, ay = 0.f, az = 0.f, aw = 0.f;
    int lo = g_off[n], hi = g_off[n + 1];
    for (int idx = lo; idx < hi; idx++) {
        int s = g_srcA[idx];
        float norm = dn * g_dinv[s];
        uint2 u = *(const uint2*)(g_h2H + (long)s * HID + q);
        float2 v01 = __half22float2(*(__half2*)&u.x);
        float2 v23 = __half22float2(*(__half2*)&u.y);
        ax += v01.x * norm; ay += v01.y * norm; az += v23.x * norm; aw += v23.y * norm;
    }
    float v0 = fmaxf(ax + gcn_b[q + 0], 0.f);
    float v1 = fmaxf(ay + gcn_b[q + 1], 0.f);
    float v2 = fmaxf(az + gcn_b[q + 2], 0.f);
    float v3 = fmaxf(aw + gcn_b[q + 3], 0.f);
    *(__half2*)(g_x2H + (long)n * HID + q)     = __floats2half2_rn(v0, v1);
    *(__half2*)(g_x2H + (long)n * HID + q + 2) = __floats2half2_rn(v2, v3);
}

// ---------------- segment pool (no atomics) ----------------
__global__ void __launch_bounds__(256) k_pool() {
    int b = blockIdx.x, t = threadIdx.x;
    if (t >= 195) return;
    int q = t * 4;
    int lo = g_start[b], hi = g_start[b + 1];
    float ax = 0.f, ay = 0.f, az = 0.f, aw = 0.f;
    for (int n = lo; n < hi; n++) {
        uint2 u = *(const uint2*)(g_x2H + (long)n * HID + q);
        float2 v01 = __half22float2(*(__half2*)&u.x);
        float2 v23 = __half22float2(*(__half2*)&u.y);
        ax += v01.x; ay += v01.y; az += v23.x; aw += v23.y;
    }
    float* o = g_xg + (long)b * HID + q;
    o[0] = ax; o[1] = ay; o[2] = az; o[3] = aw;
}

// ---------------- protein branch ----------------
__global__ void k_Pbias(const float* __restrict__ emb, const float* __restrict__ cW,
                        const float* __restrict__ fxtW, const float* __restrict__ cb) {
    int bi = blockIdx.x, j = threadIdx.x;
    if (bi < 256) {
        int o = bi >> 3, c = bi & 7;
        int t0 = c * 125, t1 = min(t0 + 125, COUT);
        float p = 0.f;
        for (int t = t0; t < t1; t++)
            p += fxtW[((long)(o * COUT + t)) * 128 + j];
        atomicAdd(&g_biasY[j], cb[o] * p);
    } else {
        int g = (bi - 256) * 128 + j;
        if (g >= VOC * NF * KS) return;
        int v = g / (NF * KS), r = g % (NF * KS);
        int o = r / KS, k = r % KS;
        float s = 0.f;
#pragma unroll 16
        for (int e = 0; e < EMB; e++)
            s += emb[v * EMB + e] * cW[o * EMB * KS + e * KS + k];
        g_P[g] = s;
    }
}
__global__ void k_R(const float* __restrict__ fxtW) {
    __shared__ float Ps[VOC * NF * KS];
    int s = blockIdx.x, j = threadIdx.x;
    for (int idx = j; idx < VOC * NF * KS; idx += 128) Ps[idx] = g_P[idx];
    __syncthreads();
    float acc[VOC];
#pragma unroll
    for (int v = 0; v < VOC; v++) acc[v] = 0.f;
    int kmin = (s > COUT - 1) ? (s - (COUT - 1)) : 0;
    int kmax = (s < KS - 1) ? s : (KS - 1);
    for (int o = 0; o < NF; o++) {
        for (int k = kmin; k <= kmax; k++) {
            float w = fxtW[((long)(o * COUT + s - k)) * 128 + j];
#pragma unroll
            for (int v = 0; v < VOC; v++)
                acc[v] += Ps[v * (NF * KS) + o * KS + k] * w;
        }
    }
#pragma unroll
    for (int v = 0; v < VOC; v++)
        g_R[((long)v * SEQ + s) * 128 + j] = acc[v];
}
__global__ void k_Y(const int* __restrict__ target, const float* __restrict__ fxt_b) {
    __shared__ int sv[SEQ];
    int b = blockIdx.x, j = threadIdx.x;
    for (int i = j; i < SEQ; i += 128) sv[i] = target[b * SEQ + i];
    __syncthreads();
    float acc = g_biasY[j] + fxt_b[j];
    for (int s = 0; s < SEQ; s += 4) {
        float r0 = g_R[((long)sv[s]     * SEQ + s)     * 128 + j];
        float r1 = g_R[((long)sv[s + 1] * SEQ + s + 1) * 128 + j];
        float r2 = g_R[((long)sv[s + 2] * SEQ + s + 2) * 128 + j];
        float r3 = g_R[((long)sv[s + 3] * SEQ + s + 3) * 128 + j];
        acc += (r0 + r1) + (r2 + r3);
    }
    g_xc[b * 256 + 128 + j] = acc;
}

// ---------------- output ----------------
__global__ void k_out(const float* __restrict__ oW, const float* __restrict__ ob,
                      float* __restrict__ out) {
    __shared__ float red[4];
    int b = blockIdx.x, j = threadIdx.x;
    float v = g_t5[b * 128 + j] * oW[j];
#pragma unroll
    for (int off = 16; off; off >>= 1) v += __shfl_down_sync(0xffffffffu, v, off);
    if ((j & 31) == 0) red[j >> 5] = v;
    __syncthreads();
    if (j == 0) out[b] = red[0] + red[1] + red[2] + red[3] + ob[0];
}

// ---------------- host ----------------
static inline dim3 ggrid(long n, int t) { return dim3((unsigned)((n + t - 1) / t)); }

extern "C" void kernel_launch(void* const* d_in, const int* in_sizes, int n_in,
                              void* d_out, int out_size) {
    const float* x      = (const float*)d_in[0];
    const int*   edge   = (const int*)  d_in[1];
    const int*   batch  = (const int*)  d_in[2];
    const int*   target = (const int*)  d_in[3];
    const float* gat_W  = (const float*)d_in[4];
    const float* a_src  = (const float*)d_in[5];
    const float* a_dst  = (const float*)d_in[6];
    const float* gat_b  = (const float*)d_in[7];
    const float* gcn_W  = (const float*)d_in[8];
    const float* gcn_b  = (const float*)d_in[9];
    const float* fcg1_W = (const float*)d_in[10];
    const float* fcg1_b = (const float*)d_in[11];
    const float* fcg2_W = (const float*)d_in[12];
    const float* fcg2_b = (const float*)d_in[13];
    const float* emb    = (const float*)d_in[14];
    const float* cW     = (const float*)d_in[15];
    const float* cb     = (const float*)d_in[16];
    const float* fxt_W  = (const float*)d_in[17];
    const float* fxt_b  = (const float*)d_in[18];
    const float* f1_W   = (const float*)d_in[19];
    const float* f1_b   = (const float*)d_in[20];
    const float* f2_W   = (const float*)d_in[21];
    const float* f2_b   = (const float*)d_in[22];
    const float* f3_W   = (const float*)d_in[23];
    const float* f3_b   = (const float*)d_in[24];
    const float* f4_W   = (const float*)d_in[25];
    const float* f4_b   = (const float*)d_in[26];
    const float* o_W    = (const float*)d_in[27];
    const float* o_b    = (const float*)d_in[28];
    float* out = (float*)d_out;

    float *p_xg, *p_t1, *p_xc, *p_t2, *p_t3, *p_t4, *p_t5, *p_asad;
    __half *p_hH, *p_h2H, *p_Axh, *p_Bah, *p_Ag, *p_Bgh;
    cudaGetSymbolAddress((void**)&p_hH,  g_hH);
    cudaGetSymbolAddress((void**)&p_h2H, g_h2H);
    cudaGetSymbolAddress((void**)&p_asad, g_asad);
    cudaGetSymbolAddress((void**)&p_xg,  g_xg);
    cudaGetSymbolAddress((void**)&p_t1,  g_t1);
    cudaGetSymbolAddress((void**)&p_xc,  g_xc);
    cudaGetSymbolAddress((void**)&p_t2,  g_t2);
    cudaGetSymbolAddress((void**)&p_t3,  g_t3);
    cudaGetSymbolAddress((void**)&p_t4,  g_t4);
    cudaGetSymbolAddress((void**)&p_t5,  g_t5);
    cudaGetSymbolAddress((void**)&p_Axh, g_Axh);
    cudaGetSymbolAddress((void**)&p_Bah, g_Bah);
    cudaGetSymbolAddress((void**)&p_Ag,  g_Ag);
    cudaGetSymbolAddress((void**)&p_Bgh, g_Bgh);

    static cudaStream_t s1, s2;
    static cudaEvent_t eF, e1, e2;
    static int inited = 0;
    if (!inited) {
        cudaStreamCreateWithFlags(&s1, cudaStreamNonBlocking);
        cudaStreamCreateWithFlags(&s2, cudaStreamNonBlocking);
        cudaEventCreateWithFlags(&eF, cudaEventDisableTiming);
        cudaEventCreateWithFlags(&e1, cudaEventDisableTiming);
        cudaEventCreateWithFlags(&e2, cudaEventDisableTiming);
        cudaFuncSetAttribute(gemm_mma, cudaFuncAttributeMaxDynamicSharedMemorySize, GEMM_SMEM);
        inited = 1;
    }

    cudaEventRecord(eF, 0);
    cudaStreamWaitEvent(s1, eF, 0);
    cudaStreamWaitEvent(s2, eF, 0);

    // main: merged prep
    k_prep<<<PB_A + PB_B + PB_E + PB_G, 256>>>(x, gat_W, gcn_W, a_src, a_dst);
    // s1: CSR + segment boundaries
    k_count<<<ggrid(ET, 256), 256, 0, s1>>>(edge);
    k_startB<<<ggrid(NN, 256), 256, 0, s1>>>(batch);
    k_scan<<<1, 256, 0, s1>>>();
    // main: GAT GEMM (N=800 incl. attn cols)
    gemm_mma<<<dim3(7, 157), 256, GEMM_SMEM>>>(p_Axh, p_Bah, p_hH, NN, NEXT, KPA, KPA / KC, NEXT,
                                               p_asad, HID);
    // s1: scatter
    k_scatter<<<ggrid(ET, 256), 256, 0, s1>>>(edge);
    cudaEventRecord(e1, s1);
    // s2: protein branch
    k_init0<<<1, 128, 0, s2>>>();
    k_Pbias<<<308, 128, 0, s2>>>(emb, cW, fxt_W, cb);
    k_R<<<SEQ, 128, 0, s2>>>(fxt_W);
    k_Y<<<BB, 128, 0, s2>>>(target, fxt_b);
    cudaEventRecord(e2, s2);
    // main: graph branch
    cudaStreamWaitEvent(0, e1, 0);
    k_gat_soft_agg<<<NN, 256>>>(gat_b);
    gemm_mma<<<dim3(7, 157), 256, GEMM_SMEM>>>(p_Ag, p_Bgh, p_h2H, NN, HID, KPG, KPG / KC, HID,
                                               nullptr, 1 << 30);
    k_gcn_agg<<<NN, 256>>>(gcn_b);
    k_pool<<<BB, 256>>>();
    // head
    mlp8<<<dim3(24, 25), 256>>>(p_xg, fcg1_W, p_t1, fcg1_b, BB, 1500, HID, HID, 1500, 0, 1);
    mlp8<<<dim3(2, 25), 256>>>(p_t1, fcg2_W, p_xc, fcg2_b, BB, 128, 1500, 1500, 256, 0, 0);
    cudaStreamWaitEvent(0, e2, 0);
    mlp8<<<dim3(16, 25), 256>>>(p_xc, f1_W, p_t2, f1_b, BB, 1024, 256, 256, 1024, 0, 1);
    mlp8<<<dim3(8, 25), 256>>>(p_t2, f2_W, p_t3, f2_b, BB, 512, 1024, 1024, 512, 0, 1);
    mlp8<<<dim3(4, 25), 256>>>(p_t3, f3_W, p_t4, f3_b, BB, 256, 512, 512, 256, 0, 1);
    mlp8<<<dim3(2, 25), 256>>>(p_t4, f4_W, p_t5, f4_b, BB, 128, 256, 256, 128, 0, 1);
    k_out<<<BB, 128>>>(o_W, o_b, out);
}

// round 10
// speedup vs baseline: 9.4265x; 1.0001x over previous
#include <cuda_runtime.h>
#include <cuda_fp16.h>
#include <math.h>
#include <stdint.h>

#define NN   20000
#define EE   400000
#define ET   (EE + NN)
#define HH   10
#define FF   78
#define HID  780
#define NEXT 800
#define BB   200
#define SEQ  1000
#define VOC  26
#define EMB  128
#define NF   32
#define KS   8
#define COUT 993
#define KPA  128
#define KPG  832
#define DMAX 256
#define NB   79        // scan blocks: ceil(NN/256)

// ---------------- scratch ----------------
__device__ __half g_hH [(long)NN * NEXT];
__device__ __half g_h2H[(long)NN * HID];
__device__ __half g_x2H[(long)NN * HID];
__device__ float g_asad[NN * 20];
__device__ float g_e  [(long)ET * HH];
__device__ float g_xg [BB * HID];
__device__ float g_t1 [BB * 1500];
__device__ float g_xc [BB * 256];
__device__ float g_t2 [BB * 1024];
__device__ float g_t3 [BB * 512];
__device__ float g_t4 [BB * 256];
__device__ float g_t5 [BB * 128];
__device__ float g_P  [VOC * NF * KS];
__device__ float g_R  [(long)VOC * SEQ * 128];
__device__ float g_biasY[128];
__device__ int   g_cnt[NN];        // invariant: zero at kernel_launch entry
__device__ int   g_off[NN + 1];
__device__ int   g_bsum[NB];
__device__ int   g_bpre[NB];
__device__ int   g_srcA[ET];
__device__ int   g_start[BB + 1];
__device__ float g_dinv[NN];
__device__ __half g_Axh[(long)NN * KPA];
__device__ __half g_Bah[(long)NEXT * KPA];
__device__ __half g_Ag [(long)NN * KPG];
__device__ __half g_Bgh[(long)HID * KPG];

// ---------------- helpers ----------------
__device__ __forceinline__ uint32_t smem_u32(const void* p) {
    uint32_t a;
    asm("{ .reg .u64 t; cvta.to.shared.u64 t, %1; cvt.u32.u64 %0, t; }" : "=r"(a) : "l"(p));
    return a;
}
__device__ __forceinline__ void cpasync16(uint32_t dst, const void* src, int nbytes) {
    asm volatile("cp.async.cg.shared.global [%0], [%1], 16, %2;"
                 :: "r"(dst), "l"(__cvta_generic_to_global(src)), "r"(nbytes) : "memory");
}
__device__ __forceinline__ void ldm4(uint32_t* r, uint32_t addr) {
    asm volatile("ldmatrix.sync.aligned.m8n8.x4.shared.b16 {%0,%1,%2,%3}, [%4];"
                 : "=r"(r[0]), "=r"(r[1]), "=r"(r[2]), "=r"(r[3]) : "r"(addr));
}
__device__ __forceinline__ void mma16816h(float* c, const uint32_t* a, uint32_t b0, uint32_t b1) {
    asm volatile("mma.sync.aligned.m16n8k16.row.col.f32.f16.f16.f32 "
                 "{%0,%1,%2,%3}, {%4,%5,%6,%7}, {%8,%9}, {%0,%1,%2,%3};"
                 : "+f"(c[0]), "+f"(c[1]), "+f"(c[2]), "+f"(c[3])
                 : "r"(a[0]), "r"(a[1]), "r"(a[2]), "r"(a[3]), "r"(b0), "r"(b1));
}

// ---------------- tiny init ----------------
__global__ void k_init0() {
    g_biasY[threadIdx.x] = 0.f;
}

// ---------------- prep: A fp16 convert + attn projection rows ----------------
#define PB_A 10000
#define PB_E 20
__global__ void __launch_bounds__(256) k_prep(const float* __restrict__ x,
                                              const float* __restrict__ gat_W,
                                              const float* __restrict__ aS,
                                              const float* __restrict__ aD) {
    int bid = blockIdx.x, t = threadIdx.x;
    if (bid < PB_A) {
        int i = bid * 256 + t;
        int m = i >> 7, k = i & 127;
        g_Axh[i] = __float2half_rn(k < FF ? x[(long)m * FF + k] : 0.f);
    } else {
        int i = bid - PB_A;          // 0..19
        int k = t;
        if (k >= 128) return;
        int h = i % 10;
        const float* av = ((i < 10) ? aS : aD) + h * FF;
        float s = 0.f;
        if (k < FF) {
            const float* wr = gat_W + (long)k * HID + h * FF;
#pragma unroll 13
            for (int f = 0; f < FF; f++) s += wr[f] * av[f];
        }
        g_Bah[(long)(HID + i) * KPA + k] = __float2half_rn(s);
    }
}

// ---------------- coalesced transpose-convert: dst[n*Kp+k] = half(W[k*N+n]) ----------------
__global__ void __launch_bounds__(256) k_transW(const float* __restrict__ W,
                                                __half* __restrict__ dst,
                                                int K, int N, int Kp) {
    __shared__ float tile[32][33];
    int k0 = blockIdx.x * 32, n0 = blockIdx.y * 32;
    int tx = threadIdx.x & 31, ty = threadIdx.x >> 5;   // 32 x 8
#pragma unroll
    for (int r = 0; r < 4; r++) {
        int k = k0 + ty + r * 8, n = n0 + tx;
        tile[ty + r * 8][tx] = (k < K && n < N) ? W[(long)k * N + n] : 0.f;
    }
    __syncthreads();
#pragma unroll
    for (int r = 0; r < 4; r++) {
        int n = n0 + ty + r * 8, k = k0 + tx;
        if (n < N && k < Kp)
            dst[(long)n * Kp + k] = __float2half_rn(tile[tx][ty + r * 8]);
    }
}

// ============ fp16 tensor-core GEMM, 4-stage cp.async pipeline ============
#define KC 32
#define ASTR 40
#define HALF_BYTES (128 * ASTR * 2)
#define STAGE_BYTES (2 * HALF_BYTES)
#define GEMM_SMEM (4 * STAGE_BYTES)       // 81920

__global__ void __launch_bounds__(256)
gemm_mma(const __half* __restrict__ Ah, const __half* __restrict__ Bh,
         __half* __restrict__ C, int M, int N, int Kp, int NC, int ldc,
         float* __restrict__ aux, int auxcol) {
    extern __shared__ char smem_raw[];
    uint32_t sb = smem_u32(smem_raw);
    int tid = threadIdx.x, w = tid >> 5, l = tid & 31;
    int m0 = blockIdx.y * 128, n0 = blockIdx.x * 128;
    int wm = w & 3, wn = w >> 2;

    float acc[2][8][4];
#pragma unroll
    for (int i = 0; i < 2; i++)
#pragma unroll
        for (int j = 0; j < 8; j++)
#pragma unroll
            for (int q = 0; q < 4; q++) acc[i][j][q] = 0.f;

    auto issue = [&](int c) {
        int k0 = c * KC;
        uint32_t st = sb + (uint32_t)(c & 3) * STAGE_BYTES;
#pragma unroll
        for (int p = 0; p < 2; p++) {
            int f = tid + p * 256;
            int row = f >> 2, c16 = f & 3;
            uint32_t doff = (uint32_t)(row * (ASTR * 2) + c16 * 16);
            int am = m0 + row;
            int amc = am < M ? am : M - 1;
            int av = am < M ? 16 : 0;
            cpasync16(st + doff, Ah + (long)amc * Kp + k0 + c16 * 8, av);
            int bn = n0 + row;
            int bnc = bn < N ? bn : N - 1;
            int bv = bn < N ? 16 : 0;
            cpasync16(st + HALF_BYTES + doff, Bh + (long)bnc * Kp + k0 + c16 * 8, bv);
        }
        asm volatile("cp.async.commit_group;" ::: "memory");
    };

    issue(0);
    if (NC > 1) issue(1);
    if (NC > 2) issue(2);
    for (int c = 0; c < NC; c++) {
        if (c + 3 <= NC)      asm volatile("cp.async.wait_group 2;" ::: "memory");
        else if (c + 2 <= NC) asm volatile("cp.async.wait_group 1;" ::: "memory");
        else                  asm volatile("cp.async.wait_group 0;" ::: "memory");
        __syncthreads();
        if (c + 3 < NC) issue(c + 3);
        uint32_t st = sb + (uint32_t)(c & 3) * STAGE_BYTES;
        int lrow = l & 15, lcb = l >> 4;
#pragma unroll
        for (int k16 = 0; k16 < 2; k16++) {
            uint32_t coff = (uint32_t)((k16 * 16 + lcb * 8) * 2);
            uint32_t bh[4][4];
#pragma unroll
            for (int nt2 = 0; nt2 < 4; nt2++) {
                uint32_t roff = (uint32_t)((wn * 64 + nt2 * 16 + lrow) * (ASTR * 2));
                ldm4(bh[nt2], st + HALF_BYTES + roff + coff);
            }
#pragma unroll
            for (int mt = 0; mt < 2; mt++) {
                uint32_t roff = (uint32_t)((wm * 32 + mt * 16 + lrow) * (ASTR * 2));
                uint32_t ah[4];
                ldm4(ah, st + roff + coff);
#pragma unroll
                for (int nt = 0; nt < 8; nt++) {
                    int nt2 = nt >> 1, sel = nt & 1;
                    mma16816h(acc[mt][nt], ah, bh[nt2][sel], bh[nt2][sel + 2]);
                }
            }
        }
    }

#pragma unroll
    for (int mt = 0; mt < 2; mt++) {
#pragma unroll
        for (int nt = 0; nt < 8; nt++) {
            int row = m0 + wm * 32 + mt * 16 + (l >> 2);
            int col = n0 + wn * 64 + nt * 8 + 2 * (l & 3);
            if (col < N) {
                if (col >= auxcol) {
                    int ac = col - auxcol;
                    if (row < M) {
                        aux[row * 20 + ac]     = acc[mt][nt][0];
                        aux[row * 20 + ac + 1] = acc[mt][nt][1];
                    }
                    int row2 = row + 8;
                    if (row2 < M) {
                        aux[row2 * 20 + ac]     = acc[mt][nt][2];
                        aux[row2 * 20 + ac + 1] = acc[mt][nt][3];
                    }
                } else {
                    if (row < M)
                        *(__half2*)(C + (long)row * ldc + col) =
                            __floats2half2_rn(acc[mt][nt][0], acc[mt][nt][1]);
                    int row2 = row + 8;
                    if (row2 < M)
                        *(__half2*)(C + (long)row2 * ldc + col) =
                            __floats2half2_rn(acc[mt][nt][2], acc[mt][nt][3]);
                }
            }
        }
    }
}

// ---------------- latency-optimized skinny GEMM ----------------
__global__ void __launch_bounds__(256)
mlp8(const float* __restrict__ A, const float* __restrict__ W,
     float* __restrict__ C, const float* __restrict__ bias,
     int M, int N, int K, int lda, int ldc, int coff, int relu) {
    __shared__ float sact[8 * 1504];
    int t = threadIdx.x;
    int j = t & 63, kc = t >> 6;
    int jg = blockIdx.x * 64 + j;
    int r0 = blockIdx.y * 8;

    for (int i = t; i < 8 * K; i += 256) {
        int r = i / K, k = i - r * K;
        int row = r0 + r;
        sact[i] = (row < M) ? A[(long)row * lda + k] : 0.f;
    }
    __syncthreads();

    float acc[8];
#pragma unroll
    for (int r = 0; r < 8; r++) acc[r] = 0.f;
    if (jg < N) {
        for (int k = kc; k < K; k += 4) {
            float wv = W[(long)k * N + jg];
            const float* ar = &sact[k];
#pragma unroll
            for (int r = 0; r < 8; r++) acc[r] += ar[r * K] * wv;
        }
    }
    __syncthreads();
    float* red = sact;
#pragma unroll
    for (int r = 0; r < 8; r++) red[(j * 4 + kc) + r * 256] = acc[r];
    __syncthreads();
    if (kc == 0 && jg < N) {
        float b = bias ? bias[jg] : 0.f;
#pragma unroll
        for (int r = 0; r < 8; r++) {
            int row = r0 + r;
            if (row >= M) break;
            float v = red[j * 4 + r * 256] + red[j * 4 + 1 + r * 256]
                    + red[j * 4 + 2 + r * 256] + red[j * 4 + 3 + r * 256] + b;
            if (relu) v = fmaxf(v, 0.f);
            C[(long)row * ldc + coff + jg] = v;
        }
    }
}

// ---------------- CSR build ----------------
__global__ void k_count(const int* __restrict__ edge) {
    int i = blockIdx.x * blockDim.x + threadIdx.x;
    if (i >= ET) return;
    int dst = (i < EE) ? edge[EE + i] : i - EE;
    atomicAdd(&g_cnt[dst], 1);
}
// parallel scan: A (block sums) -> B (scan of sums) -> C (block-local scan + write)
__global__ void __launch_bounds__(256) k_scanA() {
    __shared__ int s[256];
    int t = threadIdx.x;
    int i = blockIdx.x * 256 + t;
    s[t] = (i < NN) ? g_cnt[i] : 0;
    __syncthreads();
    for (int off = 128; off > 0; off >>= 1) {
        if (t < off) s[t] += s[t + off];
        __syncthreads();
    }
    if (t == 0) g_bsum[blockIdx.x] = s[0];
}
__global__ void k_scanB() {
    __shared__ int s[NB];
    int t = threadIdx.x;
    if (t < NB) s[t] = g_bsum[t];
    __syncthreads();
    if (t == 0) {
        int r = 0;
        for (int i = 0; i < NB; i++) { int v = s[i]; g_bpre[i] = r; r += v; }
        g_off[NN] = r;
    }
}
__global__ void __launch_bounds__(256) k_scanC() {
    __shared__ int s[256];
    int t = threadIdx.x;
    int i = blockIdx.x * 256 + t;
    int c = (i < NN) ? g_cnt[i] : 0;
    s[t] = c;
    __syncthreads();
    for (int off = 1; off < 256; off <<= 1) {
        int v = (t >= off) ? s[t - off] : 0;
        __syncthreads();
        s[t] += v;
        __syncthreads();
    }
    if (i < NN) {
        g_off[i] = g_bpre[blockIdx.x] + s[t] - c;
        g_dinv[i] = rsqrtf((float)(c > 0 ? c : 1));
    }
}
__global__ void k_scatter(const int* __restrict__ edge) {
    int i = blockIdx.x * blockDim.x + threadIdx.x;
    if (i >= ET) return;
    int src = (i < EE) ? edge[i]      : i - EE;
    int dst = (i < EE) ? edge[EE + i] : i - EE;
    int old = atomicSub(&g_cnt[dst], 1);
    g_srcA[g_off[dst] + old - 1] = src;
}
__global__ void k_startB(const int* __restrict__ batch) {
    int n = blockIdx.x * blockDim.x + threadIdx.x;
    if (n >= NN) return;
    int b = batch[n];
    if (n == 0) {
        for (int bb = 0; bb <= b; bb++) g_start[bb] = 0;
    } else {
        int pb = batch[n - 1];
        if (pb != b) for (int bb = pb + 1; bb <= b; bb++) g_start[bb] = n;
    }
    if (n == NN - 1) {
        for (int bb = b + 1; bb <= BB; bb++) g_start[bb] = NN;
    }
}

// ---------------- fused softmax + GAT aggregation ----------------
__device__ __forceinline__ uint32_t fmapU(float f) {
    uint32_t u = __float_as_uint(f);
    return u ^ (uint32_t)(((int)u >> 31) | 0x80000000);
}
__device__ __forceinline__ float finvU(uint32_t u) {
    return (u & 0x80000000u) ? __uint_as_float(u ^ 0x80000000u) : __uint_as_float(~u);
}
__global__ void __launch_bounds__(256) k_gat_soft_agg(const float* __restrict__ gat_b) {
    __shared__ float sal[DMAX * HH];
    __shared__ int ssrc[DMAX];
    __shared__ uint32_t sm[HH];
    __shared__ float sden[HH], sad[HH];
    int n = blockIdx.x, t = threadIdx.x;
    int lo = g_off[n], d = g_off[n + 1] - lo;
    bool small = (d <= DMAX);
    float* ebuf = small ? sal : &g_e[(long)lo * HH];
    const int* sp = small ? ssrc : &g_srcA[lo];
    if (t < HH) { sm[t] = fmapU(-INFINITY); sden[t] = 0.f; sad[t] = g_asad[n * 20 + 10 + t]; }
    if (small)
        for (int i = t; i < d; i += 256) ssrc[i] = g_srcA[lo + i];
    __syncthreads();
    int tot = d * HH;
    for (int p = t; p < tot; p += 256) {
        int i = p / HH, h = p - i * HH;
        int src = sp[i];
        float e = g_asad[src * 20 + h] + sad[h];
        e = (e > 0.f) ? e : 0.2f * e;
        ebuf[p] = e;
        atomicMax(&sm[h], fmapU(e));
    }
    __syncthreads();
    for (int p = t; p < tot; p += 256) {
        int h = p % HH;
        float ex = expf(ebuf[p] - finvU(sm[h]));
        ebuf[p] = ex;
        atomicAdd(&sden[h], ex);
    }
    __syncthreads();
    if (t < HH) sden[t] = 1.f / sden[t];
    __syncthreads();
    for (int p = t; p < tot; p += 256) ebuf[p] *= sden[p % HH];
    __syncthreads();

    if (t >= 208) return;
    long base = (long)n * KPG + t * 4;
    if (t >= 195) {
        __half2 z = __floats2half2_rn(0.f, 0.f);
        *(__half2*)(g_Ag + base) = z;
        *(__half2*)(g_Ag + base + 2) = z;
        return;
    }
    int q = t * 4;
    int h0 = q / FF, h1 = (q + 1) / FF, h2 = (q + 2) / FF, h3 = (q + 3) / FF;
    float ax = 0.f, ay = 0.f, az = 0.f, aw = 0.f;
    for (int idx = 0; idx < d; idx++) {
        int s = sp[idx];
        uint2 u = *(const uint2*)(g_hH + (long)s * NEXT + q);
        float2 v01 = __half22float2(*(__half2*)&u.x);
        float2 v23 = __half22float2(*(__half2*)&u.y);
        const float* al = &ebuf[idx * HH];
        ax += v01.x * al[h0]; ay += v01.y * al[h1]; az += v23.x * al[h2]; aw += v23.y * al[h3];
    }
    float v0 = fmaxf(ax + gat_b[q + 0], 0.f);
    float v1 = fmaxf(ay + gat_b[q + 1], 0.f);
    float v2 = fmaxf(az + gat_b[q + 2], 0.f);
    float v3 = fmaxf(aw + gat_b[q + 3], 0.f);
    *(__half2*)(g_Ag + base)     = __floats2half2_rn(v0, v1);
    *(__half2*)(g_Ag + base + 2) = __floats2half2_rn(v2, v3);
}

// ---------------- GCN aggregation ----------------
__global__ void __launch_bounds__(256) k_gcn_agg(const float* __restrict__ gcn_b) {
    int n = blockIdx.x, t = threadIdx.x;
    if (t >= 195) return;
    int q = t * 4;
    float dn = g_dinv[n];
    float ax = 0.f, ay = 0.f, az = 0.f, aw = 0.f;
    int lo = g_off[n], hi = g_off[n + 1];
    for (int idx = lo; idx < hi; idx++) {
        int s = g_srcA[idx];
        float norm = dn * g_dinv[s];
        uint2 u = *(const uint2*)(g_h2H + (long)s * HID + q);
        float2 v01 = __half22float2(*(__half2*)&u.x);
        float2 v23 = __half22float2(*(__half2*)&u.y);
        ax += v01.x * norm; ay += v01.y * norm; az += v23.x * norm; aw += v23.y * norm;
    }
    float v0 = fmaxf(ax + gcn_b[q + 0], 0.f);
    float v1 = fmaxf(ay + gcn_b[q + 1], 0.f);
    float v2 = fmaxf(az + gcn_b[q + 2], 0.f);
    float v3 = fmaxf(aw + gcn_b[q + 3], 0.f);
    *(__half2*)(g_x2H + (long)n * HID + q)     = __floats2half2_rn(v0, v1);
    *(__half2*)(g_x2H + (long)n * HID + q + 2) = __floats2half2_rn(v2, v3);
}

// ---------------- segment pool ----------------
__global__ void __launch_bounds__(256) k_pool() {
    int b = blockIdx.x, t = threadIdx.x;
    if (t >= 195) return;
    int q = t * 4;
    int lo = g_start[b], hi = g_start[b + 1];
    float ax = 0.f, ay = 0.f, az = 0.f, aw = 0.f;
    for (int n = lo; n < hi; n++) {
        uint2 u = *(const uint2*)(g_x2H + (long)n * HID + q);
        float2 v01 = __half22float2(*(__half2*)&u.x);
        float2 v23 = __half22float2(*(__half2*)&u.y);
        ax += v01.x; ay += v01.y; az += v23.x; aw += v23.y;
    }
    float* o = g_xg + (long)b * HID + q;
    o[0] = ax; o[1] = ay; o[2] = az; o[3] = aw;
}

// ---------------- protein branch ----------------
__global__ void k_Pbias(const float* __restrict__ emb, const float* __restrict__ cW,
                        const float* __restrict__ fxtW, const float* __restrict__ cb) {
    int bi = blockIdx.x, j = threadIdx.x;
    if (bi < 256) {
        int o = bi >> 3, c = bi & 7;
        int t0 = c * 125, t1 = min(t0 + 125, COUT);
        float p = 0.f;
        for (int t = t0; t < t1; t++)
            p += fxtW[((long)(o * COUT + t)) * 128 + j];
        atomicAdd(&g_biasY[j], cb[o] * p);
    } else {
        int g = (bi - 256) * 128 + j;
        if (g >= VOC * NF * KS) return;
        int v = g / (NF * KS), r = g % (NF * KS);
        int o = r / KS, k = r % KS;
        float s = 0.f;
#pragma unroll 16
        for (int e = 0; e < EMB; e++)
            s += emb[v * EMB + e] * cW[o * EMB * KS + e * KS + k];
        g_P[g] = s;
    }
}
__global__ void k_R(const float* __restrict__ fxtW) {
    __shared__ float Ps[VOC * NF * KS];
    int s = blockIdx.x, j = threadIdx.x;
    for (int idx = j; idx < VOC * NF * KS; idx += 128) Ps[idx] = g_P[idx];
    __syncthreads();
    float acc[VOC];
#pragma unroll
    for (int v = 0; v < VOC; v++) acc[v] = 0.f;
    int kmin = (s > COUT - 1) ? (s - (COUT - 1)) : 0;
    int kmax = (s < KS - 1) ? s : (KS - 1);
    for (int o = 0; o < NF; o++) {
        for (int k = kmin; k <= kmax; k++) {
            float w = fxtW[((long)(o * COUT + s - k)) * 128 + j];
#pragma unroll
            for (int v = 0; v < VOC; v++)
                acc[v] += Ps[v * (NF * KS) + o * KS + k] * w;
        }
    }
#pragma unroll
    for (int v = 0; v < VOC; v++)
        g_R[((long)v * SEQ + s) * 128 + j] = acc[v];
}
__global__ void k_Y(const int* __restrict__ target, const float* __restrict__ fxt_b) {
    __shared__ int sv[SEQ];
    int b = blockIdx.x, j = threadIdx.x;
    for (int i = j; i < SEQ; i += 128) sv[i] = target[b * SEQ + i];
    __syncthreads();
    float acc = g_biasY[j] + fxt_b[j];
    for (int s = 0; s < SEQ; s += 4) {
        float r0 = g_R[((long)sv[s]     * SEQ + s)     * 128 + j];
        float r1 = g_R[((long)sv[s + 1] * SEQ + s + 1) * 128 + j];
        float r2 = g_R[((long)sv[s + 2] * SEQ + s + 2) * 128 + j];
        float r3 = g_R[((long)sv[s + 3] * SEQ + s + 3) * 128 + j];
        acc += (r0 + r1) + (r2 + r3);
    }
    g_xc[b * 256 + 128 + j] = acc;
}

// ---------------- output ----------------
__global__ void k_out(const float* __restrict__ oW, const float* __restrict__ ob,
                      float* __restrict__ out) {
    __shared__ float red[4];
    int b = blockIdx.x, j = threadIdx.x;
    float v = g_t5[b * 128 + j] * oW[j];
#pragma unroll
    for (int off = 16; off; off >>= 1) v += __shfl_down_sync(0xffffffffu, v, off);
    if ((j & 31) == 0) red[j >> 5] = v;
    __syncthreads();
    if (j == 0) out[b] = red[0] + red[1] + red[2] + red[3] + ob[0];
}

// ---------------- host ----------------
static inline dim3 ggrid(long n, int t) { return dim3((unsigned)((n + t - 1) / t)); }

extern "C" void kernel_launch(void* const* d_in, const int* in_sizes, int n_in,
                              void* d_out, int out_size) {
    const float* x      = (const float*)d_in[0];
    const int*   edge   = (const int*)  d_in[1];
    const int*   batch  = (const int*)  d_in[2];
    const int*   target = (const int*)  d_in[3];
    const float* gat_W  = (const float*)d_in[4];
    const float* a_src  = (const float*)d_in[5];
    const float* a_dst  = (const float*)d_in[6];
    const float* gat_b  = (const float*)d_in[7];
    const float* gcn_W  = (const float*)d_in[8];
    const float* gcn_b  = (const float*)d_in[9];
    const float* fcg1_W = (const float*)d_in[10];
    const float* fcg1_b = (const float*)d_in[11];
    const float* fcg2_W = (const float*)d_in[12];
    const float* fcg2_b = (const float*)d_in[13];
    const float* emb    = (const float*)d_in[14];
    const float* cW     = (const float*)d_in[15];
    const float* cb     = (const float*)d_in[16];
    const float* fxt_W  = (const float*)d_in[17];
    const float* fxt_b  = (const float*)d_in[18];
    const float* f1_W   = (const float*)d_in[19];
    const float* f1_b   = (const float*)d_in[20];
    const float* f2_W   = (const float*)d_in[21];
    const float* f2_b   = (const float*)d_in[22];
    const float* f3_W   = (const float*)d_in[23];
    const float* f3_b   = (const float*)d_in[24];
    const float* f4_W   = (const float*)d_in[25];
    const float* f4_b   = (const float*)d_in[26];
    const float* o_W    = (const float*)d_in[27];
    const float* o_b    = (const float*)d_in[28];
    float* out = (float*)d_out;

    float *p_xg, *p_t1, *p_xc, *p_t2, *p_t3, *p_t4, *p_t5, *p_asad;
    __half *p_hH, *p_h2H, *p_Axh, *p_Bah, *p_Ag, *p_Bgh;
    cudaGetSymbolAddress((void**)&p_hH,  g_hH);
    cudaGetSymbolAddress((void**)&p_h2H, g_h2H);
    cudaGetSymbolAddress((void**)&p_asad, g_asad);
    cudaGetSymbolAddress((void**)&p_xg,  g_xg);
    cudaGetSymbolAddress((void**)&p_t1,  g_t1);
    cudaGetSymbolAddress((void**)&p_xc,  g_xc);
    cudaGetSymbolAddress((void**)&p_t2,  g_t2);
    cudaGetSymbolAddress((void**)&p_t3,  g_t3);
    cudaGetSymbolAddress((void**)&p_t4,  g_t4);
    cudaGetSymbolAddress((void**)&p_t5,  g_t5);
    cudaGetSymbolAddress((void**)&p_Axh, g_Axh);
    cudaGetSymbolAddress((void**)&p_Bah, g_Bah);
    cudaGetSymbolAddress((void**)&p_Ag,  g_Ag);
    cudaGetSymbolAddress((void**)&p_Bgh, g_Bgh);

    static cudaStream_t s1, s2;
    static cudaEvent_t eF, e1, e2;
    static int inited = 0;
    if (!inited) {
        cudaStreamCreateWithFlags(&s1, cudaStreamNonBlocking);
        cudaStreamCreateWithFlags(&s2, cudaStreamNonBlocking);
        cudaEventCreateWithFlags(&eF, cudaEventDisableTiming);
        cudaEventCreateWithFlags(&e1, cudaEventDisableTiming);
        cudaEventCreateWithFlags(&e2, cudaEventDisableTiming);
        cudaFuncSetAttribute(gemm_mma, cudaFuncAttributeMaxDynamicSharedMemorySize, GEMM_SMEM);
        inited = 1;
    }

    cudaEventRecord(eF, 0);
    cudaStreamWaitEvent(s1, eF, 0);
    cudaStreamWaitEvent(s2, eF, 0);

    // main: conversions (coalesced) + A convert + attn rows
    k_transW<<<dim3(4, 25), 256>>>(gat_W, p_Bah, FF, HID, KPA);
    k_transW<<<dim3(26, 25), 256>>>(gcn_W, p_Bgh, HID, HID, KPG);
    k_prep<<<PB_A + PB_E, 256>>>(x, gat_W, a_src, a_dst);
    // s1: CSR build with parallel scan
    k_count<<<ggrid(ET, 256), 256, 0, s1>>>(edge);
    k_startB<<<ggrid(NN, 256), 256, 0, s1>>>(batch);
    k_scanA<<<NB, 256, 0, s1>>>();
    k_scanB<<<1, 128, 0, s1>>>();
    k_scanC<<<NB, 256, 0, s1>>>();
    // main: GAT GEMM (N=800 incl. attn cols)
    gemm_mma<<<dim3(7, 157), 256, GEMM_SMEM>>>(p_Axh, p_Bah, p_hH, NN, NEXT, KPA, KPA / KC, NEXT,
                                               p_asad, HID);
    // s1: scatter
    k_scatter<<<ggrid(ET, 256), 256, 0, s1>>>(edge);
    cudaEventRecord(e1, s1);
    // s2: protein branch
    k_init0<<<1, 128, 0, s2>>>();
    k_Pbias<<<308, 128, 0, s2>>>(emb, cW, fxt_W, cb);
    k_R<<<SEQ, 128, 0, s2>>>(fxt_W);
    k_Y<<<BB, 128, 0, s2>>>(target, fxt_b);
    cudaEventRecord(e2, s2);
    // main: graph branch
    cudaStreamWaitEvent(0, e1, 0);
    k_gat_soft_agg<<<NN, 256>>>(gat_b);
    gemm_mma<<<dim3(7, 157), 256, GEMM_SMEM>>>(p_Ag, p_Bgh, p_h2H, NN, HID, KPG, KPG / KC, HID,
                                               nullptr, 1 << 30);
    k_gcn_agg<<<NN, 256>>>(gcn_b);
    k_pool<<<BB, 256>>>();
    // head
    mlp8<<<dim3(24, 25), 256>>>(p_xg, fcg1_W, p_t1, fcg1_b, BB, 1500, HID, HID, 1500, 0, 1);
    mlp8<<<dim3(2, 25), 256>>>(p_t1, fcg2_W, p_xc, fcg2_b, BB, 128, 1500, 1500, 256, 0, 0);
    cudaStreamWaitEvent(0, e2, 0);
    mlp8<<<dim3(16, 25), 256>>>(p_xc, f1_W, p_t2, f1_b, BB, 1024, 256, 256, 1024, 0, 1);
    mlp8<<<dim3(8, 25), 256>>>(p_t2, f2_W, p_t3, f2_b, BB, 512, 1024, 1024, 512, 0, 1);
    mlp8<<<dim3(4, 25), 256>>>(p_t3, f3_W, p_t4, f3_b, BB, 256, 512, 512, 256, 0, 1);
    mlp8<<<dim3(2, 25), 256>>>(p_t4, f4_W, p_t5, f4_b, BB, 128, 256, 256, 128, 0, 1);
    k_out<<<BB, 128>>>(o_W, o_b, out);
}

// round 11
// speedup vs baseline: 9.7360x; 1.0328x over previous
#include <cuda_runtime.h>
#include <cuda_fp16.h>
#include <math.h>
#include <stdint.h>

#define NN   20000
#define EE   400000
#define ET   (EE + NN)
#define HH   10
#define FF   78
#define HID  780
#define NEXT 800
#define BB   200
#define SEQ  1000
#define VOC  26
#define EMB  128
#define NF   32
#define KS   8
#define COUT 993
#define KPA  128
#define KPG  832
#define DMAX 256
#define NB   79

// ---------------- scratch ----------------
__device__ __half g_hH [(long)NN * NEXT];
__device__ __half g_h2H[(long)NN * HID];
__device__ __half g_x2H[(long)NN * HID];
__device__ float g_asad[NN * 20];
__device__ float g_e  [(long)ET * HH];
__device__ float g_xg [BB * HID];
__device__ float g_t1 [BB * 1500];
__device__ float g_xc [BB * 256];
__device__ float g_t2 [BB * 1024];
__device__ float g_t3 [BB * 512];
__device__ float g_t4 [BB * 256];
__device__ float g_t5 [BB * 128];
__device__ float g_P  [VOC * NF * KS];
__device__ float g_R  [(long)VOC * SEQ * 128];
__device__ float g_biasY[128];
__device__ int   g_cnt[NN];        // invariant: zero at kernel_launch entry
__device__ int   g_off[NN + 1];
__device__ int   g_bsum[NB];
__device__ int   g_bpre[NB];
__device__ int   g_srcA[ET];
__device__ int   g_start[BB + 1];
__device__ float g_dinv[NN];
__device__ __half g_Axh[(long)NN * KPA];
__device__ __half g_Bah[(long)NEXT * KPA];
__device__ __half g_Ag [(long)NN * KPG];
__device__ __half g_Bgh[(long)HID * KPG];

// ---------------- helpers ----------------
__device__ __forceinline__ uint32_t smem_u32(const void* p) {
    uint32_t a;
    asm("{ .reg .u64 t; cvta.to.shared.u64 t, %1; cvt.u32.u64 %0, t; }" : "=r"(a) : "l"(p));
    return a;
}
__device__ __forceinline__ void cpasync16(uint32_t dst, const void* src, int nbytes) {
    asm volatile("cp.async.cg.shared.global [%0], [%1], 16, %2;"
                 :: "r"(dst), "l"(__cvta_generic_to_global(src)), "r"(nbytes) : "memory");
}
__device__ __forceinline__ void ldm4(uint32_t* r, uint32_t addr) {
    asm volatile("ldmatrix.sync.aligned.m8n8.x4.shared.b16 {%0,%1,%2,%3}, [%4];"
                 : "=r"(r[0]), "=r"(r[1]), "=r"(r[2]), "=r"(r[3]) : "r"(addr));
}
__device__ __forceinline__ void mma16816h(float* c, const uint32_t* a, uint32_t b0, uint32_t b1) {
    asm volatile("mma.sync.aligned.m16n8k16.row.col.f32.f16.f16.f32 "
                 "{%0,%1,%2,%3}, {%4,%5,%6,%7}, {%8,%9}, {%0,%1,%2,%3};"
                 : "+f"(c[0]), "+f"(c[1]), "+f"(c[2]), "+f"(c[3])
                 : "r"(a[0]), "r"(a[1]), "r"(a[2]), "r"(a[3]), "r"(b0), "r"(b1));
}

// ---------------- tiny init ----------------
__global__ void k_init0() {
    g_biasY[threadIdx.x] = 0.f;
}

// ---------------- prep ----------------
#define PB_A 10000
#define PB_E 20
__global__ void __launch_bounds__(256) k_prep(const float* __restrict__ x,
                                              const float* __restrict__ gat_W,
                                              const float* __restrict__ aS,
                                              const float* __restrict__ aD) {
    int bid = blockIdx.x, t = threadIdx.x;
    if (bid < PB_A) {
        int i = bid * 256 + t;
        int m = i >> 7, k = i & 127;
        g_Axh[i] = __float2half_rn(k < FF ? x[(long)m * FF + k] : 0.f);
    } else {
        int i = bid - PB_A;
        int k = t;
        if (k >= 128) return;
        int h = i % 10;
        const float* av = ((i < 10) ? aS : aD) + h * FF;
        float s = 0.f;
        if (k < FF) {
            const float* wr = gat_W + (long)k * HID + h * FF;
#pragma unroll 13
            for (int f = 0; f < FF; f++) s += wr[f] * av[f];
        }
        g_Bah[(long)(HID + i) * KPA + k] = __float2half_rn(s);
    }
}

// ---------------- coalesced transpose-convert ----------------
__global__ void __launch_bounds__(256) k_transW(const float* __restrict__ W,
                                                __half* __restrict__ dst,
                                                int K, int N, int Kp) {
    __shared__ float tile[32][33];
    int k0 = blockIdx.x * 32, n0 = blockIdx.y * 32;
    int tx = threadIdx.x & 31, ty = threadIdx.x >> 5;
#pragma unroll
    for (int r = 0; r < 4; r++) {
        int k = k0 + ty + r * 8, n = n0 + tx;
        tile[ty + r * 8][tx] = (k < K && n < N) ? W[(long)k * N + n] : 0.f;
    }
    __syncthreads();
#pragma unroll
    for (int r = 0; r < 4; r++) {
        int n = n0 + ty + r * 8, k = k0 + tx;
        if (n < N && k < Kp)
            dst[(long)n * Kp + k] = __float2half_rn(tile[tx][ty + r * 8]);
    }
}

// ============ fp16 tensor-core GEMM, KC=64, 3-stage cp.async pipeline ============
#define KC 64
#define ASTR 72                           // 64 + 8 pad halves per row
#define HALF_BYTES (128 * ASTR * 2)       // 18432
#define STAGE_BYTES (2 * HALF_BYTES)      // 36864
#define GEMM_SMEM (3 * STAGE_BYTES)       // 110592

__global__ void __launch_bounds__(256)
gemm_mma(const __half* __restrict__ Ah, const __half* __restrict__ Bh,
         __half* __restrict__ C, int M, int N, int Kp, int NC, int ldc,
         float* __restrict__ aux, int auxcol) {
    extern __shared__ char smem_raw[];
    uint32_t sb = smem_u32(smem_raw);
    int tid = threadIdx.x, w = tid >> 5, l = tid & 31;
    int m0 = blockIdx.y * 128, n0 = blockIdx.x * 128;
    int wm = w & 3, wn = w >> 2;

    float acc[2][8][4];
#pragma unroll
    for (int i = 0; i < 2; i++)
#pragma unroll
        for (int j = 0; j < 8; j++)
#pragma unroll
            for (int q = 0; q < 4; q++) acc[i][j][q] = 0.f;

    auto issue = [&](int c) {
        int k0 = c * KC;
        uint32_t st = sb + (uint32_t)(c % 3) * STAGE_BYTES;
#pragma unroll
        for (int p = 0; p < 4; p++) {
            int f = tid + p * 256;
            int row = f >> 3, c16 = f & 7;
            uint32_t doff = (uint32_t)(row * (ASTR * 2) + c16 * 16);
            int am = m0 + row;
            int amc = am < M ? am : M - 1;
            int av = am < M ? 16 : 0;
            cpasync16(st + doff, Ah + (long)amc * Kp + k0 + c16 * 8, av);
            int bn = n0 + row;
            int bnc = bn < N ? bn : N - 1;
            int bv = bn < N ? 16 : 0;
            cpasync16(st + HALF_BYTES + doff, Bh + (long)bnc * Kp + k0 + c16 * 8, bv);
        }
        asm volatile("cp.async.commit_group;" ::: "memory");
    };

    issue(0);
    if (NC > 1) issue(1);
    for (int c = 0; c < NC; c++) {
        if (c + 1 < NC) asm volatile("cp.async.wait_group 1;" ::: "memory");
        else            asm volatile("cp.async.wait_group 0;" ::: "memory");
        __syncthreads();
        if (c + 2 < NC) issue(c + 2);
        uint32_t st = sb + (uint32_t)(c % 3) * STAGE_BYTES;
        int lrow = l & 15, lcb = l >> 4;
#pragma unroll
        for (int k16 = 0; k16 < 4; k16++) {
            uint32_t coff = (uint32_t)((k16 * 16 + lcb * 8) * 2);
            uint32_t bh[4][4];
#pragma unroll
            for (int nt2 = 0; nt2 < 4; nt2++) {
                uint32_t roff = (uint32_t)((wn * 64 + nt2 * 16 + lrow) * (ASTR * 2));
                ldm4(bh[nt2], st + HALF_BYTES + roff + coff);
            }
#pragma unroll
            for (int mt = 0; mt < 2; mt++) {
                uint32_t roff = (uint32_t)((wm * 32 + mt * 16 + lrow) * (ASTR * 2));
                uint32_t ah[4];
                ldm4(ah, st + roff + coff);
#pragma unroll
                for (int nt = 0; nt < 8; nt++) {
                    int nt2 = nt >> 1, sel = nt & 1;
                    mma16816h(acc[mt][nt], ah, bh[nt2][sel], bh[nt2][sel + 2]);
                }
            }
        }
    }

#pragma unroll
    for (int mt = 0; mt < 2; mt++) {
#pragma unroll
        for (int nt = 0; nt < 8; nt++) {
            int row = m0 + wm * 32 + mt * 16 + (l >> 2);
            int col = n0 + wn * 64 + nt * 8 + 2 * (l & 3);
            if (col < N) {
                if (col >= auxcol) {
                    int ac = col - auxcol;
                    if (row < M) {
                        aux[row * 20 + ac]     = acc[mt][nt][0];
                        aux[row * 20 + ac + 1] = acc[mt][nt][1];
                    }
                    int row2 = row + 8;
                    if (row2 < M) {
                        aux[row2 * 20 + ac]     = acc[mt][nt][2];
                        aux[row2 * 20 + ac + 1] = acc[mt][nt][3];
                    }
                } else {
                    if (row < M)
                        *(__half2*)(C + (long)row * ldc + col) =
                            __floats2half2_rn(acc[mt][nt][0], acc[mt][nt][1]);
                    int row2 = row + 8;
                    if (row2 < M)
                        *(__half2*)(C + (long)row2 * ldc + col) =
                            __floats2half2_rn(acc[mt][nt][2], acc[mt][nt][3]);
                }
            }
        }
    }
}

// ---------------- latency-optimized skinny GEMM ----------------
__global__ void __launch_bounds__(256)
mlp8(const float* __restrict__ A, const float* __restrict__ W,
     float* __restrict__ C, const float* __restrict__ bias,
     int M, int N, int K, int lda, int ldc, int coff, int relu) {
    __shared__ float sact[8 * 1504];
    int t = threadIdx.x;
    int j = t & 63, kc = t >> 6;
    int jg = blockIdx.x * 64 + j;
    int r0 = blockIdx.y * 8;

    for (int i = t; i < 8 * K; i += 256) {
        int r = i / K, k = i - r * K;
        int row = r0 + r;
        sact[i] = (row < M) ? A[(long)row * lda + k] : 0.f;
    }
    __syncthreads();

    float acc[8];
#pragma unroll
    for (int r = 0; r < 8; r++) acc[r] = 0.f;
    if (jg < N) {
        for (int k = kc; k < K; k += 4) {
            float wv = W[(long)k * N + jg];
            const float* ar = &sact[k];
#pragma unroll
            for (int r = 0; r < 8; r++) acc[r] += ar[r * K] * wv;
        }
    }
    __syncthreads();
    float* red = sact;
#pragma unroll
    for (int r = 0; r < 8; r++) red[(j * 4 + kc) + r * 256] = acc[r];
    __syncthreads();
    if (kc == 0 && jg < N) {
        float b = bias ? bias[jg] : 0.f;
#pragma unroll
        for (int r = 0; r < 8; r++) {
            int row = r0 + r;
            if (row >= M) break;
            float v = red[j * 4 + r * 256] + red[j * 4 + 1 + r * 256]
                    + red[j * 4 + 2 + r * 256] + red[j * 4 + 3 + r * 256] + b;
            if (relu) v = fmaxf(v, 0.f);
            C[(long)row * ldc + coff + jg] = v;
        }
    }
}

// ---------------- CSR build ----------------
__global__ void k_count(const int* __restrict__ edge) {
    int i = blockIdx.x * blockDim.x + threadIdx.x;
    if (i >= ET) return;
    int dst = (i < EE) ? edge[EE + i] : i - EE;
    atomicAdd(&g_cnt[dst], 1);
}
__global__ void __launch_bounds__(256) k_scanA() {
    __shared__ int s[256];
    int t = threadIdx.x;
    int i = blockIdx.x * 256 + t;
    s[t] = (i < NN) ? g_cnt[i] : 0;
    __syncthreads();
    for (int off = 128; off > 0; off >>= 1) {
        if (t < off) s[t] += s[t + off];
        __syncthreads();
    }
    if (t == 0) g_bsum[blockIdx.x] = s[0];
}
__global__ void k_scanB() {
    __shared__ int s[NB];
    int t = threadIdx.x;
    if (t < NB) s[t] = g_bsum[t];
    __syncthreads();
    if (t == 0) {
        int r = 0;
        for (int i = 0; i < NB; i++) { int v = s[i]; g_bpre[i] = r; r += v; }
        g_off[NN] = r;
    }
}
__global__ void __launch_bounds__(256) k_scanC() {
    __shared__ int s[256];
    int t = threadIdx.x;
    int i = blockIdx.x * 256 + t;
    int c = (i < NN) ? g_cnt[i] : 0;
    s[t] = c;
    __syncthreads();
    for (int off = 1; off < 256; off <<= 1) {
        int v = (t >= off) ? s[t - off] : 0;
        __syncthreads();
        s[t] += v;
        __syncthreads();
    }
    if (i < NN) {
        g_off[i] = g_bpre[blockIdx.x] + s[t] - c;
        g_dinv[i] = rsqrtf((float)(c > 0 ? c : 1));
    }
}
__global__ void k_scatter(const int* __restrict__ edge) {
    int i = blockIdx.x * blockDim.x + threadIdx.x;
    if (i >= ET) return;
    int src = (i < EE) ? edge[i]      : i - EE;
    int dst = (i < EE) ? edge[EE + i] : i - EE;
    int old = atomicSub(&g_cnt[dst], 1);
    g_srcA[g_off[dst] + old - 1] = src;
}
__global__ void k_startB(const int* __restrict__ batch) {
    int n = blockIdx.x * blockDim.x + threadIdx.x;
    if (n >= NN) return;
    int b = batch[n];
    if (n == 0) {
        for (int bb = 0; bb <= b; bb++) g_start[bb] = 0;
    } else {
        int pb = batch[n - 1];
        if (pb != b) for (int bb = pb + 1; bb <= b; bb++) g_start[bb] = n;
    }
    if (n == NN - 1) {
        for (int bb = b + 1; bb <= BB; bb++) g_start[bb] = NN;
    }
}

// ---------------- fused softmax + GAT aggregation (divide-at-end) ----------------
__device__ __forceinline__ uint32_t fmapU(float f) {
    uint32_t u = __float_as_uint(f);
    return u ^ (uint32_t)(((int)u >> 31) | 0x80000000);
}
__device__ __forceinline__ float finvU(uint32_t u) {
    return (u & 0x80000000u) ? __uint_as_float(u ^ 0x80000000u) : __uint_as_float(~u);
}
__global__ void __launch_bounds__(256) k_gat_soft_agg(const float* __restrict__ gat_b) {
    __shared__ float sal[DMAX * HH];
    __shared__ int ssrc[DMAX];
    __shared__ uint32_t sm[HH];
    __shared__ float sden[HH], sad[HH];
    int n = blockIdx.x, t = threadIdx.x;
    int lo = g_off[n], d = g_off[n + 1] - lo;
    bool small = (d <= DMAX);
    float* ebuf = small ? sal : &g_e[(long)lo * HH];
    const int* sp = small ? ssrc : &g_srcA[lo];
    if (t < HH) { sm[t] = fmapU(-INFINITY); sden[t] = 0.f; sad[t] = g_asad[n * 20 + 10 + t]; }
    if (small)
        for (int i = t; i < d; i += 256) ssrc[i] = g_srcA[lo + i];
    __syncthreads();
    int tot = d * HH;
    for (int p = t; p < tot; p += 256) {
        int i = p / HH, h = p - i * HH;
        int src = sp[i];
        float e = g_asad[src * 20 + h] + sad[h];
        e = (e > 0.f) ? e : 0.2f * e;
        ebuf[p] = e;
        atomicMax(&sm[h], fmapU(e));
    }
    __syncthreads();
    for (int p = t; p < tot; p += 256) {
        int h = p % HH;
        float ex = expf(ebuf[p] - finvU(sm[h]));
        ebuf[p] = ex;                    // unnormalized
        atomicAdd(&sden[h], ex);
    }
    __syncthreads();
    if (t < HH) sden[t] = 1.f / sden[t];
    __syncthreads();

    if (t >= 208) return;
    long base = (long)n * KPG + t * 4;
    if (t >= 195) {
        __half2 z = __floats2half2_rn(0.f, 0.f);
        *(__half2*)(g_Ag + base) = z;
        *(__half2*)(g_Ag + base + 2) = z;
        return;
    }
    int q = t * 4;
    int h0 = q / FF, h1 = (q + 1) / FF, h2 = (q + 2) / FF, h3 = (q + 3) / FF;
    float ax = 0.f, ay = 0.f, az = 0.f, aw = 0.f;
    for (int idx = 0; idx < d; idx++) {
        int s = sp[idx];
        uint2 u = *(const uint2*)(g_hH + (long)s * NEXT + q);
        float2 v01 = __half22float2(*(__half2*)&u.x);
        float2 v23 = __half22float2(*(__half2*)&u.y);
        const float* al = &ebuf[idx * HH];
        ax += v01.x * al[h0]; ay += v01.y * al[h1]; az += v23.x * al[h2]; aw += v23.y * al[h3];
    }
    ax *= sden[h0]; ay *= sden[h1]; az *= sden[h2]; aw *= sden[h3];
    float v0 = fmaxf(ax + gat_b[q + 0], 0.f);
    float v1 = fmaxf(ay + gat_b[q + 1], 0.f);
    float v2 = fmaxf(az + gat_b[q + 2], 0.f);
    float v3 = fmaxf(aw + gat_b[q + 3], 0.f);
    *(__half2*)(g_Ag + base)     = __floats2half2_rn(v0, v1);
    *(__half2*)(g_Ag + base + 2) = __floats2half2_rn(v2, v3);
}

// ---------------- GCN aggregation ----------------
__global__ void __launch_bounds__(256) k_gcn_agg(const float* __restrict__ gcn_b) {
    int n = blockIdx.x, t = threadIdx.x;
    if (t >= 195) return;
    int q = t * 4;
    float dn = g_dinv[n];
    float ax = 0.f, ay = 0.f, az = 0.f, aw = 0.f;
    int lo = g_off[n], hi = g_off[n + 1];
    for (int idx = lo; idx < hi; idx++) {
        int s = g_srcA[idx];
        float norm = dn * g_dinv[s];
        uint2 u = *(const uint2*)(g_h2H + (long)s * HID + q);
        float2 v01 = __half22float2(*(__half2*)&u.x);
        float2 v23 = __half22float2(*(__half2*)&u.y);
        ax += v01.x * norm; ay += v01.y * norm; az += v23.x * norm; aw += v23.y * norm;
    }
    float v0 = fmaxf(ax + gcn_b[q + 0], 0.f);
    float v1 = fmaxf(ay + gcn_b[q + 1], 0.f);
    float v2 = fmaxf(az + gcn_b[q + 2], 0.f);
    float v3 = fmaxf(aw + gcn_b[q + 3], 0.f);
    *(__half2*)(g_x2H + (long)n * HID + q)     = __floats2half2_rn(v0, v1);
    *(__half2*)(g_x2H + (long)n * HID + q + 2) = __floats2half2_rn(v2, v3);
}

// ---------------- segment pool ----------------
__global__ void __launch_bounds__(256) k_pool() {
    int b = blockIdx.x, t = threadIdx.x;
    if (t >= 195) return;
    int q = t * 4;
    int lo = g_start[b], hi = g_start[b + 1];
    float ax = 0.f, ay = 0.f, az = 0.f, aw = 0.f;
    for (int n = lo; n < hi; n++) {
        uint2 u = *(const uint2*)(g_x2H + (long)n * HID + q);
        float2 v01 = __half22float2(*(__half2*)&u.x);
        float2 v23 = __half22float2(*(__half2*)&u.y);
        ax += v01.x; ay += v01.y; az += v23.x; aw += v23.y;
    }
    float* o = g_xg + (long)b * HID + q;
    o[0] = ax; o[1] = ay; o[2] = az; o[3] = aw;
}

// ---------------- protein branch ----------------
__global__ void k_Pbias(const float* __restrict__ emb, const float* __restrict__ cW,
                        const float* __restrict__ fxtW, const float* __restrict__ cb) {
    int bi = blockIdx.x, j = threadIdx.x;
    if (bi < 256) {
        int o = bi >> 3, c = bi & 7;
        int t0 = c * 125, t1 = min(t0 + 125, COUT);
        float p = 0.f;
        for (int t = t0; t < t1; t++)
            p += fxtW[((long)(o * COUT + t)) * 128 + j];
        atomicAdd(&g_biasY[j], cb[o] * p);
    } else {
        int g = (bi - 256) * 128 + j;
        if (g >= VOC * NF * KS) return;
        int v = g / (NF * KS), r = g % (NF * KS);
        int o = r / KS, k = r % KS;
        float s = 0.f;
#pragma unroll 16
        for (int e = 0; e < EMB; e++)
            s += emb[v * EMB + e] * cW[o * EMB * KS + e * KS + k];
        g_P[g] = s;
    }
}
__global__ void k_R(const float* __restrict__ fxtW) {
    __shared__ float Ps[VOC * NF * KS];
    int s = blockIdx.x, j = threadIdx.x;
    for (int idx = j; idx < VOC * NF * KS; idx += 128) Ps[idx] = g_P[idx];
    __syncthreads();
    float acc[VOC];
#pragma unroll
    for (int v = 0; v < VOC; v++) acc[v] = 0.f;
    int kmin = (s > COUT - 1) ? (s - (COUT - 1)) : 0;
    int kmax = (s < KS - 1) ? s : (KS - 1);
    for (int o = 0; o < NF; o++) {
        for (int k = kmin; k <= kmax; k++) {
            float w = fxtW[((long)(o * COUT + s - k)) * 128 + j];
#pragma unroll
            for (int v = 0; v < VOC; v++)
                acc[v] += Ps[v * (NF * KS) + o * KS + k] * w;
        }
    }
#pragma unroll
    for (int v = 0; v < VOC; v++)
        g_R[((long)v * SEQ + s) * 128 + j] = acc[v];
}
__global__ void k_Y(const int* __restrict__ target, const float* __restrict__ fxt_b) {
    __shared__ int sv[SEQ];
    int b = blockIdx.x, j = threadIdx.x;
    for (int i = j; i < SEQ; i += 128) sv[i] = target[b * SEQ + i];
    __syncthreads();
    float acc = g_biasY[j] + fxt_b[j];
    for (int s = 0; s < SEQ; s += 4) {
        float r0 = g_R[((long)sv[s]     * SEQ + s)     * 128 + j];
        float r1 = g_R[((long)sv[s + 1] * SEQ + s + 1) * 128 + j];
        float r2 = g_R[((long)sv[s + 2] * SEQ + s + 2) * 128 + j];
        float r3 = g_R[((long)sv[s + 3] * SEQ + s + 3) * 128 + j];
        acc += (r0 + r1) + (r2 + r3);
    }
    g_xc[b * 256 + 128 + j] = acc;
}

// ---------------- output ----------------
__global__ void k_out(const float* __restrict__ oW, const float* __restrict__ ob,
                      float* __restrict__ out) {
    __shared__ float red[4];
    int b = blockIdx.x, j = threadIdx.x;
    float v = g_t5[b * 128 + j] * oW[j];
#pragma unroll
    for (int off = 16; off; off >>= 1) v += __shfl_down_sync(0xffffffffu, v, off);
    if ((j & 31) == 0) red[j >> 5] = v;
    __syncthreads();
    if (j == 0) out[b] = red[0] + red[1] + red[2] + red[3] + ob[0];
}

// ---------------- host ----------------
static inline dim3 ggrid(long n, int t) { return dim3((unsigned)((n + t - 1) / t)); }

extern "C" void kernel_launch(void* const* d_in, const int* in_sizes, int n_in,
                              void* d_out, int out_size) {
    const float* x      = (const float*)d_in[0];
    const int*   edge   = (const int*)  d_in[1];
    const int*   batch  = (const int*)  d_in[2];
    const int*   target = (const int*)  d_in[3];
    const float* gat_W  = (const float*)d_in[4];
    const float* a_src  = (const float*)d_in[5];
    const float* a_dst  = (const float*)d_in[6];
    const float* gat_b  = (const float*)d_in[7];
    const float* gcn_W  = (const float*)d_in[8];
    const float* gcn_b  = (const float*)d_in[9];
    const float* fcg1_W = (const float*)d_in[10];
    const float* fcg1_b = (const float*)d_in[11];
    const float* fcg2_W = (const float*)d_in[12];
    const float* fcg2_b = (const float*)d_in[13];
    const float* emb    = (const float*)d_in[14];
    const float* cW     = (const float*)d_in[15];
    const float* cb     = (const float*)d_in[16];
    const float* fxt_W  = (const float*)d_in[17];
    const float* fxt_b  = (const float*)d_in[18];
    const float* f1_W   = (const float*)d_in[19];
    const float* f1_b   = (const float*)d_in[20];
    const float* f2_W   = (const float*)d_in[21];
    const float* f2_b   = (const float*)d_in[22];
    const float* f3_W   = (const float*)d_in[23];
    const float* f3_b   = (const float*)d_in[24];
    const float* f4_W   = (const float*)d_in[25];
    const float* f4_b   = (const float*)d_in[26];
    const float* o_W    = (const float*)d_in[27];
    const float* o_b    = (const float*)d_in[28];
    float* out = (float*)d_out;

    float *p_xg, *p_t1, *p_xc, *p_t2, *p_t3, *p_t4, *p_t5, *p_asad;
    __half *p_hH, *p_h2H, *p_Axh, *p_Bah, *p_Ag, *p_Bgh;
    cudaGetSymbolAddress((void**)&p_hH,  g_hH);
    cudaGetSymbolAddress((void**)&p_h2H, g_h2H);
    cudaGetSymbolAddress((void**)&p_asad, g_asad);
    cudaGetSymbolAddress((void**)&p_xg,  g_xg);
    cudaGetSymbolAddress((void**)&p_t1,  g_t1);
    cudaGetSymbolAddress((void**)&p_xc,  g_xc);
    cudaGetSymbolAddress((void**)&p_t2,  g_t2);
    cudaGetSymbolAddress((void**)&p_t3,  g_t3);
    cudaGetSymbolAddress((void**)&p_t4,  g_t4);
    cudaGetSymbolAddress((void**)&p_t5,  g_t5);
    cudaGetSymbolAddress((void**)&p_Axh, g_Axh);
    cudaGetSymbolAddress((void**)&p_Bah, g_Bah);
    cudaGetSymbolAddress((void**)&p_Ag,  g_Ag);
    cudaGetSymbolAddress((void**)&p_Bgh, g_Bgh);

    static cudaStream_t s1, s2;
    static cudaEvent_t eF, e1, e2;
    static int inited = 0;
    if (!inited) {
        cudaStreamCreateWithFlags(&s1, cudaStreamNonBlocking);
        cudaStreamCreateWithFlags(&s2, cudaStreamNonBlocking);
        cudaEventCreateWithFlags(&eF, cudaEventDisableTiming);
        cudaEventCreateWithFlags(&e1, cudaEventDisableTiming);
        cudaEventCreateWithFlags(&e2, cudaEventDisableTiming);
        cudaFuncSetAttribute(gemm_mma, cudaFuncAttributeMaxDynamicSharedMemorySize, GEMM_SMEM);
        inited = 1;
    }

    cudaEventRecord(eF, 0);
    cudaStreamWaitEvent(s1, eF, 0);
    cudaStreamWaitEvent(s2, eF, 0);

    // main: conversions + attn rows
    k_transW<<<dim3(4, 25), 256>>>(gat_W, p_Bah, FF, HID, KPA);
    k_transW<<<dim3(26, 25), 256>>>(gcn_W, p_Bgh, HID, HID, KPG);
    k_prep<<<PB_A + PB_E, 256>>>(x, gat_W, a_src, a_dst);
    // s1: CSR build
    k_count<<<ggrid(ET, 256), 256, 0, s1>>>(edge);
    k_startB<<<ggrid(NN, 256), 256, 0, s1>>>(batch);
    k_scanA<<<NB, 256, 0, s1>>>();
    k_scanB<<<1, 128, 0, s1>>>();
    k_scanC<<<NB, 256, 0, s1>>>();
    // main: GAT GEMM (KC=64, NC=2)
    gemm_mma<<<dim3(7, 157), 256, GEMM_SMEM>>>(p_Axh, p_Bah, p_hH, NN, NEXT, KPA, KPA / KC, NEXT,
                                               p_asad, HID);
    // s1: scatter
    k_scatter<<<ggrid(ET, 256), 256, 0, s1>>>(edge);
    cudaEventRecord(e1, s1);
    // s2: protein branch
    k_init0<<<1, 128, 0, s2>>>();
    k_Pbias<<<308, 128, 0, s2>>>(emb, cW, fxt_W, cb);
    k_R<<<SEQ, 128, 0, s2>>>(fxt_W);
    k_Y<<<BB, 128, 0, s2>>>(target, fxt_b);
    cudaEventRecord(e2, s2);
    // main: graph branch
    cudaStreamWaitEvent(0, e1, 0);
    k_gat_soft_agg<<<NN, 256>>>(gat_b);
    gemm_mma<<<dim3(7, 157), 256, GEMM_SMEM>>>(p_Ag, p_Bgh, p_h2H, NN, HID, KPG, KPG / KC, HID,
                                               nullptr, 1 << 30);
    k_gcn_agg<<<NN, 256>>>(gcn_b);
    k_pool<<<BB, 256>>>();
    // head
    mlp8<<<dim3(24, 25), 256>>>(p_xg, fcg1_W, p_t1, fcg1_b, BB, 1500, HID, HID, 1500, 0, 1);
    mlp8<<<dim3(2, 25), 256>>>(p_t1, fcg2_W, p_xc, fcg2_b, BB, 128, 1500, 1500, 256, 0, 0);
    cudaStreamWaitEvent(0, e2, 0);
    mlp8<<<dim3(16, 25), 256>>>(p_xc, f1_W, p_t2, f1_b, BB, 1024, 256, 256, 1024, 0, 1);
    mlp8<<<dim3(8, 25), 256>>>(p_t2, f2_W, p_t3, f2_b, BB, 512, 1024, 1024, 512, 0, 1);
    mlp8<<<dim3(4, 25), 256>>>(p_t3, f3_W, p_t4, f3_b, BB, 256, 512, 512, 256, 0, 1);
    mlp8<<<dim3(2, 25), 256>>>(p_t4, f4_W, p_t5, f4_b, BB, 128, 256, 256, 128, 0, 1);
    k_out<<<BB, 128>>>(o_W, o_b, out);
}